// round 6
// baseline (speedup 1.0000x reference)
#include <cuda_runtime.h>
#include <cuda_bf16.h>
#include <cstdint>

#define T_SEQ 2048
#define NFEAT 512
#define HEADS 8
#define DK 64
#define BHTOT 32
#define MTOT 8192
#define TLD 36   // smem row stride in 32-bit words (72 bf16 = 144 B)

// Scratch (static device globals). Q pre-scaled by 1/8. V stored transposed.
__device__ __nv_bfloat16 g_q_h[(size_t)BHTOT*T_SEQ*DK];
__device__ __nv_bfloat16 g_q_l[(size_t)BHTOT*T_SEQ*DK];
__device__ __nv_bfloat16 g_k_h[(size_t)BHTOT*T_SEQ*DK];
__device__ __nv_bfloat16 g_k_l[(size_t)BHTOT*T_SEQ*DK];
__device__ __nv_bfloat16 g_vt_h[(size_t)BHTOT*DK*T_SEQ];   // [bh][d][t]
__device__ __nv_bfloat16 g_vt_l[(size_t)BHTOT*DK*T_SEQ];
__device__ float g_x[(size_t)MTOT*NFEAT];                  // attn out (fp32)

// split x,y into packed bf16 hi-pair and lo-pair (residual)
static __device__ __forceinline__ void split2(float x, float y,
                                              uint32_t& hw, uint32_t& lw) {
    __nv_bfloat162 h = __floats2bfloat162_rn(x, y);
    float hx = __low2float(h), hy = __high2float(h);
    __nv_bfloat162 l = __floats2bfloat162_rn(x - hx, y - hy);
    hw = *reinterpret_cast<uint32_t*>(&h);
    lw = *reinterpret_cast<uint32_t*>(&l);
}

static __device__ __forceinline__ void mma16816(float* d, const uint32_t* a,
                                                const uint32_t* b) {
    asm volatile(
        "mma.sync.aligned.m16n8k16.row.col.f32.bf16.bf16.f32 "
        "{%0,%1,%2,%3}, {%4,%5,%6,%7}, {%8,%9}, {%0,%1,%2,%3};"
        : "+f"(d[0]), "+f"(d[1]), "+f"(d[2]), "+f"(d[3])
        : "r"(a[0]), "r"(a[1]), "r"(a[2]), "r"(a[3]), "r"(b[0]), "r"(b[1]));
}

static __device__ __forceinline__ void mma16808(float* d, const uint32_t* a,
                                                uint32_t b) {
    asm volatile(
        "mma.sync.aligned.m16n8k8.row.col.f32.bf16.bf16.f32 "
        "{%0,%1,%2,%3}, {%4,%5}, {%6}, {%0,%1,%2,%3};"
        : "+f"(d[0]), "+f"(d[1]), "+f"(d[2]), "+f"(d[3])
        : "r"(a[0]), "r"(a[1]), "r"(b));
}

static __device__ __forceinline__ uint32_t smem_u32(const void* p) {
    uint32_t a;
    asm("{ .reg .u64 t; cvta.to.shared.u64 t, %1; cvt.u32.u64 %0, t; }"
        : "=r"(a) : "l"(p));
    return a;
}

#define CP16(saddr, gptr) \
    asm volatile("cp.async.ca.shared.global [%0], [%1], 16;" \
                 :: "r"(saddr), "l"(gptr))
#define CP_COMMIT() asm volatile("cp.async.commit_group;" ::: "memory")
#define CP_WAIT0()  asm volatile("cp.async.wait_group 0;" ::: "memory")

// ---------------------------------------------------------------------------
// bf16-3x GEMM: Out[M,N] = X[M,K] @ W[N,K]^T + bias ; M=8192, N=K=512
// (unchanged from round 5 — passing)
// ---------------------------------------------------------------------------
extern __shared__ uint32_t smw[];

__global__ __launch_bounds__(256) void gemm_tc(
    const float* __restrict__ X, const float* __restrict__ W,
    const float* __restrict__ Bv, float* __restrict__ Out,
    int out_sel, int in_sel)
{
    if (in_sel) X = g_x;
    uint32_t* Ah = smw;
    uint32_t* Al = smw + 128*TLD;
    uint32_t* Bh = smw + 2*128*TLD;
    uint32_t* Bl = smw + 3*128*TLD;

    const int tid = threadIdx.x, lane = tid & 31, wid = tid >> 5;
    const int g = lane >> 2, c = lane & 3;
    const int mw = wid >> 1, nw = wid & 1;
    const int m0 = blockIdx.y * 128, n0 = blockIdx.x * 128;

    float acc[2][8][4] = {};

    for (int k0 = 0; k0 < NFEAT; k0 += 64) {
        __syncthreads();
        #pragma unroll
        for (int l = 0; l < 8; l++) {
            int idx = tid + l * 256, row = idx >> 4, c4 = idx & 15;
            float4 a = *(const float4*)&X[(size_t)(m0+row)*NFEAT + k0 + c4*4];
            uint32_t h0, l0, h1, l1;
            split2(a.x, a.y, h0, l0); split2(a.z, a.w, h1, l1);
            Ah[row*TLD + c4*2] = h0; Ah[row*TLD + c4*2 + 1] = h1;
            Al[row*TLD + c4*2] = l0; Al[row*TLD + c4*2 + 1] = l1;
            float4 w = *(const float4*)&W[(size_t)(n0+row)*NFEAT + k0 + c4*4];
            split2(w.x, w.y, h0, l0); split2(w.z, w.w, h1, l1);
            Bh[row*TLD + c4*2] = h0; Bh[row*TLD + c4*2 + 1] = h1;
            Bl[row*TLD + c4*2] = l0; Bl[row*TLD + c4*2 + 1] = l1;
        }
        __syncthreads();

        #pragma unroll
        for (int ks = 0; ks < 4; ks++) {
            uint32_t ah[2][4], alr[2][4], bhr[8][2], blr[8][2];
            #pragma unroll
            for (int mf = 0; mf < 2; mf++) {
                int rb = mw*32 + mf*16;
                ah[mf][0]  = Ah[(rb+g  )*TLD + ks*8 + c];
                ah[mf][1]  = Ah[(rb+g+8)*TLD + ks*8 + c];
                ah[mf][2]  = Ah[(rb+g  )*TLD + ks*8 + c + 4];
                ah[mf][3]  = Ah[(rb+g+8)*TLD + ks*8 + c + 4];
                alr[mf][0] = Al[(rb+g  )*TLD + ks*8 + c];
                alr[mf][1] = Al[(rb+g+8)*TLD + ks*8 + c];
                alr[mf][2] = Al[(rb+g  )*TLD + ks*8 + c + 4];
                alr[mf][3] = Al[(rb+g+8)*TLD + ks*8 + c + 4];
            }
            #pragma unroll
            for (int nf = 0; nf < 8; nf++) {
                int rb = (nw*64 + nf*8 + g)*TLD + ks*8;
                bhr[nf][0] = Bh[rb + c]; bhr[nf][1] = Bh[rb + c + 4];
                blr[nf][0] = Bl[rb + c]; blr[nf][1] = Bl[rb + c + 4];
            }
            #pragma unroll
            for (int mf = 0; mf < 2; mf++)
                #pragma unroll
                for (int nf = 0; nf < 8; nf++) {
                    mma16816(acc[mf][nf], ah[mf],  bhr[nf]);
                    mma16816(acc[mf][nf], ah[mf],  blr[nf]);
                    mma16816(acc[mf][nf], alr[mf], bhr[nf]);
                }
        }
    }

    if (out_sel == 0) {
        #pragma unroll
        for (int mf = 0; mf < 2; mf++) {
            int r0 = mw*32 + mf*16 + g;
            #pragma unroll
            for (int nf = 0; nf < 8; nf++) {
                int col = n0 + nw*64 + nf*8 + 2*c;
                float2 bb = *(const float2*)&Bv[col];
                float2 o0 = {acc[mf][nf][0] + bb.x, acc[mf][nf][1] + bb.y};
                float2 o1 = {acc[mf][nf][2] + bb.x, acc[mf][nf][3] + bb.y};
                *(float2*)&Out[(size_t)(m0+r0  )*NFEAT + col] = o0;
                *(float2*)&Out[(size_t)(m0+r0+8)*NFEAT + col] = o1;
            }
        }
    } else if (out_sel == 1 || out_sel == 2) {
        __nv_bfloat16* Oh = (out_sel == 1) ? g_q_h : g_k_h;
        __nv_bfloat16* Ol = (out_sel == 1) ? g_q_l : g_k_l;
        const float scl = (out_sel == 1) ? 0.125f : 1.0f;
        #pragma unroll
        for (int mf = 0; mf < 2; mf++)
            #pragma unroll
            for (int half = 0; half < 2; half++) {
                int m  = m0 + mw*32 + mf*16 + g + half*8;
                int bb_ = m >> 11, tt = m & (T_SEQ - 1);
                #pragma unroll
                for (int nf = 0; nf < 8; nf++) {
                    int col = nw*64 + nf*8 + 2*c;
                    int hh = (n0 + col) >> 6, d = (n0 + col) & 63;
                    float2 bb = *(const float2*)&Bv[n0 + col];
                    float v0 = (acc[mf][nf][half*2+0] + bb.x) * scl;
                    float v1 = (acc[mf][nf][half*2+1] + bb.y) * scl;
                    uint32_t hw, lw; split2(v0, v1, hw, lw);
                    size_t widx = (((size_t)(bb_*HEADS+hh)*T_SEQ + tt)*DK + d) >> 1;
                    ((uint32_t*)Oh)[widx] = hw;
                    ((uint32_t*)Ol)[widx] = lw;
                }
            }
    } else {
        __syncthreads();
        __nv_bfloat16* Tsh = (__nv_bfloat16*)smw;                       // [128n][136]
        __nv_bfloat16* Tsl = (__nv_bfloat16*)((char*)smw + 128*272);
        #pragma unroll
        for (int mf = 0; mf < 2; mf++)
            #pragma unroll
            for (int half = 0; half < 2; half++) {
                int t_loc = mw*32 + mf*16 + g + half*8;
                #pragma unroll
                for (int nf = 0; nf < 8; nf++) {
                    int col = nw*64 + nf*8 + 2*c;
                    float2 bb = *(const float2*)&Bv[n0 + col];
                    float v0 = acc[mf][nf][half*2+0] + bb.x;
                    float v1 = acc[mf][nf][half*2+1] + bb.y;
                    __nv_bfloat162 h2 = __floats2bfloat162_rn(v0, v1);
                    __nv_bfloat162 l2 = __floats2bfloat162_rn(
                        v0 - __low2float(h2), v1 - __high2float(h2));
                    Tsh[(size_t)(col  )*136 + t_loc] = h2.x;
                    Tsh[(size_t)(col+1)*136 + t_loc] = h2.y;
                    Tsl[(size_t)(col  )*136 + t_loc] = l2.x;
                    Tsl[(size_t)(col+1)*136 + t_loc] = l2.y;
                }
            }
        __syncthreads();
        int bb_ = m0 >> 11, tt0 = m0 & (T_SEQ - 1);
        #pragma unroll
        for (int l = 0; l < 8; l++) {
            int idx = tid + l * 256, n = idx >> 4, j = idx & 15;
            int hh = (n0 >> 6) + (n >> 6), d = n & 63;
            size_t go = ((size_t)(bb_*HEADS + hh)*DK + d)*T_SEQ + tt0 + j*8;
            *(uint4*)&g_vt_h[go] = *(uint4*)((char*)Tsh + (size_t)n*272 + j*16);
            *(uint4*)&g_vt_l[go] = *(uint4*)((char*)Tsl + (size_t)n*272 + j*16);
        }
    }
}

// ---------------------------------------------------------------------------
// bf16-3x attention, round 6: warp = 16 q-rows (full key/dim range),
// P in registers (m16n8k8 PV), cp.async double-buffered K/V, 1 sync/tile.
// ---------------------------------------------------------------------------
#define AQH 0
#define AQL 18432
#define ABUF 36864          // two K/V buffers, stride 36864
//   per buffer: KH +0, KL +9216, VH +18432, VL +27648  (each 64 rows x 144 B)
#define AMB 110592          // 2 x 64 floats (mask)
#define ATTN_SMEM 111104

static __device__ __forceinline__ void attn_issue_tile(
    uint32_t kbase, int bh, int kt, int tid)
{
    #pragma unroll
    for (int l = 0; l < 2; l++) {
        int idx = tid + l * 256, row = idx >> 3, j = idx & 7;
        uint32_t soff = row * 144 + j * 16;
        size_t kg = ((size_t)bh * T_SEQ + kt + row) * DK + j * 8;
        size_t vg = ((size_t)bh * DK + row) * T_SEQ + kt + j * 8;
        CP16(kbase +     0 + soff, (const char*)&g_k_h[kg]);
        CP16(kbase +  9216 + soff, (const char*)&g_k_l[kg]);
        CP16(kbase + 18432 + soff, (const char*)&g_vt_h[vg]);
        CP16(kbase + 27648 + soff, (const char*)&g_vt_l[vg]);
    }
    CP_COMMIT();
}

__global__ __launch_bounds__(256) void attn_tc(const int* __restrict__ mask)
{
    extern __shared__ char sm[];
    const uint32_t sb = smem_u32(sm);
    float* mbufF = (float*)(sm + AMB);

    const int tid = threadIdx.x, lane = tid & 31, wid = tid >> 5;
    const int g = lane >> 2, c = lane & 3;
    const int bh = blockIdx.y, b = bh >> 3, h = bh & 7;
    const int q0 = blockIdx.x * 128;
    const int rb = wid * 16;              // this warp's 16 q-rows

    // ---- prologue: Q tile + first K/V tile + first mask ----
    #pragma unroll
    for (int l = 0; l < 4; l++) {
        int idx = tid + l * 256, row = idx >> 3, j = idx & 7;
        size_t gsrc = ((size_t)bh*T_SEQ + q0 + row)*DK + j*8;
        *(uint4*)(sm + AQH + row*144 + j*16) = *(const uint4*)&g_q_h[gsrc];
        *(uint4*)(sm + AQL + row*144 + j*16) = *(const uint4*)&g_q_l[gsrc];
    }
    attn_issue_tile(sb + ABUF, bh, 0, tid);
    if (tid < 64) mbufF[tid] = (float)mask[b*T_SEQ + tid];
    CP_WAIT0();
    __syncthreads();

    const uint32_t* Qh = (const uint32_t*)(sm + AQH);
    const uint32_t* Ql = (const uint32_t*)(sm + AQL);

    float oacc[8][4] = {};
    float lacc0 = 0.f, lacc1 = 0.f;

    for (int it = 0; it < T_SEQ / 64; it++) {
        const int cur = it & 1;
        const char* Kbuf = sm + ABUF + cur * 36864;
        const uint32_t* Kh = (const uint32_t*)(Kbuf);
        const uint32_t* Kl = (const uint32_t*)(Kbuf + 9216);
        const uint32_t* Vh = (const uint32_t*)(Kbuf + 18432);
        const uint32_t* Vl = (const uint32_t*)(Kbuf + 27648);

        // prefetch next tile (cp.async into the other buffer) + next mask
        int mreg = 0;
        const bool more = (it + 1 < T_SEQ / 64);
        if (more) {
            attn_issue_tile(sb + ABUF + (cur ^ 1) * 36864, bh, (it+1)*64, tid);
            if (tid < 64) mreg = mask[b*T_SEQ + (it+1)*64 + tid];
        }

        // ---- S = Q K^T : 16 rows x 64 keys ----
        float sacc[8][4] = {};
        #pragma unroll
        for (int ks = 0; ks < 4; ks++) {
            uint32_t ah[4], al[4];
            ah[0] = Qh[(rb+g  )*TLD + ks*8 + c];
            ah[1] = Qh[(rb+g+8)*TLD + ks*8 + c];
            ah[2] = Qh[(rb+g  )*TLD + ks*8 + c + 4];
            ah[3] = Qh[(rb+g+8)*TLD + ks*8 + c + 4];
            al[0] = Ql[(rb+g  )*TLD + ks*8 + c];
            al[1] = Ql[(rb+g+8)*TLD + ks*8 + c];
            al[2] = Ql[(rb+g  )*TLD + ks*8 + c + 4];
            al[3] = Ql[(rb+g+8)*TLD + ks*8 + c + 4];
            #pragma unroll
            for (int nf = 0; nf < 8; nf++) {
                int rk = (nf*8 + g)*TLD + ks*8;
                uint32_t bh0[2] = {Kh[rk + c], Kh[rk + c + 4]};
                uint32_t bl0[2] = {Kl[rk + c], Kl[rk + c + 4]};
                mma16816(sacc[nf], ah, bh0);
                mma16816(sacc[nf], ah, bl0);
                mma16816(sacc[nf], al, bh0);
            }
        }

        // ---- exp + mask + row-sum; P fragments stay in registers ----
        uint32_t ph[8][2], pl[8][2];
        #pragma unroll
        for (int nf = 0; nf < 8; nf++) {
            int cb = nf*8 + 2*c;
            float m0v = mbufF[cur*64 + cb], m1v = mbufF[cur*64 + cb + 1];
            float e0 = __expf(sacc[nf][0]) * m0v;
            float e1 = __expf(sacc[nf][1]) * m1v;
            float e2 = __expf(sacc[nf][2]) * m0v;
            float e3 = __expf(sacc[nf][3]) * m1v;
            lacc0 += e0 + e1;
            lacc1 += e2 + e3;
            split2(e0, e1, ph[nf][0], pl[nf][0]);
            split2(e2, e3, ph[nf][1], pl[nf][1]);
        }

        // ---- O += P V : m16n8k8, A = P (regs), B = V^T (smem) ----
        #pragma unroll
        for (int kg = 0; kg < 8; kg++) {
            #pragma unroll
            for (int nd = 0; nd < 8; nd++) {
                uint32_t vh0 = Vh[(nd*8 + g)*TLD + kg*4 + c];
                uint32_t vl0 = Vl[(nd*8 + g)*TLD + kg*4 + c];
                mma16808(oacc[nd], ph[kg], vh0);
                mma16808(oacc[nd], ph[kg], vl0);
                mma16808(oacc[nd], pl[kg], vh0);
            }
        }

        if (more) {
            if (tid < 64) mbufF[(cur ^ 1)*64 + tid] = (float)mreg;
            CP_WAIT0();
        }
        __syncthreads();
    }

    // ---- normalize + store (warp owns its rows completely) ----
    lacc0 += __shfl_xor_sync(0xffffffffu, lacc0, 1);
    lacc0 += __shfl_xor_sync(0xffffffffu, lacc0, 2);
    lacc1 += __shfl_xor_sync(0xffffffffu, lacc1, 1);
    lacc1 += __shfl_xor_sync(0xffffffffu, lacc1, 2);
    float inv0 = (lacc0 > 0.f) ? 1.f / (lacc0 * (1.f + 1e-8f)) : 0.f;
    float inv1 = (lacc1 > 0.f) ? 1.f / (lacc1 * (1.f + 1e-8f)) : 0.f;

    const int row0 = q0 + rb + g, row1 = row0 + 8;
    #pragma unroll
    for (int nd = 0; nd < 8; nd++) {
        int col = h*DK + nd*8 + 2*c;
        float2 o0 = {oacc[nd][0] * inv0, oacc[nd][1] * inv0};
        float2 o1 = {oacc[nd][2] * inv1, oacc[nd][3] * inv1};
        *(float2*)&g_x[(size_t)(b*T_SEQ + row0)*NFEAT + col] = o0;
        *(float2*)&g_x[(size_t)(b*T_SEQ + row1)*NFEAT + col] = o1;
    }
}

// ---------------------------------------------------------------------------
extern "C" void kernel_launch(void* const* d_in, const int* in_sizes, int n_in,
                              void* d_out, int out_size)
{
    const float* query = (const float*)d_in[0];
    const float* key_  = (const float*)d_in[1];
    const float* value = (const float*)d_in[2];
    const int*   mask  = (const int*)d_in[3];
    const float* Wq = (const float*)d_in[4];
    const float* bq = (const float*)d_in[5];
    const float* Wk = (const float*)d_in[6];
    const float* bk = (const float*)d_in[7];
    const float* Wv = (const float*)d_in[8];
    const float* bv = (const float*)d_in[9];
    const float* Wo = (const float*)d_in[10];
    const float* bo = (const float*)d_in[11];
    float* out = (float*)d_out;

    const int GS = 4 * 128 * TLD * (int)sizeof(uint32_t);   // 73728
    cudaFuncSetAttribute(gemm_tc, cudaFuncAttributeMaxDynamicSharedMemorySize, GS);
    cudaFuncSetAttribute(attn_tc, cudaFuncAttributeMaxDynamicSharedMemorySize,
                         ATTN_SMEM);

    dim3 gg(NFEAT / 128, MTOT / 128);   // (4, 64)

    gemm_tc<<<gg, 256, GS>>>(query, Wq, bq, nullptr, 1, 0);
    gemm_tc<<<gg, 256, GS>>>(key_,  Wk, bk, nullptr, 2, 0);
    gemm_tc<<<gg, 256, GS>>>(value, Wv, bv, nullptr, 3, 0);

    attn_tc<<<dim3(T_SEQ / 128, BHTOT), 256, ATTN_SMEM>>>(mask);

    gemm_tc<<<gg, 256, GS>>>(nullptr, Wo, bo, out, 0, 1);
}

// round 7
// speedup vs baseline: 1.1509x; 1.1509x over previous
#include <cuda_runtime.h>
#include <cuda_bf16.h>
#include <cstdint>

#define T_SEQ 2048
#define NFEAT 512
#define HEADS 8
#define DK 64
#define BHTOT 32
#define MTOT 8192
#define TLD 36   // smem row stride in 32-bit words (72 bf16 = 144 B)

// Scratch (static device globals). Q pre-scaled by 1/8. V stored transposed.
__device__ __nv_bfloat16 g_q_h[(size_t)BHTOT*T_SEQ*DK];
__device__ __nv_bfloat16 g_q_l[(size_t)BHTOT*T_SEQ*DK];
__device__ __nv_bfloat16 g_k_h[(size_t)BHTOT*T_SEQ*DK];
__device__ __nv_bfloat16 g_k_l[(size_t)BHTOT*T_SEQ*DK];
__device__ __nv_bfloat16 g_vt_h[(size_t)BHTOT*DK*T_SEQ];   // [bh][d][t]
__device__ __nv_bfloat16 g_vt_l[(size_t)BHTOT*DK*T_SEQ];
__device__ float g_x[(size_t)MTOT*NFEAT];                  // attn out (fp32)

// split x,y into packed bf16 hi-pair and lo-pair (residual)
static __device__ __forceinline__ void split2(float x, float y,
                                              uint32_t& hw, uint32_t& lw) {
    __nv_bfloat162 h = __floats2bfloat162_rn(x, y);
    float hx = __low2float(h), hy = __high2float(h);
    __nv_bfloat162 l = __floats2bfloat162_rn(x - hx, y - hy);
    hw = *reinterpret_cast<uint32_t*>(&h);
    lw = *reinterpret_cast<uint32_t*>(&l);
}

static __device__ __forceinline__ void mma16816(float* d, const uint32_t* a,
                                                const uint32_t* b) {
    asm volatile(
        "mma.sync.aligned.m16n8k16.row.col.f32.bf16.bf16.f32 "
        "{%0,%1,%2,%3}, {%4,%5,%6,%7}, {%8,%9}, {%0,%1,%2,%3};"
        : "+f"(d[0]), "+f"(d[1]), "+f"(d[2]), "+f"(d[3])
        : "r"(a[0]), "r"(a[1]), "r"(a[2]), "r"(a[3]), "r"(b[0]), "r"(b[1]));
}

static __device__ __forceinline__ uint32_t smem_u32(const void* p) {
    uint32_t a;
    asm("{ .reg .u64 t; cvta.to.shared.u64 t, %1; cvt.u32.u64 %0, t; }"
        : "=r"(a) : "l"(p));
    return a;
}

#define CP16(saddr, gptr) \
    asm volatile("cp.async.ca.shared.global [%0], [%1], 16;" \
                 :: "r"(saddr), "l"(gptr))
#define CP_COMMIT() asm volatile("cp.async.commit_group;" ::: "memory")
#define CP_WAIT0()  asm volatile("cp.async.wait_group 0;" ::: "memory")

// ---------------------------------------------------------------------------
// bf16-3x GEMM: Out[M,N] = X[M,K] @ W[N,K]^T + bias ; M=8192, N=K=512
// (unchanged — passing)
// ---------------------------------------------------------------------------
extern __shared__ uint32_t smw[];

__global__ __launch_bounds__(256) void gemm_tc(
    const float* __restrict__ X, const float* __restrict__ W,
    const float* __restrict__ Bv, float* __restrict__ Out,
    int out_sel, int in_sel)
{
    if (in_sel) X = g_x;
    uint32_t* Ah = smw;
    uint32_t* Al = smw + 128*TLD;
    uint32_t* Bh = smw + 2*128*TLD;
    uint32_t* Bl = smw + 3*128*TLD;

    const int tid = threadIdx.x, lane = tid & 31, wid = tid >> 5;
    const int g = lane >> 2, c = lane & 3;
    const int mw = wid >> 1, nw = wid & 1;
    const int m0 = blockIdx.y * 128, n0 = blockIdx.x * 128;

    float acc[2][8][4] = {};

    for (int k0 = 0; k0 < NFEAT; k0 += 64) {
        __syncthreads();
        #pragma unroll
        for (int l = 0; l < 8; l++) {
            int idx = tid + l * 256, row = idx >> 4, c4 = idx & 15;
            float4 a = *(const float4*)&X[(size_t)(m0+row)*NFEAT + k0 + c4*4];
            uint32_t h0, l0, h1, l1;
            split2(a.x, a.y, h0, l0); split2(a.z, a.w, h1, l1);
            Ah[row*TLD + c4*2] = h0; Ah[row*TLD + c4*2 + 1] = h1;
            Al[row*TLD + c4*2] = l0; Al[row*TLD + c4*2 + 1] = l1;
            float4 w = *(const float4*)&W[(size_t)(n0+row)*NFEAT + k0 + c4*4];
            split2(w.x, w.y, h0, l0); split2(w.z, w.w, h1, l1);
            Bh[row*TLD + c4*2] = h0; Bh[row*TLD + c4*2 + 1] = h1;
            Bl[row*TLD + c4*2] = l0; Bl[row*TLD + c4*2 + 1] = l1;
        }
        __syncthreads();

        #pragma unroll
        for (int ks = 0; ks < 4; ks++) {
            uint32_t ah[2][4], alr[2][4], bhr[8][2], blr[8][2];
            #pragma unroll
            for (int mf = 0; mf < 2; mf++) {
                int rb = mw*32 + mf*16;
                ah[mf][0]  = Ah[(rb+g  )*TLD + ks*8 + c];
                ah[mf][1]  = Ah[(rb+g+8)*TLD + ks*8 + c];
                ah[mf][2]  = Ah[(rb+g  )*TLD + ks*8 + c + 4];
                ah[mf][3]  = Ah[(rb+g+8)*TLD + ks*8 + c + 4];
                alr[mf][0] = Al[(rb+g  )*TLD + ks*8 + c];
                alr[mf][1] = Al[(rb+g+8)*TLD + ks*8 + c];
                alr[mf][2] = Al[(rb+g  )*TLD + ks*8 + c + 4];
                alr[mf][3] = Al[(rb+g+8)*TLD + ks*8 + c + 4];
            }
            #pragma unroll
            for (int nf = 0; nf < 8; nf++) {
                int rb = (nw*64 + nf*8 + g)*TLD + ks*8;
                bhr[nf][0] = Bh[rb + c]; bhr[nf][1] = Bh[rb + c + 4];
                blr[nf][0] = Bl[rb + c]; blr[nf][1] = Bl[rb + c + 4];
            }
            #pragma unroll
            for (int mf = 0; mf < 2; mf++)
                #pragma unroll
                for (int nf = 0; nf < 8; nf++) {
                    mma16816(acc[mf][nf], ah[mf],  bhr[nf]);
                    mma16816(acc[mf][nf], ah[mf],  blr[nf]);
                    mma16816(acc[mf][nf], alr[mf], bhr[nf]);
                }
        }
    }

    if (out_sel == 0) {
        #pragma unroll
        for (int mf = 0; mf < 2; mf++) {
            int r0 = mw*32 + mf*16 + g;
            #pragma unroll
            for (int nf = 0; nf < 8; nf++) {
                int col = n0 + nw*64 + nf*8 + 2*c;
                float2 bb = *(const float2*)&Bv[col];
                float2 o0 = {acc[mf][nf][0] + bb.x, acc[mf][nf][1] + bb.y};
                float2 o1 = {acc[mf][nf][2] + bb.x, acc[mf][nf][3] + bb.y};
                *(float2*)&Out[(size_t)(m0+r0  )*NFEAT + col] = o0;
                *(float2*)&Out[(size_t)(m0+r0+8)*NFEAT + col] = o1;
            }
        }
    } else if (out_sel == 1 || out_sel == 2) {
        __nv_bfloat16* Oh = (out_sel == 1) ? g_q_h : g_k_h;
        __nv_bfloat16* Ol = (out_sel == 1) ? g_q_l : g_k_l;
        const float scl = (out_sel == 1) ? 0.125f : 1.0f;
        #pragma unroll
        for (int mf = 0; mf < 2; mf++)
            #pragma unroll
            for (int half = 0; half < 2; half++) {
                int m  = m0 + mw*32 + mf*16 + g + half*8;
                int bb_ = m >> 11, tt = m & (T_SEQ - 1);
                #pragma unroll
                for (int nf = 0; nf < 8; nf++) {
                    int col = nw*64 + nf*8 + 2*c;
                    int hh = (n0 + col) >> 6, d = (n0 + col) & 63;
                    float2 bb = *(const float2*)&Bv[n0 + col];
                    float v0 = (acc[mf][nf][half*2+0] + bb.x) * scl;
                    float v1 = (acc[mf][nf][half*2+1] + bb.y) * scl;
                    uint32_t hw, lw; split2(v0, v1, hw, lw);
                    size_t widx = (((size_t)(bb_*HEADS+hh)*T_SEQ + tt)*DK + d) >> 1;
                    ((uint32_t*)Oh)[widx] = hw;
                    ((uint32_t*)Ol)[widx] = lw;
                }
            }
    } else {
        __syncthreads();
        __nv_bfloat16* Tsh = (__nv_bfloat16*)smw;                       // [128n][136]
        __nv_bfloat16* Tsl = (__nv_bfloat16*)((char*)smw + 128*272);
        #pragma unroll
        for (int mf = 0; mf < 2; mf++)
            #pragma unroll
            for (int half = 0; half < 2; half++) {
                int t_loc = mw*32 + mf*16 + g + half*8;
                #pragma unroll
                for (int nf = 0; nf < 8; nf++) {
                    int col = nw*64 + nf*8 + 2*c;
                    float2 bb = *(const float2*)&Bv[n0 + col];
                    float v0 = acc[mf][nf][half*2+0] + bb.x;
                    float v1 = acc[mf][nf][half*2+1] + bb.y;
                    __nv_bfloat162 h2 = __floats2bfloat162_rn(v0, v1);
                    __nv_bfloat162 l2 = __floats2bfloat162_rn(
                        v0 - __low2float(h2), v1 - __high2float(h2));
                    Tsh[(size_t)(col  )*136 + t_loc] = h2.x;
                    Tsh[(size_t)(col+1)*136 + t_loc] = h2.y;
                    Tsl[(size_t)(col  )*136 + t_loc] = l2.x;
                    Tsl[(size_t)(col+1)*136 + t_loc] = l2.y;
                }
            }
        __syncthreads();
        int bb_ = m0 >> 11, tt0 = m0 & (T_SEQ - 1);
        #pragma unroll
        for (int l = 0; l < 8; l++) {
            int idx = tid + l * 256, n = idx >> 4, j = idx & 15;
            int hh = (n0 >> 6) + (n >> 6), d = n & 63;
            size_t go = ((size_t)(bb_*HEADS + hh)*DK + d)*T_SEQ + tt0 + j*8;
            *(uint4*)&g_vt_h[go] = *(uint4*)((char*)Tsh + (size_t)n*272 + j*16);
            *(uint4*)&g_vt_l[go] = *(uint4*)((char*)Tsl + (size_t)n*272 + j*16);
        }
    }
}

// ---------------------------------------------------------------------------
// bf16-3x attention, round 7: round-6 structure (P in regs, cp.async double
// buffer, 1 sync/tile) but PV restored to m16n8k16 — two adjacent k8 P
// fragments concatenated form the k16 A fragment. Halves PV tensor cycles.
// ---------------------------------------------------------------------------
#define AQH 0
#define AQL 18432
#define ABUF 36864          // two K/V buffers, stride 36864
//   per buffer: KH +0, KL +9216, VH +18432, VL +27648  (each 64 rows x 144 B)
#define AMB 110592          // 2 x 64 floats (mask)
#define ATTN_SMEM 111104

static __device__ __forceinline__ void attn_issue_tile(
    uint32_t kbase, int bh, int kt, int tid)
{
    #pragma unroll
    for (int l = 0; l < 2; l++) {
        int idx = tid + l * 256, row = idx >> 3, j = idx & 7;
        uint32_t soff = row * 144 + j * 16;
        size_t kg = ((size_t)bh * T_SEQ + kt + row) * DK + j * 8;
        size_t vg = ((size_t)bh * DK + row) * T_SEQ + kt + j * 8;
        CP16(kbase +     0 + soff, (const char*)&g_k_h[kg]);
        CP16(kbase +  9216 + soff, (const char*)&g_k_l[kg]);
        CP16(kbase + 18432 + soff, (const char*)&g_vt_h[vg]);
        CP16(kbase + 27648 + soff, (const char*)&g_vt_l[vg]);
    }
    CP_COMMIT();
}

__global__ __launch_bounds__(256) void attn_tc(const int* __restrict__ mask)
{
    extern __shared__ char sm[];
    const uint32_t sb = smem_u32(sm);
    float* mbufF = (float*)(sm + AMB);

    const int tid = threadIdx.x, lane = tid & 31, wid = tid >> 5;
    const int g = lane >> 2, c = lane & 3;
    const int bh = blockIdx.y, b = bh >> 3, h = bh & 7;
    const int q0 = blockIdx.x * 128;
    const int rb = wid * 16;              // this warp's 16 q-rows

    // ---- prologue: Q tile + first K/V tile + first mask ----
    #pragma unroll
    for (int l = 0; l < 4; l++) {
        int idx = tid + l * 256, row = idx >> 3, j = idx & 7;
        size_t gsrc = ((size_t)bh*T_SEQ + q0 + row)*DK + j*8;
        *(uint4*)(sm + AQH + row*144 + j*16) = *(const uint4*)&g_q_h[gsrc];
        *(uint4*)(sm + AQL + row*144 + j*16) = *(const uint4*)&g_q_l[gsrc];
    }
    attn_issue_tile(sb + ABUF, bh, 0, tid);
    if (tid < 64) mbufF[tid] = (float)mask[b*T_SEQ + tid];
    CP_WAIT0();
    __syncthreads();

    const uint32_t* Qh = (const uint32_t*)(sm + AQH);
    const uint32_t* Ql = (const uint32_t*)(sm + AQL);

    float oacc[8][4] = {};
    float lacc0 = 0.f, lacc1 = 0.f;

    for (int it = 0; it < T_SEQ / 64; it++) {
        const int cur = it & 1;
        const char* Kbuf = sm + ABUF + cur * 36864;
        const uint32_t* Kh = (const uint32_t*)(Kbuf);
        const uint32_t* Kl = (const uint32_t*)(Kbuf + 9216);
        const uint32_t* Vh = (const uint32_t*)(Kbuf + 18432);
        const uint32_t* Vl = (const uint32_t*)(Kbuf + 27648);

        // prefetch next tile (cp.async into the other buffer) + next mask
        int mreg = 0;
        const bool more = (it + 1 < T_SEQ / 64);
        if (more) {
            attn_issue_tile(sb + ABUF + (cur ^ 1) * 36864, bh, (it+1)*64, tid);
            if (tid < 64) mreg = mask[b*T_SEQ + (it+1)*64 + tid];
        }

        // ---- S = Q K^T : 16 rows x 64 keys ----
        float sacc[8][4] = {};
        #pragma unroll
        for (int ks = 0; ks < 4; ks++) {
            uint32_t ah[4], al[4];
            ah[0] = Qh[(rb+g  )*TLD + ks*8 + c];
            ah[1] = Qh[(rb+g+8)*TLD + ks*8 + c];
            ah[2] = Qh[(rb+g  )*TLD + ks*8 + c + 4];
            ah[3] = Qh[(rb+g+8)*TLD + ks*8 + c + 4];
            al[0] = Ql[(rb+g  )*TLD + ks*8 + c];
            al[1] = Ql[(rb+g+8)*TLD + ks*8 + c];
            al[2] = Ql[(rb+g  )*TLD + ks*8 + c + 4];
            al[3] = Ql[(rb+g+8)*TLD + ks*8 + c + 4];
            #pragma unroll
            for (int nf = 0; nf < 8; nf++) {
                int rk = (nf*8 + g)*TLD + ks*8;
                uint32_t bh0[2] = {Kh[rk + c], Kh[rk + c + 4]};
                uint32_t bl0[2] = {Kl[rk + c], Kl[rk + c + 4]};
                mma16816(sacc[nf], ah, bh0);
                mma16816(sacc[nf], ah, bl0);
                mma16816(sacc[nf], al, bh0);
            }
        }

        // ---- exp + mask + row-sum; P fragments stay in registers ----
        uint32_t ph[8][2], pl[8][2];
        #pragma unroll
        for (int nf = 0; nf < 8; nf++) {
            int cb = nf*8 + 2*c;
            float m0v = mbufF[cur*64 + cb], m1v = mbufF[cur*64 + cb + 1];
            float e0 = __expf(sacc[nf][0]) * m0v;
            float e1 = __expf(sacc[nf][1]) * m1v;
            float e2 = __expf(sacc[nf][2]) * m0v;
            float e3 = __expf(sacc[nf][3]) * m1v;
            lacc0 += e0 + e1;
            lacc1 += e2 + e3;
            split2(e0, e1, ph[nf][0], pl[nf][0]);
            split2(e2, e3, ph[nf][1], pl[nf][1]);
        }

        // ---- O += P V : m16n8k16, A = paired P fragments (regs), B = V^T ----
        #pragma unroll
        for (int kg = 0; kg < 4; kg++) {
            uint32_t pa_h[4] = {ph[2*kg][0], ph[2*kg][1],
                                ph[2*kg+1][0], ph[2*kg+1][1]};
            uint32_t pa_l[4] = {pl[2*kg][0], pl[2*kg][1],
                                pl[2*kg+1][0], pl[2*kg+1][1]};
            #pragma unroll
            for (int nd = 0; nd < 8; nd++) {
                int rv = (nd*8 + g)*TLD + kg*8;
                uint32_t vh0[2] = {Vh[rv + c], Vh[rv + c + 4]};
                uint32_t vl0[2] = {Vl[rv + c], Vl[rv + c + 4]};
                mma16816(oacc[nd], pa_h, vh0);
                mma16816(oacc[nd], pa_h, vl0);
                mma16816(oacc[nd], pa_l, vh0);
            }
        }

        if (more) {
            if (tid < 64) mbufF[(cur ^ 1)*64 + tid] = (float)mreg;
            CP_WAIT0();
        }
        __syncthreads();
    }

    // ---- normalize + store (warp owns its rows completely) ----
    lacc0 += __shfl_xor_sync(0xffffffffu, lacc0, 1);
    lacc0 += __shfl_xor_sync(0xffffffffu, lacc0, 2);
    lacc1 += __shfl_xor_sync(0xffffffffu, lacc1, 1);
    lacc1 += __shfl_xor_sync(0xffffffffu, lacc1, 2);
    float inv0 = (lacc0 > 0.f) ? 1.f / (lacc0 * (1.f + 1e-8f)) : 0.f;
    float inv1 = (lacc1 > 0.f) ? 1.f / (lacc1 * (1.f + 1e-8f)) : 0.f;

    const int row0 = q0 + rb + g, row1 = row0 + 8;
    #pragma unroll
    for (int nd = 0; nd < 8; nd++) {
        int col = h*DK + nd*8 + 2*c;
        float2 o0 = {oacc[nd][0] * inv0, oacc[nd][1] * inv0};
        float2 o1 = {oacc[nd][2] * inv1, oacc[nd][3] * inv1};
        *(float2*)&g_x[(size_t)(b*T_SEQ + row0)*NFEAT + col] = o0;
        *(float2*)&g_x[(size_t)(b*T_SEQ + row1)*NFEAT + col] = o1;
    }
}

// ---------------------------------------------------------------------------
extern "C" void kernel_launch(void* const* d_in, const int* in_sizes, int n_in,
                              void* d_out, int out_size)
{
    const float* query = (const float*)d_in[0];
    const float* key_  = (const float*)d_in[1];
    const float* value = (const float*)d_in[2];
    const int*   mask  = (const int*)d_in[3];
    const float* Wq = (const float*)d_in[4];
    const float* bq = (const float*)d_in[5];
    const float* Wk = (const float*)d_in[6];
    const float* bk = (const float*)d_in[7];
    const float* Wv = (const float*)d_in[8];
    const float* bv = (const float*)d_in[9];
    const float* Wo = (const float*)d_in[10];
    const float* bo = (const float*)d_in[11];
    float* out = (float*)d_out;

    const int GS = 4 * 128 * TLD * (int)sizeof(uint32_t);   // 73728
    cudaFuncSetAttribute(gemm_tc, cudaFuncAttributeMaxDynamicSharedMemorySize, GS);
    cudaFuncSetAttribute(attn_tc, cudaFuncAttributeMaxDynamicSharedMemorySize,
                         ATTN_SMEM);

    dim3 gg(NFEAT / 128, MTOT / 128);   // (4, 64)

    gemm_tc<<<gg, 256, GS>>>(query, Wq, bq, nullptr, 1, 0);
    gemm_tc<<<gg, 256, GS>>>(key_,  Wk, bk, nullptr, 2, 0);
    gemm_tc<<<gg, 256, GS>>>(value, Wv, bv, nullptr, 3, 0);

    attn_tc<<<dim3(T_SEQ / 128, BHTOT), 256, ATTN_SMEM>>>(mask);

    gemm_tc<<<gg, 256, GS>>>(nullptr, Wo, bo, out, 0, 1);
}

// round 8
// speedup vs baseline: 1.1812x; 1.0263x over previous
#include <cuda_runtime.h>
#include <cuda_bf16.h>
#include <cstdint>

#define T_SEQ 2048
#define NFEAT 512
#define HEADS 8
#define DK 64
#define BHTOT 32
#define MTOT 8192
#define TLD 36   // smem row stride in 32-bit words (72 bf16 = 144 B)

// Scratch (static device globals). Q pre-scaled by 1/8. V stored transposed.
__device__ __nv_bfloat16 g_q_h[(size_t)BHTOT*T_SEQ*DK];
__device__ __nv_bfloat16 g_q_l[(size_t)BHTOT*T_SEQ*DK];
__device__ __nv_bfloat16 g_k_h[(size_t)BHTOT*T_SEQ*DK];
__device__ __nv_bfloat16 g_k_l[(size_t)BHTOT*T_SEQ*DK];
__device__ __nv_bfloat16 g_vt_h[(size_t)BHTOT*DK*T_SEQ];   // [bh][d][t]
__device__ __nv_bfloat16 g_vt_l[(size_t)BHTOT*DK*T_SEQ];
__device__ float g_x[(size_t)MTOT*NFEAT];                  // attn out (fp32)

static __device__ __forceinline__ void split2(float x, float y,
                                              uint32_t& hw, uint32_t& lw) {
    __nv_bfloat162 h = __floats2bfloat162_rn(x, y);
    float hx = __low2float(h), hy = __high2float(h);
    __nv_bfloat162 l = __floats2bfloat162_rn(x - hx, y - hy);
    hw = *reinterpret_cast<uint32_t*>(&h);
    lw = *reinterpret_cast<uint32_t*>(&l);
}

static __device__ __forceinline__ void mma16816(float* d, const uint32_t* a,
                                                const uint32_t* b) {
    asm volatile(
        "mma.sync.aligned.m16n8k16.row.col.f32.bf16.bf16.f32 "
        "{%0,%1,%2,%3}, {%4,%5,%6,%7}, {%8,%9}, {%0,%1,%2,%3};"
        : "+f"(d[0]), "+f"(d[1]), "+f"(d[2]), "+f"(d[3])
        : "r"(a[0]), "r"(a[1]), "r"(a[2]), "r"(a[3]), "r"(b[0]), "r"(b[1]));
}

static __device__ __forceinline__ void ldsm4(uint32_t* r, uint32_t addr) {
    asm volatile(
        "ldmatrix.sync.aligned.m8n8.x4.shared.b16 {%0,%1,%2,%3}, [%4];"
        : "=r"(r[0]), "=r"(r[1]), "=r"(r[2]), "=r"(r[3]) : "r"(addr));
}

static __device__ __forceinline__ uint32_t smem_u32(const void* p) {
    uint32_t a;
    asm("{ .reg .u64 t; cvta.to.shared.u64 t, %1; cvt.u32.u64 %0, t; }"
        : "=r"(a) : "l"(p));
    return a;
}

#define CP16(saddr, gptr) \
    asm volatile("cp.async.ca.shared.global [%0], [%1], 16;" \
                 :: "r"(saddr), "l"(gptr))
#define CP_COMMIT() asm volatile("cp.async.commit_group;" ::: "memory")
#define CP_WAIT0()  asm volatile("cp.async.wait_group 0;" ::: "memory")

// Per-lane ldmatrix address offsets (bytes), row stride 144 B.
// A-type: lanes 0-7 rows 0-7 chunk0; 8-15 rows 8-15 chunk0;
//         16-23 rows 0-7 chunk1; 24-31 rows 8-15 chunk1.
static __device__ __forceinline__ uint32_t a_lane_off(int lane) {
    return (uint32_t)((lane & 15) * 144 + ((lane & 16) ? 16 : 0));
}
// B-type: lanes 0-7 rows 0-7 chunk0; 8-15 rows 0-7 chunk1;
//         16-23 rows 8-15 chunk0; 24-31 rows 8-15 chunk1.
static __device__ __forceinline__ uint32_t b_lane_off(int lane) {
    return (uint32_t)(((lane & 7) + ((lane >> 4) & 1) * 8) * 144 +
                      ((lane & 8) ? 16 : 0));
}

// ---------------------------------------------------------------------------
// bf16-3x GEMM with ldmatrix fragment loads.
// ---------------------------------------------------------------------------
extern __shared__ uint32_t smw[];

__global__ __launch_bounds__(256) void gemm_tc(
    const float* __restrict__ X, const float* __restrict__ W,
    const float* __restrict__ Bv, float* __restrict__ Out,
    int out_sel, int in_sel)
{
    if (in_sel) X = g_x;
    uint32_t* Ah = smw;
    uint32_t* Al = smw + 128*TLD;
    uint32_t* Bh = smw + 2*128*TLD;
    uint32_t* Bl = smw + 3*128*TLD;

    const int tid = threadIdx.x, lane = tid & 31, wid = tid >> 5;
    const int g = lane >> 2, c = lane & 3;
    const int mw = wid >> 1, nw = wid & 1;
    const int m0 = blockIdx.y * 128, n0 = blockIdx.x * 128;

    const uint32_t sbg = smem_u32(smw);
    const uint32_t a_base = sbg + (uint32_t)(mw*32)*144 + a_lane_off(lane);
    const uint32_t b_base = sbg + 36864u + (uint32_t)(nw*64)*144 + b_lane_off(lane);

    float acc[2][8][4] = {};

    for (int k0 = 0; k0 < NFEAT; k0 += 64) {
        __syncthreads();
        #pragma unroll
        for (int l = 0; l < 8; l++) {
            int idx = tid + l * 256, row = idx >> 4, c4 = idx & 15;
            float4 a = *(const float4*)&X[(size_t)(m0+row)*NFEAT + k0 + c4*4];
            uint32_t h0, l0, h1, l1;
            split2(a.x, a.y, h0, l0); split2(a.z, a.w, h1, l1);
            Ah[row*TLD + c4*2] = h0; Ah[row*TLD + c4*2 + 1] = h1;
            Al[row*TLD + c4*2] = l0; Al[row*TLD + c4*2 + 1] = l1;
            float4 w = *(const float4*)&W[(size_t)(n0+row)*NFEAT + k0 + c4*4];
            split2(w.x, w.y, h0, l0); split2(w.z, w.w, h1, l1);
            Bh[row*TLD + c4*2] = h0; Bh[row*TLD + c4*2 + 1] = h1;
            Bl[row*TLD + c4*2] = l0; Bl[row*TLD + c4*2 + 1] = l1;
        }
        __syncthreads();

        #pragma unroll
        for (int ks = 0; ks < 4; ks++) {
            uint32_t ah[2][4], al[2][4], bh4[4][4], bl4[4][4];
            #pragma unroll
            for (int mf = 0; mf < 2; mf++) {
                ldsm4(ah[mf], a_base + mf*(16*144) + ks*32);
                ldsm4(al[mf], a_base + mf*(16*144) + ks*32 + 18432);
            }
            #pragma unroll
            for (int np = 0; np < 4; np++) {
                ldsm4(bh4[np], b_base + np*2304 + ks*32);
                ldsm4(bl4[np], b_base + np*2304 + ks*32 + 18432);
            }
            #pragma unroll
            for (int mf = 0; mf < 2; mf++)
                #pragma unroll
                for (int np = 0; np < 4; np++) {
                    mma16816(acc[mf][2*np  ], ah[mf], &bh4[np][0]);
                    mma16816(acc[mf][2*np  ], ah[mf], &bl4[np][0]);
                    mma16816(acc[mf][2*np  ], al[mf], &bh4[np][0]);
                    mma16816(acc[mf][2*np+1], ah[mf], &bh4[np][2]);
                    mma16816(acc[mf][2*np+1], ah[mf], &bl4[np][2]);
                    mma16816(acc[mf][2*np+1], al[mf], &bh4[np][2]);
                }
        }
    }

    if (out_sel == 0) {
        #pragma unroll
        for (int mf = 0; mf < 2; mf++) {
            int r0 = mw*32 + mf*16 + g;
            #pragma unroll
            for (int nf = 0; nf < 8; nf++) {
                int col = n0 + nw*64 + nf*8 + 2*c;
                float2 bb = *(const float2*)&Bv[col];
                float2 o0 = {acc[mf][nf][0] + bb.x, acc[mf][nf][1] + bb.y};
                float2 o1 = {acc[mf][nf][2] + bb.x, acc[mf][nf][3] + bb.y};
                *(float2*)&Out[(size_t)(m0+r0  )*NFEAT + col] = o0;
                *(float2*)&Out[(size_t)(m0+r0+8)*NFEAT + col] = o1;
            }
        }
    } else if (out_sel == 1 || out_sel == 2) {
        __nv_bfloat16* Oh = (out_sel == 1) ? g_q_h : g_k_h;
        __nv_bfloat16* Ol = (out_sel == 1) ? g_q_l : g_k_l;
        const float scl = (out_sel == 1) ? 0.125f : 1.0f;
        #pragma unroll
        for (int mf = 0; mf < 2; mf++)
            #pragma unroll
            for (int half = 0; half < 2; half++) {
                int m  = m0 + mw*32 + mf*16 + g + half*8;
                int bb_ = m >> 11, tt = m & (T_SEQ - 1);
                #pragma unroll
                for (int nf = 0; nf < 8; nf++) {
                    int col = nw*64 + nf*8 + 2*c;
                    int hh = (n0 + col) >> 6, d = (n0 + col) & 63;
                    float2 bb = *(const float2*)&Bv[n0 + col];
                    float v0 = (acc[mf][nf][half*2+0] + bb.x) * scl;
                    float v1 = (acc[mf][nf][half*2+1] + bb.y) * scl;
                    uint32_t hw, lw; split2(v0, v1, hw, lw);
                    size_t widx = (((size_t)(bb_*HEADS+hh)*T_SEQ + tt)*DK + d) >> 1;
                    ((uint32_t*)Oh)[widx] = hw;
                    ((uint32_t*)Ol)[widx] = lw;
                }
            }
    } else {
        __syncthreads();
        __nv_bfloat16* Tsh = (__nv_bfloat16*)smw;                       // [128n][136]
        __nv_bfloat16* Tsl = (__nv_bfloat16*)((char*)smw + 128*272);
        #pragma unroll
        for (int mf = 0; mf < 2; mf++)
            #pragma unroll
            for (int half = 0; half < 2; half++) {
                int t_loc = mw*32 + mf*16 + g + half*8;
                #pragma unroll
                for (int nf = 0; nf < 8; nf++) {
                    int col = nw*64 + nf*8 + 2*c;
                    float2 bb = *(const float2*)&Bv[n0 + col];
                    float v0 = acc[mf][nf][half*2+0] + bb.x;
                    float v1 = acc[mf][nf][half*2+1] + bb.y;
                    __nv_bfloat162 h2 = __floats2bfloat162_rn(v0, v1);
                    __nv_bfloat162 l2 = __floats2bfloat162_rn(
                        v0 - __low2float(h2), v1 - __high2float(h2));
                    Tsh[(size_t)(col  )*136 + t_loc] = h2.x;
                    Tsh[(size_t)(col+1)*136 + t_loc] = h2.y;
                    Tsl[(size_t)(col  )*136 + t_loc] = l2.x;
                    Tsl[(size_t)(col+1)*136 + t_loc] = l2.y;
                }
            }
        __syncthreads();
        int bb_ = m0 >> 11, tt0 = m0 & (T_SEQ - 1);
        #pragma unroll
        for (int l = 0; l < 8; l++) {
            int idx = tid + l * 256, n = idx >> 4, j = idx & 15;
            int hh = (n0 >> 6) + (n >> 6), d = n & 63;
            size_t go = ((size_t)(bb_*HEADS + hh)*DK + d)*T_SEQ + tt0 + j*8;
            *(uint4*)&g_vt_h[go] = *(uint4*)((char*)Tsh + (size_t)n*272 + j*16);
            *(uint4*)&g_vt_l[go] = *(uint4*)((char*)Tsl + (size_t)n*272 + j*16);
        }
    }
}

// ---------------------------------------------------------------------------
// bf16-3x attention with ldmatrix fragment loads.
// ---------------------------------------------------------------------------
#define AQH 0
#define AQL 18432
#define ABUF 36864
#define AMB 110592
#define ATTN_SMEM 111104

static __device__ __forceinline__ void attn_issue_tile(
    uint32_t kbase, int bh, int kt, int tid)
{
    #pragma unroll
    for (int l = 0; l < 2; l++) {
        int idx = tid + l * 256, row = idx >> 3, j = idx & 7;
        uint32_t soff = row * 144 + j * 16;
        size_t kg = ((size_t)bh * T_SEQ + kt + row) * DK + j * 8;
        size_t vg = ((size_t)bh * DK + row) * T_SEQ + kt + j * 8;
        CP16(kbase +     0 + soff, (const char*)&g_k_h[kg]);
        CP16(kbase +  9216 + soff, (const char*)&g_k_l[kg]);
        CP16(kbase + 18432 + soff, (const char*)&g_vt_h[vg]);
        CP16(kbase + 27648 + soff, (const char*)&g_vt_l[vg]);
    }
    CP_COMMIT();
}

__global__ __launch_bounds__(256) void attn_tc(const int* __restrict__ mask)
{
    extern __shared__ char sm[];
    const uint32_t sb = smem_u32(sm);
    float* mbufF = (float*)(sm + AMB);

    const int tid = threadIdx.x, lane = tid & 31, wid = tid >> 5;
    const int c = lane & 3;
    const int bh = blockIdx.y, b = bh >> 3, h = bh & 7;
    const int q0 = blockIdx.x * 128;
    const int rb = wid * 16;

    const uint32_t q_amem = sb + AQH + (uint32_t)rb*144 + a_lane_off(lane);
    const uint32_t b_off  = b_lane_off(lane);

    #pragma unroll
    for (int l = 0; l < 4; l++) {
        int idx = tid + l * 256, row = idx >> 3, j = idx & 7;
        size_t gsrc = ((size_t)bh*T_SEQ + q0 + row)*DK + j*8;
        *(uint4*)(sm + AQH + row*144 + j*16) = *(const uint4*)&g_q_h[gsrc];
        *(uint4*)(sm + AQL + row*144 + j*16) = *(const uint4*)&g_q_l[gsrc];
    }
    attn_issue_tile(sb + ABUF, bh, 0, tid);
    if (tid < 64) mbufF[tid] = (float)mask[b*T_SEQ + tid];
    CP_WAIT0();
    __syncthreads();

    float oacc[8][4] = {};
    float lacc0 = 0.f, lacc1 = 0.f;

    for (int it = 0; it < T_SEQ / 64; it++) {
        const int cur = it & 1;
        const uint32_t kb = sb + ABUF + cur * 36864 + b_off;
        const uint32_t vb = kb + 18432;

        int mreg = 0;
        const bool more = (it + 1 < T_SEQ / 64);
        if (more) {
            attn_issue_tile(sb + ABUF + (cur ^ 1) * 36864, bh, (it+1)*64, tid);
            if (tid < 64) mreg = mask[b*T_SEQ + (it+1)*64 + tid];
        }

        // ---- S = Q K^T ----
        float sacc[8][4] = {};
        #pragma unroll
        for (int ks = 0; ks < 4; ks++) {
            uint32_t ah[4], al[4];
            ldsm4(ah, q_amem + ks*32);
            ldsm4(al, q_amem + ks*32 + 18432);
            #pragma unroll
            for (int np = 0; np < 4; np++) {
                uint32_t kh4[4], kl4[4];
                ldsm4(kh4, kb + np*2304 + ks*32);
                ldsm4(kl4, kb + np*2304 + ks*32 + 9216);
                mma16816(sacc[2*np  ], ah, &kh4[0]);
                mma16816(sacc[2*np  ], ah, &kl4[0]);
                mma16816(sacc[2*np  ], al, &kh4[0]);
                mma16816(sacc[2*np+1], ah, &kh4[2]);
                mma16816(sacc[2*np+1], ah, &kl4[2]);
                mma16816(sacc[2*np+1], al, &kh4[2]);
            }
        }

        // ---- exp + mask + row-sum; P stays in registers ----
        uint32_t ph[8][2], pl[8][2];
        #pragma unroll
        for (int nf = 0; nf < 8; nf++) {
            int cb = nf*8 + 2*c;
            float m0v = mbufF[cur*64 + cb], m1v = mbufF[cur*64 + cb + 1];
            float e0 = __expf(sacc[nf][0]) * m0v;
            float e1 = __expf(sacc[nf][1]) * m1v;
            float e2 = __expf(sacc[nf][2]) * m0v;
            float e3 = __expf(sacc[nf][3]) * m1v;
            lacc0 += e0 + e1;
            lacc1 += e2 + e3;
            split2(e0, e1, ph[nf][0], pl[nf][0]);
            split2(e2, e3, ph[nf][1], pl[nf][1]);
        }

        // ---- O += P V ----
        #pragma unroll
        for (int kg = 0; kg < 4; kg++) {
            uint32_t pa_h[4] = {ph[2*kg][0], ph[2*kg][1],
                                ph[2*kg+1][0], ph[2*kg+1][1]};
            uint32_t pa_l[4] = {pl[2*kg][0], pl[2*kg][1],
                                pl[2*kg+1][0], pl[2*kg+1][1]};
            #pragma unroll
            for (int np = 0; np < 4; np++) {
                uint32_t vh4[4], vl4[4];
                ldsm4(vh4, vb + np*2304 + kg*32);
                ldsm4(vl4, vb + np*2304 + kg*32 + 9216);
                mma16816(oacc[2*np  ], pa_h, &vh4[0]);
                mma16816(oacc[2*np  ], pa_h, &vl4[0]);
                mma16816(oacc[2*np  ], pa_l, &vh4[0]);
                mma16816(oacc[2*np+1], pa_h, &vh4[2]);
                mma16816(oacc[2*np+1], pa_h, &vl4[2]);
                mma16816(oacc[2*np+1], pa_l, &vh4[2]);
            }
        }

        if (more) {
            if (tid < 64) mbufF[(cur ^ 1)*64 + tid] = (float)mreg;
            CP_WAIT0();
        }
        __syncthreads();
    }

    lacc0 += __shfl_xor_sync(0xffffffffu, lacc0, 1);
    lacc0 += __shfl_xor_sync(0xffffffffu, lacc0, 2);
    lacc1 += __shfl_xor_sync(0xffffffffu, lacc1, 1);
    lacc1 += __shfl_xor_sync(0xffffffffu, lacc1, 2);
    float inv0 = (lacc0 > 0.f) ? 1.f / (lacc0 * (1.f + 1e-8f)) : 0.f;
    float inv1 = (lacc1 > 0.f) ? 1.f / (lacc1 * (1.f + 1e-8f)) : 0.f;

    const int g = lane >> 2;
    const int row0 = q0 + rb + g, row1 = row0 + 8;
    #pragma unroll
    for (int nd = 0; nd < 8; nd++) {
        int col = h*DK + nd*8 + 2*c;
        float2 o0 = {oacc[nd][0] * inv0, oacc[nd][1] * inv0};
        float2 o1 = {oacc[nd][2] * inv1, oacc[nd][3] * inv1};
        *(float2*)&g_x[(size_t)(b*T_SEQ + row0)*NFEAT + col] = o0;
        *(float2*)&g_x[(size_t)(b*T_SEQ + row1)*NFEAT + col] = o1;
    }
}

// ---------------------------------------------------------------------------
extern "C" void kernel_launch(void* const* d_in, const int* in_sizes, int n_in,
                              void* d_out, int out_size)
{
    const float* query = (const float*)d_in[0];
    const float* key_  = (const float*)d_in[1];
    const float* value = (const float*)d_in[2];
    const int*   mask  = (const int*)d_in[3];
    const float* Wq = (const float*)d_in[4];
    const float* bq = (const float*)d_in[5];
    const float* Wk = (const float*)d_in[6];
    const float* bk = (const float*)d_in[7];
    const float* Wv = (const float*)d_in[8];
    const float* bv = (const float*)d_in[9];
    const float* Wo = (const float*)d_in[10];
    const float* bo = (const float*)d_in[11];
    float* out = (float*)d_out;

    const int GS = 4 * 128 * TLD * (int)sizeof(uint32_t);   // 73728
    cudaFuncSetAttribute(gemm_tc, cudaFuncAttributeMaxDynamicSharedMemorySize, GS);
    cudaFuncSetAttribute(attn_tc, cudaFuncAttributeMaxDynamicSharedMemorySize,
                         ATTN_SMEM);

    dim3 gg(NFEAT / 128, MTOT / 128);   // (4, 64)

    gemm_tc<<<gg, 256, GS>>>(query, Wq, bq, nullptr, 1, 0);
    gemm_tc<<<gg, 256, GS>>>(key_,  Wk, bk, nullptr, 2, 0);
    gemm_tc<<<gg, 256, GS>>>(value, Wv, bv, nullptr, 3, 0);

    attn_tc<<<dim3(T_SEQ / 128, BHTOT), 256, ATTN_SMEM>>>(mask);

    gemm_tc<<<gg, 256, GS>>>(nullptr, Wo, bo, out, 0, 1);
}

// round 9
// speedup vs baseline: 1.2380x; 1.0481x over previous
#include <cuda_runtime.h>
#include <cuda_bf16.h>
#include <cstdint>

#define T_SEQ 2048
#define NFEAT 512
#define HEADS 8
#define DK 64
#define BHTOT 32
#define MTOT 8192
#define TLD 36   // attn smem row stride in words (144 B)

// Q pre-scaled by log2(e)/8 (exp2 in attn). V stored transposed.
__device__ __nv_bfloat16 g_q_h[(size_t)BHTOT*T_SEQ*DK];
__device__ __nv_bfloat16 g_q_l[(size_t)BHTOT*T_SEQ*DK];
__device__ __nv_bfloat16 g_k_h[(size_t)BHTOT*T_SEQ*DK];
__device__ __nv_bfloat16 g_k_l[(size_t)BHTOT*T_SEQ*DK];
__device__ __nv_bfloat16 g_vt_h[(size_t)BHTOT*DK*T_SEQ];   // [bh][d][t]
__device__ __nv_bfloat16 g_vt_l[(size_t)BHTOT*DK*T_SEQ];
// Preconverted inputs/weights/attn-output, stored as bf16x2 words.
__device__ uint32_t g_in_h[(size_t)3*MTOT*256];   // [3][8192][256]
__device__ uint32_t g_in_l[(size_t)3*MTOT*256];
__device__ uint32_t g_wt_h[(size_t)4*512*256];    // [4][512][256]
__device__ uint32_t g_wt_l[(size_t)4*512*256];
__device__ uint32_t g_x_h[(size_t)MTOT*256];      // attn out bf16 hi/lo
__device__ uint32_t g_x_l[(size_t)MTOT*256];

static __device__ __forceinline__ void split2(float x, float y,
                                              uint32_t& hw, uint32_t& lw) {
    __nv_bfloat162 h = __floats2bfloat162_rn(x, y);
    float hx = __low2float(h), hy = __high2float(h);
    __nv_bfloat162 l = __floats2bfloat162_rn(x - hx, y - hy);
    hw = *reinterpret_cast<uint32_t*>(&h);
    lw = *reinterpret_cast<uint32_t*>(&l);
}

static __device__ __forceinline__ void mma16816(float* d, const uint32_t* a,
                                                const uint32_t* b) {
    asm volatile(
        "mma.sync.aligned.m16n8k16.row.col.f32.bf16.bf16.f32 "
        "{%0,%1,%2,%3}, {%4,%5,%6,%7}, {%8,%9}, {%0,%1,%2,%3};"
        : "+f"(d[0]), "+f"(d[1]), "+f"(d[2]), "+f"(d[3])
        : "r"(a[0]), "r"(a[1]), "r"(a[2]), "r"(a[3]), "r"(b[0]), "r"(b[1]));
}

static __device__ __forceinline__ void ldsm4(uint32_t* r, uint32_t addr) {
    asm volatile(
        "ldmatrix.sync.aligned.m8n8.x4.shared.b16 {%0,%1,%2,%3}, [%4];"
        : "=r"(r[0]), "=r"(r[1]), "=r"(r[2]), "=r"(r[3]) : "r"(addr));
}

static __device__ __forceinline__ uint32_t smem_u32(const void* p) {
    uint32_t a;
    asm("{ .reg .u64 t; cvta.to.shared.u64 t, %1; cvt.u32.u64 %0, t; }"
        : "=r"(a) : "l"(p));
    return a;
}

#define CP16(saddr, gptr) \
    asm volatile("cp.async.ca.shared.global [%0], [%1], 16;" \
                 :: "r"(saddr), "l"(gptr))
#define CP_COMMIT() asm volatile("cp.async.commit_group;" ::: "memory")
#define CP_WAIT0()  asm volatile("cp.async.wait_group 0;" ::: "memory")

// ldmatrix lane offsets for 144-byte rows (attn)
static __device__ __forceinline__ uint32_t a_lane_off(int lane) {
    return (uint32_t)((lane & 15) * 144 + ((lane & 16) ? 16 : 0));
}
static __device__ __forceinline__ uint32_t b_lane_off(int lane) {
    return (uint32_t)(((lane & 7) + ((lane >> 4) & 1) * 8) * 144 +
                      ((lane & 8) ? 16 : 0));
}
// ldmatrix lane offsets for 80-byte rows (gemm, k-chunk 32)
static __device__ __forceinline__ uint32_t a80_off(int lane) {
    return (uint32_t)((lane & 15) * 80 + ((lane & 16) ? 16 : 0));
}
static __device__ __forceinline__ uint32_t b80_off(int lane) {
    return (uint32_t)(((lane & 7) + ((lane >> 4) & 1) * 8) * 80 +
                      ((lane & 8) ? 16 : 0));
}

// ---------------------------------------------------------------------------
// fp32 -> bf16 hi/lo pair converter (grid-stride over float2 pairs)
// ---------------------------------------------------------------------------
__global__ void conv_pairs(const float* __restrict__ s,
                           uint32_t* __restrict__ dh,
                           uint32_t* __restrict__ dl, int nPairs)
{
    int i = blockIdx.x * blockDim.x + threadIdx.x;
    int stride = gridDim.x * blockDim.x;
    for (; i < nPairs; i += stride) {
        float2 v = ((const float2*)s)[i];
        uint32_t hw, lw; split2(v.x, v.y, hw, lw);
        dh[i] = hw; dl[i] = lw;
    }
}

// ---------------------------------------------------------------------------
// bf16-3x GEMM, preconverted inputs, cp.async double-buffered (k-chunk 32).
// Out[M,N] = X[M,K] @ W[N,K]^T + bias ; CTA 128x128, 8 warps (4m x 2n).
// SMEM per buffer (40960 B): Ah +0, Al +10240, Bh +20480, Bl +30720,
// rows of 80 B (64 B data + 16 pad). Two buffers = 81920 B.
// ---------------------------------------------------------------------------
#define GEMM_SMEM 81920
extern __shared__ uint32_t smw[];

__global__ __launch_bounds__(256) void gemm_tc(
    const uint32_t* __restrict__ Xh, const uint32_t* __restrict__ Xl,
    const uint32_t* __restrict__ Wh, const uint32_t* __restrict__ Wl,
    const float* __restrict__ Bv, float* __restrict__ Out, int out_sel)
{
    const int tid = threadIdx.x, lane = tid & 31, wid = tid >> 5;
    const int g = lane >> 2, c = lane & 3;
    const int mw = wid >> 1, nw = wid & 1;
    const int m0 = blockIdx.y * 128, n0 = blockIdx.x * 128;

    const uint32_t sbg = smem_u32(smw);
    const uint32_t abase = sbg + (uint32_t)(mw*32)*80 + a80_off(lane);
    const uint32_t bbase = sbg + 20480u + (uint32_t)(nw*64)*80 + b80_off(lane);

    const int seg = tid & 3;
    const int row0 = tid >> 2;          // rows row0 and row0+64

    float acc[2][8][4] = {};

    // prologue: chunk 0
    {
        #pragma unroll
        for (int l = 0; l < 2; l++) {
            int row = row0 + l*64;
            uint32_t sa = sbg + row*80 + seg*16;
            uint32_t ga = (uint32_t)(m0+row)*256 + seg*4;
            uint32_t gb = (uint32_t)(n0+row)*256 + seg*4;
            CP16(sa,         Xh + ga);
            CP16(sa + 10240, Xl + ga);
            CP16(sa + 20480, Wh + gb);
            CP16(sa + 30720, Wl + gb);
        }
        CP_COMMIT();
        CP_WAIT0();
        __syncthreads();
    }

    for (int kc = 0; kc < 16; kc++) {
        const uint32_t bo_ = (uint32_t)(kc & 1) * 40960u;
        const bool more = (kc + 1 < 16);
        if (more) {
            uint32_t sb = sbg + (uint32_t)((kc+1) & 1) * 40960u;
            #pragma unroll
            for (int l = 0; l < 2; l++) {
                int row = row0 + l*64;
                uint32_t sa = sb + row*80 + seg*16;
                uint32_t ga = (uint32_t)(m0+row)*256 + (kc+1)*16 + seg*4;
                uint32_t gb = (uint32_t)(n0+row)*256 + (kc+1)*16 + seg*4;
                CP16(sa,         Xh + ga);
                CP16(sa + 10240, Xl + ga);
                CP16(sa + 20480, Wh + gb);
                CP16(sa + 30720, Wl + gb);
            }
            CP_COMMIT();
        }

        #pragma unroll
        for (int ks = 0; ks < 2; ks++) {
            uint32_t ah[2][4], al[2][4], bh4[4][4], bl4[4][4];
            #pragma unroll
            for (int mf = 0; mf < 2; mf++) {
                ldsm4(ah[mf], abase + bo_ + mf*1280 + ks*32);
                ldsm4(al[mf], abase + bo_ + mf*1280 + ks*32 + 10240);
            }
            #pragma unroll
            for (int np = 0; np < 4; np++) {
                ldsm4(bh4[np], bbase + bo_ + np*1280 + ks*32);
                ldsm4(bl4[np], bbase + bo_ + np*1280 + ks*32 + 10240);
            }
            #pragma unroll
            for (int mf = 0; mf < 2; mf++)
                #pragma unroll
                for (int np = 0; np < 4; np++) {
                    mma16816(acc[mf][2*np  ], ah[mf], &bh4[np][0]);
                    mma16816(acc[mf][2*np  ], ah[mf], &bl4[np][0]);
                    mma16816(acc[mf][2*np  ], al[mf], &bh4[np][0]);
                    mma16816(acc[mf][2*np+1], ah[mf], &bh4[np][2]);
                    mma16816(acc[mf][2*np+1], ah[mf], &bl4[np][2]);
                    mma16816(acc[mf][2*np+1], al[mf], &bh4[np][2]);
                }
        }

        if (more) CP_WAIT0();
        __syncthreads();
    }

    // ---- epilogues ----
    if (out_sel == 0) {
        #pragma unroll
        for (int mf = 0; mf < 2; mf++) {
            int r0 = mw*32 + mf*16 + g;
            #pragma unroll
            for (int nf = 0; nf < 8; nf++) {
                int col = n0 + nw*64 + nf*8 + 2*c;
                float2 bb = *(const float2*)&Bv[col];
                float2 o0 = {acc[mf][nf][0] + bb.x, acc[mf][nf][1] + bb.y};
                float2 o1 = {acc[mf][nf][2] + bb.x, acc[mf][nf][3] + bb.y};
                *(float2*)&Out[(size_t)(m0+r0  )*NFEAT + col] = o0;
                *(float2*)&Out[(size_t)(m0+r0+8)*NFEAT + col] = o1;
            }
        }
    } else if (out_sel == 1 || out_sel == 2) {
        __nv_bfloat16* Oh = (out_sel == 1) ? g_q_h : g_k_h;
        __nv_bfloat16* Ol = (out_sel == 1) ? g_q_l : g_k_l;
        // Q scale = log2(e)/8 so attention can use exp2f
        const float scl = (out_sel == 1) ? 0.1803368801111204f : 1.0f;
        #pragma unroll
        for (int mf = 0; mf < 2; mf++)
            #pragma unroll
            for (int half = 0; half < 2; half++) {
                int m  = m0 + mw*32 + mf*16 + g + half*8;
                int bb_ = m >> 11, tt = m & (T_SEQ - 1);
                #pragma unroll
                for (int nf = 0; nf < 8; nf++) {
                    int col = nw*64 + nf*8 + 2*c;
                    int hh = (n0 + col) >> 6, d = (n0 + col) & 63;
                    float2 bb = *(const float2*)&Bv[n0 + col];
                    float v0 = (acc[mf][nf][half*2+0] + bb.x) * scl;
                    float v1 = (acc[mf][nf][half*2+1] + bb.y) * scl;
                    uint32_t hw, lw; split2(v0, v1, hw, lw);
                    size_t widx = (((size_t)(bb_*HEADS+hh)*T_SEQ + tt)*DK + d) >> 1;
                    ((uint32_t*)Oh)[widx] = hw;
                    ((uint32_t*)Ol)[widx] = lw;
                }
            }
    } else {
        // V: transpose to [bh][d][t] through smem, hi+lo staged together
        __nv_bfloat16* Tsh = (__nv_bfloat16*)smw;                       // [128n][136]
        __nv_bfloat16* Tsl = (__nv_bfloat16*)((char*)smw + 128*272);
        #pragma unroll
        for (int mf = 0; mf < 2; mf++)
            #pragma unroll
            for (int half = 0; half < 2; half++) {
                int t_loc = mw*32 + mf*16 + g + half*8;
                #pragma unroll
                for (int nf = 0; nf < 8; nf++) {
                    int col = nw*64 + nf*8 + 2*c;
                    float2 bb = *(const float2*)&Bv[n0 + col];
                    float v0 = acc[mf][nf][half*2+0] + bb.x;
                    float v1 = acc[mf][nf][half*2+1] + bb.y;
                    __nv_bfloat162 h2 = __floats2bfloat162_rn(v0, v1);
                    __nv_bfloat162 l2 = __floats2bfloat162_rn(
                        v0 - __low2float(h2), v1 - __high2float(h2));
                    Tsh[(size_t)(col  )*136 + t_loc] = h2.x;
                    Tsh[(size_t)(col+1)*136 + t_loc] = h2.y;
                    Tsl[(size_t)(col  )*136 + t_loc] = l2.x;
                    Tsl[(size_t)(col+1)*136 + t_loc] = l2.y;
                }
            }
        __syncthreads();
        int bb_ = m0 >> 11, tt0 = m0 & (T_SEQ - 1);
        #pragma unroll
        for (int l = 0; l < 8; l++) {
            int idx = tid + l * 256, n = idx >> 4, j = idx & 15;
            int hh = (n0 >> 6) + (n >> 6), d = n & 63;
            size_t go = ((size_t)(bb_*HEADS + hh)*DK + d)*T_SEQ + tt0 + j*8;
            *(uint4*)&g_vt_h[go] = *(uint4*)((char*)Tsh + (size_t)n*272 + j*16);
            *(uint4*)&g_vt_l[go] = *(uint4*)((char*)Tsl + (size_t)n*272 + j*16);
        }
    }
}

// ---------------------------------------------------------------------------
// bf16-3x attention (round-8 structure; exp2f; bf16 hi/lo output).
// ---------------------------------------------------------------------------
#define AQH 0
#define AQL 18432
#define ABUF 36864
#define AMB 110592
#define ATTN_SMEM 111104

static __device__ __forceinline__ void attn_issue_tile(
    uint32_t kbase, int bh, int kt, int tid)
{
    #pragma unroll
    for (int l = 0; l < 2; l++) {
        int idx = tid + l * 256, row = idx >> 3, j = idx & 7;
        uint32_t soff = row * 144 + j * 16;
        size_t kg = ((size_t)bh * T_SEQ + kt + row) * DK + j * 8;
        size_t vg = ((size_t)bh * DK + row) * T_SEQ + kt + j * 8;
        CP16(kbase +     0 + soff, (const char*)&g_k_h[kg]);
        CP16(kbase +  9216 + soff, (const char*)&g_k_l[kg]);
        CP16(kbase + 18432 + soff, (const char*)&g_vt_h[vg]);
        CP16(kbase + 27648 + soff, (const char*)&g_vt_l[vg]);
    }
    CP_COMMIT();
}

__global__ __launch_bounds__(256) void attn_tc(const int* __restrict__ mask)
{
    extern __shared__ char sm[];
    const uint32_t sb = smem_u32(sm);
    float* mbufF = (float*)(sm + AMB);

    const int tid = threadIdx.x, lane = tid & 31, wid = tid >> 5;
    const int c = lane & 3;
    const int bh = blockIdx.y, b = bh >> 3, h = bh & 7;
    const int q0 = blockIdx.x * 128;
    const int rb = wid * 16;

    const uint32_t q_amem = sb + AQH + (uint32_t)rb*144 + a_lane_off(lane);
    const uint32_t b_off  = b_lane_off(lane);

    #pragma unroll
    for (int l = 0; l < 4; l++) {
        int idx = tid + l * 256, row = idx >> 3, j = idx & 7;
        size_t gsrc = ((size_t)bh*T_SEQ + q0 + row)*DK + j*8;
        *(uint4*)(sm + AQH + row*144 + j*16) = *(const uint4*)&g_q_h[gsrc];
        *(uint4*)(sm + AQL + row*144 + j*16) = *(const uint4*)&g_q_l[gsrc];
    }
    attn_issue_tile(sb + ABUF, bh, 0, tid);
    if (tid < 64) mbufF[tid] = (float)mask[b*T_SEQ + tid];
    CP_WAIT0();
    __syncthreads();

    float oacc[8][4] = {};
    float lacc0 = 0.f, lacc1 = 0.f;

    for (int it = 0; it < T_SEQ / 64; it++) {
        const int cur = it & 1;
        const uint32_t kb = sb + ABUF + cur * 36864 + b_off;
        const uint32_t vb = kb + 18432;

        int mreg = 0;
        const bool more = (it + 1 < T_SEQ / 64);
        if (more) {
            attn_issue_tile(sb + ABUF + (cur ^ 1) * 36864, bh, (it+1)*64, tid);
            if (tid < 64) mreg = mask[b*T_SEQ + (it+1)*64 + tid];
        }

        // ---- S = Q K^T (Q prescaled by log2e/8) ----
        float sacc[8][4] = {};
        #pragma unroll
        for (int ks = 0; ks < 4; ks++) {
            uint32_t ah[4], al[4];
            ldsm4(ah, q_amem + ks*32);
            ldsm4(al, q_amem + ks*32 + 18432);
            #pragma unroll
            for (int np = 0; np < 4; np++) {
                uint32_t kh4[4], kl4[4];
                ldsm4(kh4, kb + np*2304 + ks*32);
                ldsm4(kl4, kb + np*2304 + ks*32 + 9216);
                mma16816(sacc[2*np  ], ah, &kh4[0]);
                mma16816(sacc[2*np  ], ah, &kl4[0]);
                mma16816(sacc[2*np  ], al, &kh4[0]);
                mma16816(sacc[2*np+1], ah, &kh4[2]);
                mma16816(sacc[2*np+1], ah, &kl4[2]);
                mma16816(sacc[2*np+1], al, &kh4[2]);
            }
        }

        // ---- exp2 + mask + row-sum; P stays in registers ----
        uint32_t ph[8][2], pl[8][2];
        #pragma unroll
        for (int nf = 0; nf < 8; nf++) {
            int cb = nf*8 + 2*c;
            float m0v = mbufF[cur*64 + cb], m1v = mbufF[cur*64 + cb + 1];
            float e0 = exp2f(sacc[nf][0]) * m0v;
            float e1 = exp2f(sacc[nf][1]) * m1v;
            float e2 = exp2f(sacc[nf][2]) * m0v;
            float e3 = exp2f(sacc[nf][3]) * m1v;
            lacc0 += e0 + e1;
            lacc1 += e2 + e3;
            split2(e0, e1, ph[nf][0], pl[nf][0]);
            split2(e2, e3, ph[nf][1], pl[nf][1]);
        }

        // ---- O += P V (m16n8k16, paired P fragments) ----
        #pragma unroll
        for (int kg = 0; kg < 4; kg++) {
            uint32_t pa_h[4] = {ph[2*kg][0], ph[2*kg][1],
                                ph[2*kg+1][0], ph[2*kg+1][1]};
            uint32_t pa_l[4] = {pl[2*kg][0], pl[2*kg][1],
                                pl[2*kg+1][0], pl[2*kg+1][1]};
            #pragma unroll
            for (int np = 0; np < 4; np++) {
                uint32_t vh4[4], vl4[4];
                ldsm4(vh4, vb + np*2304 + kg*32);
                ldsm4(vl4, vb + np*2304 + kg*32 + 9216);
                mma16816(oacc[2*np  ], pa_h, &vh4[0]);
                mma16816(oacc[2*np  ], pa_h, &vl4[0]);
                mma16816(oacc[2*np  ], pa_l, &vh4[0]);
                mma16816(oacc[2*np+1], pa_h, &vh4[2]);
                mma16816(oacc[2*np+1], pa_h, &vl4[2]);
                mma16816(oacc[2*np+1], pa_l, &vh4[2]);
            }
        }

        if (more) {
            if (tid < 64) mbufF[(cur ^ 1)*64 + tid] = (float)mreg;
            CP_WAIT0();
        }
        __syncthreads();
    }

    lacc0 += __shfl_xor_sync(0xffffffffu, lacc0, 1);
    lacc0 += __shfl_xor_sync(0xffffffffu, lacc0, 2);
    lacc1 += __shfl_xor_sync(0xffffffffu, lacc1, 1);
    lacc1 += __shfl_xor_sync(0xffffffffu, lacc1, 2);
    float inv0 = (lacc0 > 0.f) ? 1.f / (lacc0 * (1.f + 1e-8f)) : 0.f;
    float inv1 = (lacc1 > 0.f) ? 1.f / (lacc1 * (1.f + 1e-8f)) : 0.f;

    const int g = lane >> 2;
    const int row0 = q0 + rb + g, row1 = row0 + 8;
    #pragma unroll
    for (int nd = 0; nd < 8; nd++) {
        int colw = h*32 + nd*4 + c;            // word index within 256-word row
        uint32_t hw, lw;
        split2(oacc[nd][0] * inv0, oacc[nd][1] * inv0, hw, lw);
        g_x_h[(size_t)(b*T_SEQ + row0)*256 + colw] = hw;
        g_x_l[(size_t)(b*T_SEQ + row0)*256 + colw] = lw;
        split2(oacc[nd][2] * inv1, oacc[nd][3] * inv1, hw, lw);
        g_x_h[(size_t)(b*T_SEQ + row1)*256 + colw] = hw;
        g_x_l[(size_t)(b*T_SEQ + row1)*256 + colw] = lw;
    }
}

// ---------------------------------------------------------------------------
extern "C" void kernel_launch(void* const* d_in, const int* in_sizes, int n_in,
                              void* d_out, int out_size)
{
    const float* query = (const float*)d_in[0];
    const float* key_  = (const float*)d_in[1];
    const float* value = (const float*)d_in[2];
    const int*   mask  = (const int*)d_in[3];
    const float* Wq = (const float*)d_in[4];
    const float* bq = (const float*)d_in[5];
    const float* Wk = (const float*)d_in[6];
    const float* bk = (const float*)d_in[7];
    const float* Wv = (const float*)d_in[8];
    const float* bv = (const float*)d_in[9];
    const float* Wo = (const float*)d_in[10];
    const float* bo = (const float*)d_in[11];
    float* out = (float*)d_out;

    uint32_t *inh, *inl, *wth, *wtl, *xh, *xl;
    cudaGetSymbolAddress((void**)&inh, g_in_h);
    cudaGetSymbolAddress((void**)&inl, g_in_l);
    cudaGetSymbolAddress((void**)&wth, g_wt_h);
    cudaGetSymbolAddress((void**)&wtl, g_wt_l);
    cudaGetSymbolAddress((void**)&xh, g_x_h);
    cudaGetSymbolAddress((void**)&xl, g_x_l);

    const int NPI = MTOT * 256;      // pairs per input  (2,097,152)
    const int NPW = 512 * 256;       // pairs per weight (131,072)

    conv_pairs<<<2048, 256>>>(query, inh,           inl,           NPI);
    conv_pairs<<<2048, 256>>>(key_,  inh + NPI,     inl + NPI,     NPI);
    conv_pairs<<<2048, 256>>>(value, inh + 2*NPI,   inl + 2*NPI,   NPI);
    conv_pairs<<<512, 256>>>(Wq, wth,         wtl,         NPW);
    conv_pairs<<<512, 256>>>(Wk, wth + NPW,   wtl + NPW,   NPW);
    conv_pairs<<<512, 256>>>(Wv, wth + 2*NPW, wtl + 2*NPW, NPW);
    conv_pairs<<<512, 256>>>(Wo, wth + 3*NPW, wtl + 3*NPW, NPW);

    cudaFuncSetAttribute(gemm_tc, cudaFuncAttributeMaxDynamicSharedMemorySize,
                         GEMM_SMEM);
    cudaFuncSetAttribute(attn_tc, cudaFuncAttributeMaxDynamicSharedMemorySize,
                         ATTN_SMEM);

    dim3 gg(NFEAT / 128, MTOT / 128);   // (4, 64)

    gemm_tc<<<gg, 256, GEMM_SMEM>>>(inh,         inl,         wth,         wtl,         bq, nullptr, 1);
    gemm_tc<<<gg, 256, GEMM_SMEM>>>(inh + NPI,   inl + NPI,   wth + NPW,   wtl + NPW,   bk, nullptr, 2);
    gemm_tc<<<gg, 256, GEMM_SMEM>>>(inh + 2*NPI, inl + 2*NPI, wth + 2*NPW, wtl + 2*NPW, bv, nullptr, 3);

    attn_tc<<<dim3(T_SEQ / 128, BHTOT), 256, ATTN_SMEM>>>(mask);

    gemm_tc<<<gg, 256, GEMM_SMEM>>>(xh, xl, wth + 3*NPW, wtl + 3*NPW, bo, out, 0);
}

// round 10
// speedup vs baseline: 1.3265x; 1.0714x over previous
#include <cuda_runtime.h>
#include <cuda_bf16.h>
#include <cstdint>

#define T_SEQ 2048
#define NFEAT 512
#define HEADS 8
#define DK 64
#define BHTOT 32
#define MTOT 8192

// Q pre-scaled by log2(e)/8 (exp2 in attn). V stored transposed.
__device__ __nv_bfloat16 g_q_h[(size_t)BHTOT*T_SEQ*DK];
__device__ __nv_bfloat16 g_q_l[(size_t)BHTOT*T_SEQ*DK];
__device__ __nv_bfloat16 g_k_h[(size_t)BHTOT*T_SEQ*DK];
__device__ __nv_bfloat16 g_k_l[(size_t)BHTOT*T_SEQ*DK];
__device__ __nv_bfloat16 g_vt_h[(size_t)BHTOT*DK*T_SEQ];   // [bh][d][t]
__device__ __nv_bfloat16 g_vt_l[(size_t)BHTOT*DK*T_SEQ];
__device__ uint32_t g_in_h[(size_t)3*MTOT*256];   // preconverted inputs
__device__ uint32_t g_in_l[(size_t)3*MTOT*256];
__device__ uint32_t g_wt_h[(size_t)4*512*256];    // preconverted weights
__device__ uint32_t g_wt_l[(size_t)4*512*256];
__device__ uint32_t g_x_h[(size_t)MTOT*256];      // attn out bf16 hi/lo
__device__ uint32_t g_x_l[(size_t)MTOT*256];

#define NPI (MTOT*256)
#define NPW (512*256)

static __device__ __forceinline__ void split2(float x, float y,
                                              uint32_t& hw, uint32_t& lw) {
    __nv_bfloat162 h = __floats2bfloat162_rn(x, y);
    float hx = __low2float(h), hy = __high2float(h);
    __nv_bfloat162 l = __floats2bfloat162_rn(x - hx, y - hy);
    hw = *reinterpret_cast<uint32_t*>(&h);
    lw = *reinterpret_cast<uint32_t*>(&l);
}

static __device__ __forceinline__ void mma16816(float* d, const uint32_t* a,
                                                const uint32_t* b) {
    asm volatile(
        "mma.sync.aligned.m16n8k16.row.col.f32.bf16.bf16.f32 "
        "{%0,%1,%2,%3}, {%4,%5,%6,%7}, {%8,%9}, {%0,%1,%2,%3};"
        : "+f"(d[0]), "+f"(d[1]), "+f"(d[2]), "+f"(d[3])
        : "r"(a[0]), "r"(a[1]), "r"(a[2]), "r"(a[3]), "r"(b[0]), "r"(b[1]));
}

static __device__ __forceinline__ void ldsm4(uint32_t* r, uint32_t addr) {
    asm volatile(
        "ldmatrix.sync.aligned.m8n8.x4.shared.b16 {%0,%1,%2,%3}, [%4];"
        : "=r"(r[0]), "=r"(r[1]), "=r"(r[2]), "=r"(r[3]) : "r"(addr));
}

static __device__ __forceinline__ uint32_t smem_u32(const void* p) {
    uint32_t a;
    asm("{ .reg .u64 t; cvta.to.shared.u64 t, %1; cvt.u32.u64 %0, t; }"
        : "=r"(a) : "l"(p));
    return a;
}

#define CP16(saddr, gptr) \
    asm volatile("cp.async.ca.shared.global [%0], [%1], 16;" \
                 :: "r"(saddr), "l"(gptr))
#define CP_COMMIT() asm volatile("cp.async.commit_group;" ::: "memory")
#define CP_WAIT0()  asm volatile("cp.async.wait_group 0;" ::: "memory")

// ldmatrix lane offsets, 144-byte rows (attn)
static __device__ __forceinline__ uint32_t a_lane_off(int lane) {
    return (uint32_t)((lane & 15) * 144 + ((lane & 16) ? 16 : 0));
}
static __device__ __forceinline__ uint32_t b_lane_off(int lane) {
    return (uint32_t)(((lane & 7) + ((lane >> 4) & 1) * 8) * 144 +
                      ((lane & 8) ? 16 : 0));
}
// ldmatrix lane offsets, 80-byte rows (gemm)
static __device__ __forceinline__ uint32_t a80_off(int lane) {
    return (uint32_t)((lane & 15) * 80 + ((lane & 16) ? 16 : 0));
}
static __device__ __forceinline__ uint32_t b80_off(int lane) {
    return (uint32_t)(((lane & 7) + ((lane >> 4) & 1) * 8) * 80 +
                      ((lane & 8) ? 16 : 0));
}

// ---------------------------------------------------------------------------
// One merged converter for all 3 inputs + 4 weights.
// ---------------------------------------------------------------------------
__global__ void conv_all(const float* __restrict__ q, const float* __restrict__ k,
                         const float* __restrict__ v, const float* __restrict__ wq,
                         const float* __restrict__ wk, const float* __restrict__ wv,
                         const float* __restrict__ wo)
{
    const int total = 3*NPI + 4*NPW;
    for (int i = blockIdx.x * blockDim.x + threadIdx.x; i < total;
         i += gridDim.x * blockDim.x) {
        const float* src; uint32_t *dh, *dl; int off;
        if (i < NPI)            { src = q;  off = i;             dh = g_in_h; dl = g_in_l; }
        else if (i < 2*NPI)     { src = k;  off = i - NPI;       dh = g_in_h + NPI;   dl = g_in_l + NPI; }
        else if (i < 3*NPI)     { src = v;  off = i - 2*NPI;     dh = g_in_h + 2*NPI; dl = g_in_l + 2*NPI; }
        else if (i < 3*NPI+NPW) { src = wq; off = i - 3*NPI;     dh = g_wt_h; dl = g_wt_l; }
        else if (i < 3*NPI+2*NPW){src = wk; off = i-3*NPI-NPW;   dh = g_wt_h + NPW;   dl = g_wt_l + NPW; }
        else if (i < 3*NPI+3*NPW){src = wv; off = i-3*NPI-2*NPW; dh = g_wt_h + 2*NPW; dl = g_wt_l + 2*NPW; }
        else                    { src = wo; off = i-3*NPI-3*NPW; dh = g_wt_h + 3*NPW; dl = g_wt_l + 3*NPW; }
        float2 p = ((const float2*)src)[off];
        uint32_t hw, lw; split2(p.x, p.y, hw, lw);
        dh[off] = hw; dl[off] = lw;
    }
}

// ---------------------------------------------------------------------------
// bf16-3x GEMM, 128 threads, 4 warps (2m x 2n), warp tile 64x64, k-chunk 32,
// cp.async double-buffered. out_sel: 0=Out fp32; -1=QKV via blockIdx.z.
// SMEM per buffer 40960 (Ah+0, Al+10240, Bh+20480, Bl+30720; 80 B rows).
// ---------------------------------------------------------------------------
#define GEMM_SMEM 81920
extern __shared__ uint32_t smw[];

__global__ __launch_bounds__(128) void gemm_tc(
    const uint32_t* __restrict__ Xh, const uint32_t* __restrict__ Xl,
    const uint32_t* __restrict__ Wh, const uint32_t* __restrict__ Wl,
    const float* __restrict__ b0, const float* __restrict__ b1,
    const float* __restrict__ b2, float* __restrict__ Out, int out_sel)
{
    const int tid = threadIdx.x, lane = tid & 31, wid = tid >> 5;
    const int g = lane >> 2, c = lane & 3;
    const int mw = wid >> 1, nw = wid & 1;
    const int m0 = blockIdx.y * 128, n0 = blockIdx.x * 128;

    int sel = out_sel;
    const float* Bv = b0;
    if (out_sel < 0) {
        int z = blockIdx.z;
        sel = 1 + z;
        Xh += (size_t)z * NPI; Xl += (size_t)z * NPI;
        Wh += (size_t)z * NPW; Wl += (size_t)z * NPW;
        Bv = (z == 0) ? b0 : (z == 1) ? b1 : b2;
    }

    const uint32_t sbg = smem_u32(smw);
    const uint32_t abase = sbg + (uint32_t)(mw*64)*80 + a80_off(lane);
    const uint32_t bbase = sbg + 20480u + (uint32_t)(nw*64)*80 + b80_off(lane);

    const int seg = tid & 3;
    const int row0 = tid >> 2;          // 0..31; rows row0 + 32*l

    float acc[4][8][4] = {};

    // prologue: chunk 0
    #pragma unroll
    for (int l = 0; l < 4; l++) {
        int row = row0 + l*32;
        uint32_t sa = sbg + row*80 + seg*16;
        uint32_t ga = (uint32_t)(m0+row)*256 + seg*4;
        uint32_t gb = (uint32_t)(n0+row)*256 + seg*4;
        CP16(sa,         Xh + ga);
        CP16(sa + 10240, Xl + ga);
        CP16(sa + 20480, Wh + gb);
        CP16(sa + 30720, Wl + gb);
    }
    CP_COMMIT();
    CP_WAIT0();
    __syncthreads();

    for (int kc = 0; kc < 16; kc++) {
        const uint32_t bo_ = (uint32_t)(kc & 1) * 40960u;
        const bool more = (kc + 1 < 16);
        if (more) {
            uint32_t sb = sbg + (uint32_t)((kc+1) & 1) * 40960u;
            #pragma unroll
            for (int l = 0; l < 4; l++) {
                int row = row0 + l*32;
                uint32_t sa = sb + row*80 + seg*16;
                uint32_t ga = (uint32_t)(m0+row)*256 + (kc+1)*16 + seg*4;
                uint32_t gb = (uint32_t)(n0+row)*256 + (kc+1)*16 + seg*4;
                CP16(sa,         Xh + ga);
                CP16(sa + 10240, Xl + ga);
                CP16(sa + 20480, Wh + gb);
                CP16(sa + 30720, Wl + gb);
            }
            CP_COMMIT();
        }

        #pragma unroll
        for (int ks = 0; ks < 2; ks++) {
            uint32_t ah[4][4], al[4][4], bh4[4][4], bl4[4][4];
            #pragma unroll
            for (int mf = 0; mf < 4; mf++) {
                ldsm4(ah[mf], abase + bo_ + mf*1280 + ks*32);
                ldsm4(al[mf], abase + bo_ + mf*1280 + ks*32 + 10240);
            }
            #pragma unroll
            for (int np = 0; np < 4; np++) {
                ldsm4(bh4[np], bbase + bo_ + np*1280 + ks*32);
                ldsm4(bl4[np], bbase + bo_ + np*1280 + ks*32 + 10240);
            }
            #pragma unroll
            for (int mf = 0; mf < 4; mf++)
                #pragma unroll
                for (int np = 0; np < 4; np++) {
                    mma16816(acc[mf][2*np  ], ah[mf], &bh4[np][0]);
                    mma16816(acc[mf][2*np  ], ah[mf], &bl4[np][0]);
                    mma16816(acc[mf][2*np  ], al[mf], &bh4[np][0]);
                    mma16816(acc[mf][2*np+1], ah[mf], &bh4[np][2]);
                    mma16816(acc[mf][2*np+1], ah[mf], &bl4[np][2]);
                    mma16816(acc[mf][2*np+1], al[mf], &bh4[np][2]);
                }
        }

        if (more) CP_WAIT0();
        __syncthreads();
    }

    // ---- epilogues ----
    if (sel == 0) {
        #pragma unroll
        for (int mf = 0; mf < 4; mf++) {
            int r0 = mw*64 + mf*16 + g;
            #pragma unroll
            for (int nf = 0; nf < 8; nf++) {
                int col = n0 + nw*64 + nf*8 + 2*c;
                float2 bb = *(const float2*)&Bv[col];
                float2 o0 = {acc[mf][nf][0] + bb.x, acc[mf][nf][1] + bb.y};
                float2 o1 = {acc[mf][nf][2] + bb.x, acc[mf][nf][3] + bb.y};
                *(float2*)&Out[(size_t)(m0+r0  )*NFEAT + col] = o0;
                *(float2*)&Out[(size_t)(m0+r0+8)*NFEAT + col] = o1;
            }
        }
    } else if (sel == 1 || sel == 2) {
        __nv_bfloat16* Oh = (sel == 1) ? g_q_h : g_k_h;
        __nv_bfloat16* Ol = (sel == 1) ? g_q_l : g_k_l;
        const float scl = (sel == 1) ? 0.1803368801111204f : 1.0f;  // log2e/8
        #pragma unroll
        for (int mf = 0; mf < 4; mf++)
            #pragma unroll
            for (int half = 0; half < 2; half++) {
                int m  = m0 + mw*64 + mf*16 + g + half*8;
                int bb_ = m >> 11, tt = m & (T_SEQ - 1);
                #pragma unroll
                for (int nf = 0; nf < 8; nf++) {
                    int col = nw*64 + nf*8 + 2*c;
                    int hh = (n0 + col) >> 6, d = (n0 + col) & 63;
                    float2 bb = *(const float2*)&Bv[n0 + col];
                    float v0 = (acc[mf][nf][half*2+0] + bb.x) * scl;
                    float v1 = (acc[mf][nf][half*2+1] + bb.y) * scl;
                    uint32_t hw, lw; split2(v0, v1, hw, lw);
                    size_t widx = (((size_t)(bb_*HEADS+hh)*T_SEQ + tt)*DK + d) >> 1;
                    ((uint32_t*)Oh)[widx] = hw;
                    ((uint32_t*)Ol)[widx] = lw;
                }
            }
    } else {
        // V: transpose to [bh][d][t] through smem
        __nv_bfloat16* Tsh = (__nv_bfloat16*)smw;                      // [128n][136]
        __nv_bfloat16* Tsl = (__nv_bfloat16*)((char*)smw + 128*272);
        #pragma unroll
        for (int mf = 0; mf < 4; mf++)
            #pragma unroll
            for (int half = 0; half < 2; half++) {
                int t_loc = mw*64 + mf*16 + g + half*8;
                #pragma unroll
                for (int nf = 0; nf < 8; nf++) {
                    int col = nw*64 + nf*8 + 2*c;
                    float2 bb = *(const float2*)&Bv[n0 + col];
                    float v0 = acc[mf][nf][half*2+0] + bb.x;
                    float v1 = acc[mf][nf][half*2+1] + bb.y;
                    __nv_bfloat162 h2 = __floats2bfloat162_rn(v0, v1);
                    __nv_bfloat162 l2 = __floats2bfloat162_rn(
                        v0 - __low2float(h2), v1 - __high2float(h2));
                    Tsh[(size_t)(col  )*136 + t_loc] = h2.x;
                    Tsh[(size_t)(col+1)*136 + t_loc] = h2.y;
                    Tsl[(size_t)(col  )*136 + t_loc] = l2.x;
                    Tsl[(size_t)(col+1)*136 + t_loc] = l2.y;
                }
            }
        __syncthreads();
        int bb_ = m0 >> 11, tt0 = m0 & (T_SEQ - 1);
        #pragma unroll
        for (int l = 0; l < 16; l++) {
            int idx = tid + l * 128, n = idx >> 4, j = idx & 15;
            int hh = (n0 >> 6) + (n >> 6), d = n & 63;
            size_t go = ((size_t)(bb_*HEADS + hh)*DK + d)*T_SEQ + tt0 + j*8;
            *(uint4*)&g_vt_h[go] = *(uint4*)((char*)Tsh + (size_t)n*272 + j*16);
            *(uint4*)&g_vt_l[go] = *(uint4*)((char*)Tsl + (size_t)n*272 + j*16);
        }
    }
}

// ---------------------------------------------------------------------------
// bf16-3x attention: 128 threads, 4 warps x 32 q-rows. K/V fragments shared
// across 2 m-frags per warp (halves smem traffic). exp2f; bf16 hi/lo output.
// ---------------------------------------------------------------------------
#define AQH 0
#define AQL 18432
#define ABUF 36864
#define AMB 110592
#define ATTN_SMEM 111104

static __device__ __forceinline__ void attn_issue_tile(
    uint32_t kbase, int bh, int kt, int tid)
{
    #pragma unroll
    for (int l = 0; l < 4; l++) {
        int idx = tid + l * 128, row = idx >> 3, j = idx & 7;
        uint32_t soff = row * 144 + j * 16;
        size_t kg = ((size_t)bh * T_SEQ + kt + row) * DK + j * 8;
        size_t vg = ((size_t)bh * DK + row) * T_SEQ + kt + j * 8;
        CP16(kbase +     0 + soff, (const char*)&g_k_h[kg]);
        CP16(kbase +  9216 + soff, (const char*)&g_k_l[kg]);
        CP16(kbase + 18432 + soff, (const char*)&g_vt_h[vg]);
        CP16(kbase + 27648 + soff, (const char*)&g_vt_l[vg]);
    }
    CP_COMMIT();
}

__global__ __launch_bounds__(128) void attn_tc(const int* __restrict__ mask)
{
    extern __shared__ char sm[];
    const uint32_t sb = smem_u32(sm);
    float* mbufF = (float*)(sm + AMB);

    const int tid = threadIdx.x, lane = tid & 31, wid = tid >> 5;
    const int c = lane & 3;
    const int bh = blockIdx.y, b = bh >> 3, h = bh & 7;
    const int q0 = blockIdx.x * 128;
    const int rb = wid * 32;

    const uint32_t q_amem = sb + AQH + (uint32_t)rb*144 + a_lane_off(lane);
    const uint32_t b_off  = b_lane_off(lane);

    #pragma unroll
    for (int l = 0; l < 8; l++) {
        int idx = tid + l * 128, row = idx >> 3, j = idx & 7;
        size_t gsrc = ((size_t)bh*T_SEQ + q0 + row)*DK + j*8;
        *(uint4*)(sm + AQH + row*144 + j*16) = *(const uint4*)&g_q_h[gsrc];
        *(uint4*)(sm + AQL + row*144 + j*16) = *(const uint4*)&g_q_l[gsrc];
    }
    attn_issue_tile(sb + ABUF, bh, 0, tid);
    if (tid < 64) mbufF[tid] = (float)mask[b*T_SEQ + tid];
    CP_WAIT0();
    __syncthreads();

    float oacc[2][8][4] = {};
    float lacc[2][2] = {};

    for (int it = 0; it < T_SEQ / 64; it++) {
        const int cur = it & 1;
        const uint32_t kb = sb + ABUF + cur * 36864 + b_off;
        const uint32_t vb = kb + 18432;

        int mreg = 0;
        const bool more = (it + 1 < T_SEQ / 64);
        if (more) {
            attn_issue_tile(sb + ABUF + (cur ^ 1) * 36864, bh, (it+1)*64, tid);
            if (tid < 64) mreg = mask[b*T_SEQ + (it+1)*64 + tid];
        }

        // ---- S = Q K^T : 32 rows x 64 keys; K frags shared across m-frags --
        float sacc[2][8][4] = {};
        #pragma unroll
        for (int ks = 0; ks < 4; ks++) {
            uint32_t ah[2][4], al[2][4];
            #pragma unroll
            for (int mf = 0; mf < 2; mf++) {
                ldsm4(ah[mf], q_amem + mf*2304 + ks*32);
                ldsm4(al[mf], q_amem + mf*2304 + ks*32 + 18432);
            }
            #pragma unroll
            for (int np = 0; np < 4; np++) {
                uint32_t kh4[4], kl4[4];
                ldsm4(kh4, kb + np*2304 + ks*32);
                ldsm4(kl4, kb + np*2304 + ks*32 + 9216);
                #pragma unroll
                for (int mf = 0; mf < 2; mf++) {
                    mma16816(sacc[mf][2*np  ], ah[mf], &kh4[0]);
                    mma16816(sacc[mf][2*np  ], ah[mf], &kl4[0]);
                    mma16816(sacc[mf][2*np  ], al[mf], &kh4[0]);
                    mma16816(sacc[mf][2*np+1], ah[mf], &kh4[2]);
                    mma16816(sacc[mf][2*np+1], ah[mf], &kl4[2]);
                    mma16816(sacc[mf][2*np+1], al[mf], &kh4[2]);
                }
            }
        }

        // ---- exp2 + mask + row-sum; P fragments stay in registers ----
        uint32_t ph[2][8][2], pl[2][8][2];
        #pragma unroll
        for (int mf = 0; mf < 2; mf++)
            #pragma unroll
            for (int nf = 0; nf < 8; nf++) {
                int cb = nf*8 + 2*c;
                float m0v = mbufF[cur*64 + cb], m1v = mbufF[cur*64 + cb + 1];
                float e0 = exp2f(sacc[mf][nf][0]) * m0v;
                float e1 = exp2f(sacc[mf][nf][1]) * m1v;
                float e2 = exp2f(sacc[mf][nf][2]) * m0v;
                float e3 = exp2f(sacc[mf][nf][3]) * m1v;
                lacc[mf][0] += e0 + e1;
                lacc[mf][1] += e2 + e3;
                split2(e0, e1, ph[mf][nf][0], pl[mf][nf][0]);
                split2(e2, e3, ph[mf][nf][1], pl[mf][nf][1]);
            }

        // ---- O += P V : V frags shared across m-frags ----
        #pragma unroll
        for (int kg = 0; kg < 4; kg++) {
            uint32_t pah[2][4], pal[2][4];
            #pragma unroll
            for (int mf = 0; mf < 2; mf++) {
                pah[mf][0] = ph[mf][2*kg][0]; pah[mf][1] = ph[mf][2*kg][1];
                pah[mf][2] = ph[mf][2*kg+1][0]; pah[mf][3] = ph[mf][2*kg+1][1];
                pal[mf][0] = pl[mf][2*kg][0]; pal[mf][1] = pl[mf][2*kg][1];
                pal[mf][2] = pl[mf][2*kg+1][0]; pal[mf][3] = pl[mf][2*kg+1][1];
            }
            #pragma unroll
            for (int np = 0; np < 4; np++) {
                uint32_t vh4[4], vl4[4];
                ldsm4(vh4, vb + np*2304 + kg*32);
                ldsm4(vl4, vb + np*2304 + kg*32 + 9216);
                #pragma unroll
                for (int mf = 0; mf < 2; mf++) {
                    mma16816(oacc[mf][2*np  ], pah[mf], &vh4[0]);
                    mma16816(oacc[mf][2*np  ], pah[mf], &vl4[0]);
                    mma16816(oacc[mf][2*np  ], pal[mf], &vh4[0]);
                    mma16816(oacc[mf][2*np+1], pah[mf], &vh4[2]);
                    mma16816(oacc[mf][2*np+1], pah[mf], &vl4[2]);
                    mma16816(oacc[mf][2*np+1], pal[mf], &vh4[2]);
                }
            }
        }

        if (more) {
            if (tid < 64) mbufF[(cur ^ 1)*64 + tid] = (float)mreg;
            CP_WAIT0();
        }
        __syncthreads();
    }

    // ---- reduce l, normalize, store bf16 hi/lo ----
    float inv[2][2];
    #pragma unroll
    for (int mf = 0; mf < 2; mf++)
        #pragma unroll
        for (int hf = 0; hf < 2; hf++) {
            float lv = lacc[mf][hf];
            lv += __shfl_xor_sync(0xffffffffu, lv, 1);
            lv += __shfl_xor_sync(0xffffffffu, lv, 2);
            inv[mf][hf] = (lv > 0.f) ? 1.f / (lv * (1.f + 1e-8f)) : 0.f;
        }

    const int g = lane >> 2;
    #pragma unroll
    for (int mf = 0; mf < 2; mf++) {
        const int row0 = q0 + rb + mf*16 + g, row1 = row0 + 8;
        #pragma unroll
        for (int nd = 0; nd < 8; nd++) {
            int colw = h*32 + nd*4 + c;
            uint32_t hw, lw;
            split2(oacc[mf][nd][0] * inv[mf][0], oacc[mf][nd][1] * inv[mf][0], hw, lw);
            g_x_h[(size_t)(b*T_SEQ + row0)*256 + colw] = hw;
            g_x_l[(size_t)(b*T_SEQ + row0)*256 + colw] = lw;
            split2(oacc[mf][nd][2] * inv[mf][1], oacc[mf][nd][3] * inv[mf][1], hw, lw);
            g_x_h[(size_t)(b*T_SEQ + row1)*256 + colw] = hw;
            g_x_l[(size_t)(b*T_SEQ + row1)*256 + colw] = lw;
        }
    }
}

// ---------------------------------------------------------------------------
extern "C" void kernel_launch(void* const* d_in, const int* in_sizes, int n_in,
                              void* d_out, int out_size)
{
    const float* query = (const float*)d_in[0];
    const float* key_  = (const float*)d_in[1];
    const float* value = (const float*)d_in[2];
    const int*   mask  = (const int*)d_in[3];
    const float* Wq = (const float*)d_in[4];
    const float* bq = (const float*)d_in[5];
    const float* Wk = (const float*)d_in[6];
    const float* bk = (const float*)d_in[7];
    const float* Wv = (const float*)d_in[8];
    const float* bv = (const float*)d_in[9];
    const float* Wo = (const float*)d_in[10];
    const float* bo = (const float*)d_in[11];
    float* out = (float*)d_out;

    uint32_t *inh, *inl, *wth, *wtl, *xh, *xl;
    cudaGetSymbolAddress((void**)&inh, g_in_h);
    cudaGetSymbolAddress((void**)&inl, g_in_l);
    cudaGetSymbolAddress((void**)&wth, g_wt_h);
    cudaGetSymbolAddress((void**)&wtl, g_wt_l);
    cudaGetSymbolAddress((void**)&xh, g_x_h);
    cudaGetSymbolAddress((void**)&xl, g_x_l);

    conv_all<<<2048, 256>>>(query, key_, value, Wq, Wk, Wv, Wo);

    cudaFuncSetAttribute(gemm_tc, cudaFuncAttributeMaxDynamicSharedMemorySize,
                         GEMM_SMEM);
    cudaFuncSetAttribute(attn_tc, cudaFuncAttributeMaxDynamicSharedMemorySize,
                         ATTN_SMEM);

    // QKV projections: one launch, blockIdx.z selects q/k/v
    gemm_tc<<<dim3(4, 64, 3), 128, GEMM_SMEM>>>(
        inh, inl, wth, wtl, bq, bk, bv, nullptr, -1);

    attn_tc<<<dim3(T_SEQ / 128, BHTOT), 128, ATTN_SMEM>>>(mask);

    gemm_tc<<<dim3(4, 64, 1), 128, GEMM_SMEM>>>(
        xh, xl, wth + 3*NPW, wtl + 3*NPW, bo, nullptr, nullptr, out, 0);
}

// round 11
// speedup vs baseline: 1.9777x; 1.4910x over previous
#include <cuda_runtime.h>
#include <cuda_fp16.h>
#include <cstdint>

#define T_SEQ 2048
#define NFEAT 512
#define HEADS 8
#define DK 64
#define BHTOT 32
#define MTOT 8192

// A-side operands split into fp16 hi/lo; B-side single fp16.
// Q pre-scaled by log2(e)/8 (exp2 in attn). V stored transposed [bh][d][t].
__device__ __half g_q_h[(size_t)BHTOT*T_SEQ*DK];
__device__ __half g_q_l[(size_t)BHTOT*T_SEQ*DK];
__device__ __half g_k[(size_t)BHTOT*T_SEQ*DK];
__device__ __half g_vt[(size_t)BHTOT*DK*T_SEQ];
__device__ uint32_t g_in_h[(size_t)3*MTOT*256];   // inputs hi (half2 words)
__device__ uint32_t g_in_l[(size_t)3*MTOT*256];   // inputs lo
__device__ uint32_t g_wt[(size_t)4*512*256];      // weights single fp16
__device__ uint32_t g_x_h[(size_t)MTOT*256];      // attn out hi/lo
__device__ uint32_t g_x_l[(size_t)MTOT*256];

#define NPI (MTOT*256)
#define NPW (512*256)

static __device__ __forceinline__ void split2h(float x, float y,
                                               uint32_t& hw, uint32_t& lw) {
    __half2 h = __floats2half2_rn(x, y);
    float hx = __low2float(h), hy = __high2float(h);
    __half2 l = __floats2half2_rn(x - hx, y - hy);
    hw = *reinterpret_cast<uint32_t*>(&h);
    lw = *reinterpret_cast<uint32_t*>(&l);
}
static __device__ __forceinline__ uint32_t pack2h(float x, float y) {
    __half2 h = __floats2half2_rn(x, y);
    return *reinterpret_cast<uint32_t*>(&h);
}

static __device__ __forceinline__ void mma16816(float* d, const uint32_t* a,
                                                const uint32_t* b) {
    asm volatile(
        "mma.sync.aligned.m16n8k16.row.col.f32.f16.f16.f32 "
        "{%0,%1,%2,%3}, {%4,%5,%6,%7}, {%8,%9}, {%0,%1,%2,%3};"
        : "+f"(d[0]), "+f"(d[1]), "+f"(d[2]), "+f"(d[3])
        : "r"(a[0]), "r"(a[1]), "r"(a[2]), "r"(a[3]), "r"(b[0]), "r"(b[1]));
}

static __device__ __forceinline__ void ldsm4(uint32_t* r, uint32_t addr) {
    asm volatile(
        "ldmatrix.sync.aligned.m8n8.x4.shared.b16 {%0,%1,%2,%3}, [%4];"
        : "=r"(r[0]), "=r"(r[1]), "=r"(r[2]), "=r"(r[3]) : "r"(addr));
}

static __device__ __forceinline__ uint32_t smem_u32(const void* p) {
    uint32_t a;
    asm("{ .reg .u64 t; cvta.to.shared.u64 t, %1; cvt.u32.u64 %0, t; }"
        : "=r"(a) : "l"(p));
    return a;
}

#define CP16(saddr, gptr) \
    asm volatile("cp.async.ca.shared.global [%0], [%1], 16;" \
                 :: "r"(saddr), "l"(gptr))
#define CP_COMMIT() asm volatile("cp.async.commit_group;" ::: "memory")
#define CP_WAIT0()  asm volatile("cp.async.wait_group 0;" ::: "memory")

// ldmatrix lane offsets, 144-byte rows (attn)
static __device__ __forceinline__ uint32_t a_lane_off(int lane) {
    return (uint32_t)((lane & 15) * 144 + ((lane & 16) ? 16 : 0));
}
static __device__ __forceinline__ uint32_t b_lane_off(int lane) {
    return (uint32_t)(((lane & 7) + ((lane >> 4) & 1) * 8) * 144 +
                      ((lane & 8) ? 16 : 0));
}
// ldmatrix lane offsets, 80-byte rows (gemm)
static __device__ __forceinline__ uint32_t a80_off(int lane) {
    return (uint32_t)((lane & 15) * 80 + ((lane & 16) ? 16 : 0));
}
static __device__ __forceinline__ uint32_t b80_off(int lane) {
    return (uint32_t)(((lane & 7) + ((lane >> 4) & 1) * 8) * 80 +
                      ((lane & 8) ? 16 : 0));
}

// ---------------------------------------------------------------------------
// Merged converter: inputs -> fp16 hi/lo pairs; weights -> single fp16.
// ---------------------------------------------------------------------------
__global__ void conv_all(const float* __restrict__ q, const float* __restrict__ k,
                         const float* __restrict__ v, const float* __restrict__ wq,
                         const float* __restrict__ wk, const float* __restrict__ wv,
                         const float* __restrict__ wo)
{
    const int total = 3*NPI + 4*NPW;
    for (int i = blockIdx.x * blockDim.x + threadIdx.x; i < total;
         i += gridDim.x * blockDim.x) {
        if (i < 3*NPI) {
            const float* src; int off; uint32_t *dh, *dl;
            if (i < NPI)        { src = q; off = i;         dh = g_in_h;         dl = g_in_l; }
            else if (i < 2*NPI) { src = k; off = i - NPI;   dh = g_in_h + NPI;   dl = g_in_l + NPI; }
            else                { src = v; off = i - 2*NPI; dh = g_in_h + 2*NPI; dl = g_in_l + 2*NPI; }
            float2 p = ((const float2*)src)[off];
            uint32_t hw, lw; split2h(p.x, p.y, hw, lw);
            dh[off] = hw; dl[off] = lw;
        } else {
            int j = i - 3*NPI;
            const float* src; int off; uint32_t* d;
            if (j < NPW)        { src = wq; off = j;         d = g_wt; }
            else if (j < 2*NPW) { src = wk; off = j - NPW;   d = g_wt + NPW; }
            else if (j < 3*NPW) { src = wv; off = j - 2*NPW; d = g_wt + 2*NPW; }
            else                { src = wo; off = j - 3*NPW; d = g_wt + 3*NPW; }
            float2 p = ((const float2*)src)[off];
            d[off] = pack2h(p.x, p.y);
        }
    }
}

// ---------------------------------------------------------------------------
// fp16-2x GEMM: Out[M,N] = X[M,K] @ W[N,K]^T + bias. 128 thr, 4 warps (2mx2n),
// warp tile 64x64, k-chunk 32, cp.async double-buffered.
// SMEM per buffer 30720: Ah +0, Al +10240, B +20480 (80 B rows). x2 = 61440.
// out_sel: 0=Out fp32; -1=QKV via blockIdx.z (1:Q hi/lo, 2:K single, 3:V^T).
// ---------------------------------------------------------------------------
#define GEMM_SMEM 61440
extern __shared__ uint32_t smw[];

__global__ __launch_bounds__(128) void gemm_tc(
    const uint32_t* __restrict__ Xh, const uint32_t* __restrict__ Xl,
    const uint32_t* __restrict__ W,
    const float* __restrict__ b0, const float* __restrict__ b1,
    const float* __restrict__ b2, float* __restrict__ Out, int out_sel)
{
    const int tid = threadIdx.x, lane = tid & 31, wid = tid >> 5;
    const int g = lane >> 2, c = lane & 3;
    const int mw = wid >> 1, nw = wid & 1;
    const int m0 = blockIdx.y * 128, n0 = blockIdx.x * 128;

    int sel = out_sel;
    const float* Bv = b0;
    if (out_sel < 0) {
        int z = blockIdx.z;
        sel = 1 + z;
        Xh += (size_t)z * NPI; Xl += (size_t)z * NPI;
        W  += (size_t)z * NPW;
        Bv = (z == 0) ? b0 : (z == 1) ? b1 : b2;
    }

    const uint32_t sbg = smem_u32(smw);
    const uint32_t abase = sbg + (uint32_t)(mw*64)*80 + a80_off(lane);
    const uint32_t bbase = sbg + 20480u + (uint32_t)(nw*64)*80 + b80_off(lane);

    const int seg = tid & 3;
    const int row0 = tid >> 2;

    float acc[4][8][4] = {};

    // prologue
    #pragma unroll
    for (int l = 0; l < 4; l++) {
        int row = row0 + l*32;
        uint32_t sa = sbg + row*80 + seg*16;
        uint32_t ga = (uint32_t)(m0+row)*256 + seg*4;
        uint32_t gb = (uint32_t)(n0+row)*256 + seg*4;
        CP16(sa,         Xh + ga);
        CP16(sa + 10240, Xl + ga);
        CP16(sa + 20480, W  + gb);
    }
    CP_COMMIT();
    CP_WAIT0();
    __syncthreads();

    for (int kc = 0; kc < 16; kc++) {
        const uint32_t bo_ = (uint32_t)(kc & 1) * 30720u;
        const bool more = (kc + 1 < 16);
        if (more) {
            uint32_t sb = sbg + (uint32_t)((kc+1) & 1) * 30720u;
            #pragma unroll
            for (int l = 0; l < 4; l++) {
                int row = row0 + l*32;
                uint32_t sa = sb + row*80 + seg*16;
                uint32_t ga = (uint32_t)(m0+row)*256 + (kc+1)*16 + seg*4;
                uint32_t gb = (uint32_t)(n0+row)*256 + (kc+1)*16 + seg*4;
                CP16(sa,         Xh + ga);
                CP16(sa + 10240, Xl + ga);
                CP16(sa + 20480, W  + gb);
            }
            CP_COMMIT();
        }

        #pragma unroll
        for (int ks = 0; ks < 2; ks++) {
            uint32_t ah[4][4], al[4][4], b4[4][4];
            #pragma unroll
            for (int mf = 0; mf < 4; mf++) {
                ldsm4(ah[mf], abase + bo_ + mf*1280 + ks*32);
                ldsm4(al[mf], abase + bo_ + mf*1280 + ks*32 + 10240);
            }
            #pragma unroll
            for (int np = 0; np < 4; np++)
                ldsm4(b4[np], bbase + bo_ + np*1280 + ks*32);
            #pragma unroll
            for (int mf = 0; mf < 4; mf++)
                #pragma unroll
                for (int np = 0; np < 4; np++) {
                    mma16816(acc[mf][2*np  ], ah[mf], &b4[np][0]);
                    mma16816(acc[mf][2*np  ], al[mf], &b4[np][0]);
                    mma16816(acc[mf][2*np+1], ah[mf], &b4[np][2]);
                    mma16816(acc[mf][2*np+1], al[mf], &b4[np][2]);
                }
        }

        if (more) CP_WAIT0();
        __syncthreads();
    }

    // ---- epilogues ----
    if (sel == 0) {
        #pragma unroll
        for (int mf = 0; mf < 4; mf++) {
            int r0 = mw*64 + mf*16 + g;
            #pragma unroll
            for (int nf = 0; nf < 8; nf++) {
                int col = n0 + nw*64 + nf*8 + 2*c;
                float2 bb = *(const float2*)&Bv[col];
                float2 o0 = {acc[mf][nf][0] + bb.x, acc[mf][nf][1] + bb.y};
                float2 o1 = {acc[mf][nf][2] + bb.x, acc[mf][nf][3] + bb.y};
                *(float2*)&Out[(size_t)(m0+r0  )*NFEAT + col] = o0;
                *(float2*)&Out[(size_t)(m0+r0+8)*NFEAT + col] = o1;
            }
        }
    } else if (sel == 1) {
        const float scl = 0.1803368801111204f;   // log2(e)/8
        #pragma unroll
        for (int mf = 0; mf < 4; mf++)
            #pragma unroll
            for (int half = 0; half < 2; half++) {
                int m  = m0 + mw*64 + mf*16 + g + half*8;
                int bb_ = m >> 11, tt = m & (T_SEQ - 1);
                #pragma unroll
                for (int nf = 0; nf < 8; nf++) {
                    int col = nw*64 + nf*8 + 2*c;
                    int hh = (n0 + col) >> 6, d = (n0 + col) & 63;
                    float2 bb = *(const float2*)&Bv[n0 + col];
                    float v0 = (acc[mf][nf][half*2+0] + bb.x) * scl;
                    float v1 = (acc[mf][nf][half*2+1] + bb.y) * scl;
                    uint32_t hw, lw; split2h(v0, v1, hw, lw);
                    size_t widx = (((size_t)(bb_*HEADS+hh)*T_SEQ + tt)*DK + d) >> 1;
                    ((uint32_t*)g_q_h)[widx] = hw;
                    ((uint32_t*)g_q_l)[widx] = lw;
                }
            }
    } else if (sel == 2) {
        #pragma unroll
        for (int mf = 0; mf < 4; mf++)
            #pragma unroll
            for (int half = 0; half < 2; half++) {
                int m  = m0 + mw*64 + mf*16 + g + half*8;
                int bb_ = m >> 11, tt = m & (T_SEQ - 1);
                #pragma unroll
                for (int nf = 0; nf < 8; nf++) {
                    int col = nw*64 + nf*8 + 2*c;
                    int hh = (n0 + col) >> 6, d = (n0 + col) & 63;
                    float2 bb = *(const float2*)&Bv[n0 + col];
                    size_t widx = (((size_t)(bb_*HEADS+hh)*T_SEQ + tt)*DK + d) >> 1;
                    ((uint32_t*)g_k)[widx] =
                        pack2h(acc[mf][nf][half*2+0] + bb.x,
                               acc[mf][nf][half*2+1] + bb.y);
                }
            }
    } else {
        // V: single fp16, transpose to [bh][d][t] through smem
        __half* Ts = (__half*)smw;                      // [128n][136]
        #pragma unroll
        for (int mf = 0; mf < 4; mf++)
            #pragma unroll
            for (int half = 0; half < 2; half++) {
                int t_loc = mw*64 + mf*16 + g + half*8;
                #pragma unroll
                for (int nf = 0; nf < 8; nf++) {
                    int col = nw*64 + nf*8 + 2*c;
                    float2 bb = *(const float2*)&Bv[n0 + col];
                    Ts[(size_t)(col  )*136 + t_loc] =
                        __float2half_rn(acc[mf][nf][half*2+0] + bb.x);
                    Ts[(size_t)(col+1)*136 + t_loc] =
                        __float2half_rn(acc[mf][nf][half*2+1] + bb.y);
                }
            }
        __syncthreads();
        int bb_ = m0 >> 11, tt0 = m0 & (T_SEQ - 1);
        #pragma unroll
        for (int l = 0; l < 16; l++) {
            int idx = tid + l * 128, n = idx >> 4, j = idx & 15;
            int hh = (n0 >> 6) + (n >> 6), d = n & 63;
            size_t go = ((size_t)(bb_*HEADS + hh)*DK + d)*T_SEQ + tt0 + j*8;
            *(uint4*)&g_vt[go] = *(uint4*)((char*)Ts + (size_t)n*272 + j*16);
        }
    }
}

// ---------------------------------------------------------------------------
// fp16-2x attention: 128 threads, 4 warps x 32 q-rows, Q/P split, K/V single.
// cp.async double-buffered, exp2f, fp16 hi/lo output.
// SMEM: QH 0 (18432), QL 18432, buffers at 36864 (K 9216 + V 9216, x2),
// mask at 73728 (512 B). Total 74240.
// ---------------------------------------------------------------------------
#define AQH 0
#define AQL 18432
#define ABUF 36864
#define AMB 73728
#define ATTN_SMEM 74240

static __device__ __forceinline__ void attn_issue_tile(
    uint32_t kbase, int bh, int kt, int tid)
{
    #pragma unroll
    for (int l = 0; l < 4; l++) {
        int idx = tid + l * 128, row = idx >> 3, j = idx & 7;
        uint32_t soff = row * 144 + j * 16;
        size_t kg = ((size_t)bh * T_SEQ + kt + row) * DK + j * 8;
        size_t vg = ((size_t)bh * DK + row) * T_SEQ + kt + j * 8;
        CP16(kbase +        soff, (const char*)&g_k[kg]);
        CP16(kbase + 9216 + soff, (const char*)&g_vt[vg]);
    }
    CP_COMMIT();
}

__global__ __launch_bounds__(128) void attn_tc(const int* __restrict__ mask)
{
    extern __shared__ char sm[];
    const uint32_t sb = smem_u32(sm);
    float* mbufF = (float*)(sm + AMB);

    const int tid = threadIdx.x, lane = tid & 31, wid = tid >> 5;
    const int c = lane & 3;
    const int bh = blockIdx.y, b = bh >> 3, h = bh & 7;
    const int q0 = blockIdx.x * 128;
    const int rb = wid * 32;

    const uint32_t q_amem = sb + AQH + (uint32_t)rb*144 + a_lane_off(lane);
    const uint32_t b_off  = b_lane_off(lane);

    #pragma unroll
    for (int l = 0; l < 8; l++) {
        int idx = tid + l * 128, row = idx >> 3, j = idx & 7;
        size_t gsrc = ((size_t)bh*T_SEQ + q0 + row)*DK + j*8;
        *(uint4*)(sm + AQH + row*144 + j*16) = *(const uint4*)&g_q_h[gsrc];
        *(uint4*)(sm + AQL + row*144 + j*16) = *(const uint4*)&g_q_l[gsrc];
    }
    attn_issue_tile(sb + ABUF, bh, 0, tid);
    if (tid < 64) mbufF[tid] = (float)mask[b*T_SEQ + tid];
    CP_WAIT0();
    __syncthreads();

    float oacc[2][8][4] = {};
    float lacc[2][2] = {};

    for (int it = 0; it < T_SEQ / 64; it++) {
        const int cur = it & 1;
        const uint32_t kb = sb + ABUF + cur * 18432 + b_off;
        const uint32_t vb = kb + 9216;

        int mreg = 0;
        const bool more = (it + 1 < T_SEQ / 64);
        if (more) {
            attn_issue_tile(sb + ABUF + (cur ^ 1) * 18432, bh, (it+1)*64, tid);
            if (tid < 64) mreg = mask[b*T_SEQ + (it+1)*64 + tid];
        }

        // ---- S = Q K^T : Q split, K single ----
        float sacc[2][8][4] = {};
        #pragma unroll
        for (int ks = 0; ks < 4; ks++) {
            uint32_t ah[2][4], al[2][4];
            #pragma unroll
            for (int mf = 0; mf < 2; mf++) {
                ldsm4(ah[mf], q_amem + mf*2304 + ks*32);
                ldsm4(al[mf], q_amem + mf*2304 + ks*32 + 18432);
            }
            #pragma unroll
            for (int np = 0; np < 4; np++) {
                uint32_t k4[4];
                ldsm4(k4, kb + np*2304 + ks*32);
                #pragma unroll
                for (int mf = 0; mf < 2; mf++) {
                    mma16816(sacc[mf][2*np  ], ah[mf], &k4[0]);
                    mma16816(sacc[mf][2*np  ], al[mf], &k4[0]);
                    mma16816(sacc[mf][2*np+1], ah[mf], &k4[2]);
                    mma16816(sacc[mf][2*np+1], al[mf], &k4[2]);
                }
            }
        }

        // ---- exp2 + mask + row-sum; P split in registers ----
        uint32_t ph[2][8][2], pl[2][8][2];
        #pragma unroll
        for (int mf = 0; mf < 2; mf++)
            #pragma unroll
            for (int nf = 0; nf < 8; nf++) {
                int cb = nf*8 + 2*c;
                float m0v = mbufF[cur*64 + cb], m1v = mbufF[cur*64 + cb + 1];
                float e0 = exp2f(sacc[mf][nf][0]) * m0v;
                float e1 = exp2f(sacc[mf][nf][1]) * m1v;
                float e2 = exp2f(sacc[mf][nf][2]) * m0v;
                float e3 = exp2f(sacc[mf][nf][3]) * m1v;
                lacc[mf][0] += e0 + e1;
                lacc[mf][1] += e2 + e3;
                split2h(e0, e1, ph[mf][nf][0], pl[mf][nf][0]);
                split2h(e2, e3, ph[mf][nf][1], pl[mf][nf][1]);
            }

        // ---- O += P V : P split, V single ----
        #pragma unroll
        for (int kg = 0; kg < 4; kg++) {
            uint32_t pah[2][4], pal[2][4];
            #pragma unroll
            for (int mf = 0; mf < 2; mf++) {
                pah[mf][0] = ph[mf][2*kg][0]; pah[mf][1] = ph[mf][2*kg][1];
                pah[mf][2] = ph[mf][2*kg+1][0]; pah[mf][3] = ph[mf][2*kg+1][1];
                pal[mf][0] = pl[mf][2*kg][0]; pal[mf][1] = pl[mf][2*kg][1];
                pal[mf][2] = pl[mf][2*kg+1][0]; pal[mf][3] = pl[mf][2*kg+1][1];
            }
            #pragma unroll
            for (int np = 0; np < 4; np++) {
                uint32_t v4[4];
                ldsm4(v4, vb + np*2304 + kg*32);
                #pragma unroll
                for (int mf = 0; mf < 2; mf++) {
                    mma16816(oacc[mf][2*np  ], pah[mf], &v4[0]);
                    mma16816(oacc[mf][2*np  ], pal[mf], &v4[0]);
                    mma16816(oacc[mf][2*np+1], pah[mf], &v4[2]);
                    mma16816(oacc[mf][2*np+1], pal[mf], &v4[2]);
                }
            }
        }

        if (more) {
            if (tid < 64) mbufF[(cur ^ 1)*64 + tid] = (float)mreg;
            CP_WAIT0();
        }
        __syncthreads();
    }

    // ---- reduce l, normalize, store fp16 hi/lo ----
    float inv[2][2];
    #pragma unroll
    for (int mf = 0; mf < 2; mf++)
        #pragma unroll
        for (int hf = 0; hf < 2; hf++) {
            float lv = lacc[mf][hf];
            lv += __shfl_xor_sync(0xffffffffu, lv, 1);
            lv += __shfl_xor_sync(0xffffffffu, lv, 2);
            inv[mf][hf] = (lv > 0.f) ? 1.f / (lv * (1.f + 1e-8f)) : 0.f;
        }

    const int g = lane >> 2;
    #pragma unroll
    for (int mf = 0; mf < 2; mf++) {
        const int row0 = q0 + rb + mf*16 + g, row1 = row0 + 8;
        #pragma unroll
        for (int nd = 0; nd < 8; nd++) {
            int colw = h*32 + nd*4 + c;
            uint32_t hw, lw;
            split2h(oacc[mf][nd][0] * inv[mf][0], oacc[mf][nd][1] * inv[mf][0], hw, lw);
            g_x_h[(size_t)(b*T_SEQ + row0)*256 + colw] = hw;
            g_x_l[(size_t)(b*T_SEQ + row0)*256 + colw] = lw;
            split2h(oacc[mf][nd][2] * inv[mf][1], oacc[mf][nd][3] * inv[mf][1], hw, lw);
            g_x_h[(size_t)(b*T_SEQ + row1)*256 + colw] = hw;
            g_x_l[(size_t)(b*T_SEQ + row1)*256 + colw] = lw;
        }
    }
}

// ---------------------------------------------------------------------------
extern "C" void kernel_launch(void* const* d_in, const int* in_sizes, int n_in,
                              void* d_out, int out_size)
{
    const float* query = (const float*)d_in[0];
    const float* key_  = (const float*)d_in[1];
    const float* value = (const float*)d_in[2];
    const int*   mask  = (const int*)d_in[3];
    const float* Wq = (const float*)d_in[4];
    const float* bq = (const float*)d_in[5];
    const float* Wk = (const float*)d_in[6];
    const float* bk = (const float*)d_in[7];
    const float* Wv = (const float*)d_in[8];
    const float* bv = (const float*)d_in[9];
    const float* Wo = (const float*)d_in[10];
    const float* bo = (const float*)d_in[11];
    float* out = (float*)d_out;

    uint32_t *inh, *inl, *wt, *xh, *xl;
    cudaGetSymbolAddress((void**)&inh, g_in_h);
    cudaGetSymbolAddress((void**)&inl, g_in_l);
    cudaGetSymbolAddress((void**)&wt,  g_wt);
    cudaGetSymbolAddress((void**)&xh,  g_x_h);
    cudaGetSymbolAddress((void**)&xl,  g_x_l);

    conv_all<<<2048, 256>>>(query, key_, value, Wq, Wk, Wv, Wo);

    cudaFuncSetAttribute(gemm_tc, cudaFuncAttributeMaxDynamicSharedMemorySize,
                         GEMM_SMEM);
    cudaFuncSetAttribute(attn_tc, cudaFuncAttributeMaxDynamicSharedMemorySize,
                         ATTN_SMEM);

    gemm_tc<<<dim3(4, 64, 3), 128, GEMM_SMEM>>>(
        inh, inl, wt, bq, bk, bv, nullptr, -1);

    attn_tc<<<dim3(T_SEQ / 128, BHTOT), 128, ATTN_SMEM>>>(mask);

    gemm_tc<<<dim3(4, 64, 1), 128, GEMM_SMEM>>>(
        xh, xl, wt + 3*NPW, bo, nullptr, nullptr, out, 0);
}

// round 12
// speedup vs baseline: 2.1023x; 1.0630x over previous
#include <cuda_runtime.h>
#include <cuda_fp16.h>
#include <cstdint>

#define T_SEQ 2048
#define NFEAT 512
#define HEADS 8
#define DK 64
#define BHTOT 32
#define MTOT 8192

// A-side operands split into fp16 hi/lo; B-side single fp16.
// Q pre-scaled by log2(e)/8 (exp2 in attn). V stored transposed [bh][d][t].
__device__ __half g_q_h[(size_t)BHTOT*T_SEQ*DK];
__device__ __half g_q_l[(size_t)BHTOT*T_SEQ*DK];
__device__ __half g_k[(size_t)BHTOT*T_SEQ*DK];
__device__ __half g_vt[(size_t)BHTOT*DK*T_SEQ];
__device__ uint32_t g_in_h[(size_t)3*MTOT*256];
__device__ uint32_t g_in_l[(size_t)3*MTOT*256];
__device__ uint32_t g_wt[(size_t)4*512*256];
__device__ uint32_t g_x_h[(size_t)MTOT*256];
__device__ uint32_t g_x_l[(size_t)MTOT*256];

#define NPI (MTOT*256)
#define NPW (512*256)

static __device__ __forceinline__ void split2h(float x, float y,
                                               uint32_t& hw, uint32_t& lw) {
    __half2 h = __floats2half2_rn(x, y);
    float hx = __low2float(h), hy = __high2float(h);
    __half2 l = __floats2half2_rn(x - hx, y - hy);
    hw = *reinterpret_cast<uint32_t*>(&h);
    lw = *reinterpret_cast<uint32_t*>(&l);
}
static __device__ __forceinline__ uint32_t pack2h(float x, float y) {
    __half2 h = __floats2half2_rn(x, y);
    return *reinterpret_cast<uint32_t*>(&h);
}

static __device__ __forceinline__ void mma16816(float* d, const uint32_t* a,
                                                const uint32_t* b) {
    asm volatile(
        "mma.sync.aligned.m16n8k16.row.col.f32.f16.f16.f32 "
        "{%0,%1,%2,%3}, {%4,%5,%6,%7}, {%8,%9}, {%0,%1,%2,%3};"
        : "+f"(d[0]), "+f"(d[1]), "+f"(d[2]), "+f"(d[3])
        : "r"(a[0]), "r"(a[1]), "r"(a[2]), "r"(a[3]), "r"(b[0]), "r"(b[1]));
}

static __device__ __forceinline__ void ldsm4(uint32_t* r, uint32_t addr) {
    asm volatile(
        "ldmatrix.sync.aligned.m8n8.x4.shared.b16 {%0,%1,%2,%3}, [%4];"
        : "=r"(r[0]), "=r"(r[1]), "=r"(r[2]), "=r"(r[3]) : "r"(addr));
}

static __device__ __forceinline__ uint32_t smem_u32(const void* p) {
    uint32_t a;
    asm("{ .reg .u64 t; cvta.to.shared.u64 t, %1; cvt.u32.u64 %0, t; }"
        : "=r"(a) : "l"(p));
    return a;
}

#define CP16(saddr, gptr) \
    asm volatile("cp.async.ca.shared.global [%0], [%1], 16;" \
                 :: "r"(saddr), "l"(gptr))
#define CP_COMMIT() asm volatile("cp.async.commit_group;" ::: "memory")
#define CP_WAIT0()  asm volatile("cp.async.wait_group 0;" ::: "memory")
#define CP_WAIT1()  asm volatile("cp.async.wait_group 1;" ::: "memory")

// ldmatrix lane offsets, 144-byte rows (attn)
static __device__ __forceinline__ uint32_t a_lane_off(int lane) {
    return (uint32_t)((lane & 15) * 144 + ((lane & 16) ? 16 : 0));
}
static __device__ __forceinline__ uint32_t b_lane_off(int lane) {
    return (uint32_t)(((lane & 7) + ((lane >> 4) & 1) * 8) * 144 +
                      ((lane & 8) ? 16 : 0));
}
// ldmatrix lane offsets, 80-byte rows (gemm)
static __device__ __forceinline__ uint32_t a80_off(int lane) {
    return (uint32_t)((lane & 15) * 80 + ((lane & 16) ? 16 : 0));
}
static __device__ __forceinline__ uint32_t b80_off(int lane) {
    return (uint32_t)(((lane & 7) + ((lane >> 4) & 1) * 8) * 80 +
                      ((lane & 8) ? 16 : 0));
}

// ---------------------------------------------------------------------------
// Merged converter: inputs -> fp16 hi/lo pairs; weights -> single fp16.
// ---------------------------------------------------------------------------
__global__ void conv_all(const float* __restrict__ q, const float* __restrict__ k,
                         const float* __restrict__ v, const float* __restrict__ wq,
                         const float* __restrict__ wk, const float* __restrict__ wv,
                         const float* __restrict__ wo)
{
    const int total = 3*NPI + 4*NPW;
    for (int i = blockIdx.x * blockDim.x + threadIdx.x; i < total;
         i += gridDim.x * blockDim.x) {
        if (i < 3*NPI) {
            const float* src; int off; uint32_t *dh, *dl;
            if (i < NPI)        { src = q; off = i;         dh = g_in_h;         dl = g_in_l; }
            else if (i < 2*NPI) { src = k; off = i - NPI;   dh = g_in_h + NPI;   dl = g_in_l + NPI; }
            else                { src = v; off = i - 2*NPI; dh = g_in_h + 2*NPI; dl = g_in_l + 2*NPI; }
            float2 p = ((const float2*)src)[off];
            uint32_t hw, lw; split2h(p.x, p.y, hw, lw);
            dh[off] = hw; dl[off] = lw;
        } else {
            int j = i - 3*NPI;
            const float* src; int off; uint32_t* d;
            if (j < NPW)        { src = wq; off = j;         d = g_wt; }
            else if (j < 2*NPW) { src = wk; off = j - NPW;   d = g_wt + NPW; }
            else if (j < 3*NPW) { src = wv; off = j - 2*NPW; d = g_wt + 2*NPW; }
            else                { src = wo; off = j - 3*NPW; d = g_wt + 3*NPW; }
            float2 p = ((const float2*)src)[off];
            d[off] = pack2h(p.x, p.y);
        }
    }
}

// ---------------------------------------------------------------------------
// fp16-2x GEMM, triple-buffered cp.async (wait_group 1). 128 thr, 4 warps
// (2mx2n), warp 64x64, k-chunk 32. Buffer 30720 B (Ah+0, Al+10240, B+20480,
// 80 B rows), x3 = 92160.
// ---------------------------------------------------------------------------
#define GEMM_SMEM 92160
extern __shared__ uint32_t smw[];

static __device__ __forceinline__ void gemm_issue_chunk(
    uint32_t sb, const uint32_t* Xh, const uint32_t* Xl, const uint32_t* W,
    int m0, int n0, int kc, int row0, int seg)
{
    #pragma unroll
    for (int l = 0; l < 4; l++) {
        int row = row0 + l*32;
        uint32_t sa = sb + row*80 + seg*16;
        uint32_t ga = (uint32_t)(m0+row)*256 + kc*16 + seg*4;
        uint32_t gb = (uint32_t)(n0+row)*256 + kc*16 + seg*4;
        CP16(sa,         Xh + ga);
        CP16(sa + 10240, Xl + ga);
        CP16(sa + 20480, W  + gb);
    }
    CP_COMMIT();
}

__global__ __launch_bounds__(128) void gemm_tc(
    const uint32_t* __restrict__ Xh, const uint32_t* __restrict__ Xl,
    const uint32_t* __restrict__ W,
    const float* __restrict__ b0, const float* __restrict__ b1,
    const float* __restrict__ b2, float* __restrict__ Out, int out_sel)
{
    const int tid = threadIdx.x, lane = tid & 31, wid = tid >> 5;
    const int g = lane >> 2, c = lane & 3;
    const int mw = wid >> 1, nw = wid & 1;
    const int m0 = blockIdx.y * 128, n0 = blockIdx.x * 128;

    int sel = out_sel;
    const float* Bv = b0;
    if (out_sel < 0) {
        int z = blockIdx.z;
        sel = 1 + z;
        Xh += (size_t)z * NPI; Xl += (size_t)z * NPI;
        W  += (size_t)z * NPW;
        Bv = (z == 0) ? b0 : (z == 1) ? b1 : b2;
    }

    const uint32_t sbg = smem_u32(smw);
    const uint32_t abase = sbg + (uint32_t)(mw*64)*80 + a80_off(lane);
    const uint32_t bbase = sbg + 20480u + (uint32_t)(nw*64)*80 + b80_off(lane);

    const int seg = tid & 3;
    const int row0 = tid >> 2;

    float acc[4][8][4] = {};

    // prologue: chunks 0 and 1
    gemm_issue_chunk(sbg,          Xh, Xl, W, m0, n0, 0, row0, seg);
    gemm_issue_chunk(sbg + 30720u, Xh, Xl, W, m0, n0, 1, row0, seg);

    for (int kc = 0; kc < 16; kc++) {
        const uint32_t bo_ = (uint32_t)(kc % 3) * 30720u;
        if (kc + 1 < 16) CP_WAIT1(); else CP_WAIT0();
        __syncthreads();
        if (kc + 2 < 16)
            gemm_issue_chunk(sbg + (uint32_t)((kc+2) % 3) * 30720u,
                             Xh, Xl, W, m0, n0, kc+2, row0, seg);

        #pragma unroll
        for (int ks = 0; ks < 2; ks++) {
            uint32_t ah[4][4], al[4][4], b4[4][4];
            #pragma unroll
            for (int mf = 0; mf < 4; mf++) {
                ldsm4(ah[mf], abase + bo_ + mf*1280 + ks*32);
                ldsm4(al[mf], abase + bo_ + mf*1280 + ks*32 + 10240);
            }
            #pragma unroll
            for (int np = 0; np < 4; np++)
                ldsm4(b4[np], bbase + bo_ + np*1280 + ks*32);
            #pragma unroll
            for (int mf = 0; mf < 4; mf++)
                #pragma unroll
                for (int np = 0; np < 4; np++) {
                    mma16816(acc[mf][2*np  ], ah[mf], &b4[np][0]);
                    mma16816(acc[mf][2*np  ], al[mf], &b4[np][0]);
                    mma16816(acc[mf][2*np+1], ah[mf], &b4[np][2]);
                    mma16816(acc[mf][2*np+1], al[mf], &b4[np][2]);
                }
        }
    }

    // ---- epilogues ----
    if (sel == 0) {
        #pragma unroll
        for (int mf = 0; mf < 4; mf++) {
            int r0 = mw*64 + mf*16 + g;
            #pragma unroll
            for (int nf = 0; nf < 8; nf++) {
                int col = n0 + nw*64 + nf*8 + 2*c;
                float2 bb = *(const float2*)&Bv[col];
                float2 o0 = {acc[mf][nf][0] + bb.x, acc[mf][nf][1] + bb.y};
                float2 o1 = {acc[mf][nf][2] + bb.x, acc[mf][nf][3] + bb.y};
                *(float2*)&Out[(size_t)(m0+r0  )*NFEAT + col] = o0;
                *(float2*)&Out[(size_t)(m0+r0+8)*NFEAT + col] = o1;
            }
        }
    } else if (sel == 1) {
        const float scl = 0.1803368801111204f;   // log2(e)/8
        #pragma unroll
        for (int mf = 0; mf < 4; mf++)
            #pragma unroll
            for (int half = 0; half < 2; half++) {
                int m  = m0 + mw*64 + mf*16 + g + half*8;
                int bb_ = m >> 11, tt = m & (T_SEQ - 1);
                #pragma unroll
                for (int nf = 0; nf < 8; nf++) {
                    int col = nw*64 + nf*8 + 2*c;
                    int hh = (n0 + col) >> 6, d = (n0 + col) & 63;
                    float2 bb = *(const float2*)&Bv[n0 + col];
                    float v0 = (acc[mf][nf][half*2+0] + bb.x) * scl;
                    float v1 = (acc[mf][nf][half*2+1] + bb.y) * scl;
                    uint32_t hw, lw; split2h(v0, v1, hw, lw);
                    size_t widx = (((size_t)(bb_*HEADS+hh)*T_SEQ + tt)*DK + d) >> 1;
                    ((uint32_t*)g_q_h)[widx] = hw;
                    ((uint32_t*)g_q_l)[widx] = lw;
                }
            }
    } else if (sel == 2) {
        #pragma unroll
        for (int mf = 0; mf < 4; mf++)
            #pragma unroll
            for (int half = 0; half < 2; half++) {
                int m  = m0 + mw*64 + mf*16 + g + half*8;
                int bb_ = m >> 11, tt = m & (T_SEQ - 1);
                #pragma unroll
                for (int nf = 0; nf < 8; nf++) {
                    int col = nw*64 + nf*8 + 2*c;
                    int hh = (n0 + col) >> 6, d = (n0 + col) & 63;
                    float2 bb = *(const float2*)&Bv[n0 + col];
                    size_t widx = (((size_t)(bb_*HEADS+hh)*T_SEQ + tt)*DK + d) >> 1;
                    ((uint32_t*)g_k)[widx] =
                        pack2h(acc[mf][nf][half*2+0] + bb.x,
                               acc[mf][nf][half*2+1] + bb.y);
                }
            }
    } else {
        // V: single fp16, transpose to [bh][d][t] through smem
        __syncthreads();
        __half* Ts = (__half*)smw;                      // [128n][136]
        #pragma unroll
        for (int mf = 0; mf < 4; mf++)
            #pragma unroll
            for (int half = 0; half < 2; half++) {
                int t_loc = mw*64 + mf*16 + g + half*8;
                #pragma unroll
                for (int nf = 0; nf < 8; nf++) {
                    int col = nw*64 + nf*8 + 2*c;
                    float2 bb = *(const float2*)&Bv[n0 + col];
                    Ts[(size_t)(col  )*136 + t_loc] =
                        __float2half_rn(acc[mf][nf][half*2+0] + bb.x);
                    Ts[(size_t)(col+1)*136 + t_loc] =
                        __float2half_rn(acc[mf][nf][half*2+1] + bb.y);
                }
            }
        __syncthreads();
        int bb_ = m0 >> 11, tt0 = m0 & (T_SEQ - 1);
        #pragma unroll
        for (int l = 0; l < 16; l++) {
            int idx = tid + l * 128, n = idx >> 4, j = idx & 15;
            int hh = (n0 >> 6) + (n >> 6), d = n & 63;
            size_t go = ((size_t)(bb_*HEADS + hh)*DK + d)*T_SEQ + tt0 + j*8;
            *(uint4*)&g_vt[go] = *(uint4*)((char*)Ts + (size_t)n*272 + j*16);
        }
    }
}

// ---------------------------------------------------------------------------
// fp16 attention: Q split (2-term S), P single (1-term PV), K/V single.
// Triple-buffered cp.async. 128 threads, 4 warps x 32 q-rows.
// SMEM: QH 0, QL 18432, 3 K/V buffers at 36864 (18432 each), mask 92160.
// ---------------------------------------------------------------------------
#define AQH 0
#define AQL 18432
#define ABUF 36864
#define AMB 92160
#define ATTN_SMEM 92928

static __device__ __forceinline__ void attn_issue_tile(
    uint32_t kbase, int bh, int kt, int tid)
{
    #pragma unroll
    for (int l = 0; l < 4; l++) {
        int idx = tid + l * 128, row = idx >> 3, j = idx & 7;
        uint32_t soff = row * 144 + j * 16;
        size_t kg = ((size_t)bh * T_SEQ + kt + row) * DK + j * 8;
        size_t vg = ((size_t)bh * DK + row) * T_SEQ + kt + j * 8;
        CP16(kbase +        soff, (const char*)&g_k[kg]);
        CP16(kbase + 9216 + soff, (const char*)&g_vt[vg]);
    }
    CP_COMMIT();
}

__global__ __launch_bounds__(128) void attn_tc(const int* __restrict__ mask)
{
    extern __shared__ char sm[];
    const uint32_t sb = smem_u32(sm);
    float* mbufF = (float*)(sm + AMB);

    const int tid = threadIdx.x, lane = tid & 31, wid = tid >> 5;
    const int c = lane & 3;
    const int bh = blockIdx.y, b = bh >> 3, h = bh & 7;
    const int q0 = blockIdx.x * 128;
    const int rb = wid * 32;

    const uint32_t q_amem = sb + AQH + (uint32_t)rb*144 + a_lane_off(lane);
    const uint32_t b_off  = b_lane_off(lane);

    #pragma unroll
    for (int l = 0; l < 8; l++) {
        int idx = tid + l * 128, row = idx >> 3, j = idx & 7;
        size_t gsrc = ((size_t)bh*T_SEQ + q0 + row)*DK + j*8;
        *(uint4*)(sm + AQH + row*144 + j*16) = *(const uint4*)&g_q_h[gsrc];
        *(uint4*)(sm + AQL + row*144 + j*16) = *(const uint4*)&g_q_l[gsrc];
    }
    // prologue: tiles 0 and 1 + masks 0 and 1
    attn_issue_tile(sb + ABUF,          bh, 0,  tid);
    attn_issue_tile(sb + ABUF + 18432u, bh, 64, tid);
    if (tid < 64) {
        mbufF[tid]      = (float)mask[b*T_SEQ + tid];
        mbufF[64 + tid] = (float)mask[b*T_SEQ + 64 + tid];
    }

    float oacc[2][8][4] = {};
    float lacc[2][2] = {};

    for (int it = 0; it < 32; it++) {
        const int cur3 = it % 3;
        const uint32_t kb = sb + ABUF + (uint32_t)cur3 * 18432u + b_off;
        const uint32_t vb = kb + 9216;

        if (it + 1 < 32) CP_WAIT1(); else CP_WAIT0();
        __syncthreads();
        if (it + 2 < 32) {
            attn_issue_tile(sb + ABUF + (uint32_t)((it+2) % 3) * 18432u,
                            bh, (it+2)*64, tid);
            if (tid < 64)
                mbufF[((it+2) % 3)*64 + tid] =
                    (float)mask[b*T_SEQ + (it+2)*64 + tid];
        }

        // ---- S = Q K^T : Q split, K single ----
        float sacc[2][8][4] = {};
        #pragma unroll
        for (int ks = 0; ks < 4; ks++) {
            uint32_t ah[2][4], al[2][4];
            #pragma unroll
            for (int mf = 0; mf < 2; mf++) {
                ldsm4(ah[mf], q_amem + mf*2304 + ks*32);
                ldsm4(al[mf], q_amem + mf*2304 + ks*32 + 18432);
            }
            #pragma unroll
            for (int np = 0; np < 4; np++) {
                uint32_t k4[4];
                ldsm4(k4, kb + np*2304 + ks*32);
                #pragma unroll
                for (int mf = 0; mf < 2; mf++) {
                    mma16816(sacc[mf][2*np  ], ah[mf], &k4[0]);
                    mma16816(sacc[mf][2*np  ], al[mf], &k4[0]);
                    mma16816(sacc[mf][2*np+1], ah[mf], &k4[2]);
                    mma16816(sacc[mf][2*np+1], al[mf], &k4[2]);
                }
            }
        }

        // ---- exp2 + mask + row-sum; P single fp16 in registers ----
        uint32_t ph[2][8][2];
        #pragma unroll
        for (int mf = 0; mf < 2; mf++)
            #pragma unroll
            for (int nf = 0; nf < 8; nf++) {
                int cb = nf*8 + 2*c;
                float m0v = mbufF[cur3*64 + cb], m1v = mbufF[cur3*64 + cb + 1];
                float e0 = exp2f(sacc[mf][nf][0]) * m0v;
                float e1 = exp2f(sacc[mf][nf][1]) * m1v;
                float e2 = exp2f(sacc[mf][nf][2]) * m0v;
                float e3 = exp2f(sacc[mf][nf][3]) * m1v;
                lacc[mf][0] += e0 + e1;
                lacc[mf][1] += e2 + e3;
                ph[mf][nf][0] = pack2h(e0, e1);
                ph[mf][nf][1] = pack2h(e2, e3);
            }

        // ---- O += P V : P single, V single ----
        #pragma unroll
        for (int kg = 0; kg < 4; kg++) {
            uint32_t pah[2][4];
            #pragma unroll
            for (int mf = 0; mf < 2; mf++) {
                pah[mf][0] = ph[mf][2*kg][0];   pah[mf][1] = ph[mf][2*kg][1];
                pah[mf][2] = ph[mf][2*kg+1][0]; pah[mf][3] = ph[mf][2*kg+1][1];
            }
            #pragma unroll
            for (int np = 0; np < 4; np++) {
                uint32_t v4[4];
                ldsm4(v4, vb + np*2304 + kg*32);
                #pragma unroll
                for (int mf = 0; mf < 2; mf++) {
                    mma16816(oacc[mf][2*np  ], pah[mf], &v4[0]);
                    mma16816(oacc[mf][2*np+1], pah[mf], &v4[2]);
                }
            }
        }
    }

    // ---- reduce l, normalize, store fp16 hi/lo ----
    float inv[2][2];
    #pragma unroll
    for (int mf = 0; mf < 2; mf++)
        #pragma unroll
        for (int hf = 0; hf < 2; hf++) {
            float lv = lacc[mf][hf];
            lv += __shfl_xor_sync(0xffffffffu, lv, 1);
            lv += __shfl_xor_sync(0xffffffffu, lv, 2);
            inv[mf][hf] = (lv > 0.f) ? 1.f / (lv * (1.f + 1e-8f)) : 0.f;
        }

    const int g = lane >> 2;
    #pragma unroll
    for (int mf = 0; mf < 2; mf++) {
        const int row0 = q0 + rb + mf*16 + g, row1 = row0 + 8;
        #pragma unroll
        for (int nd = 0; nd < 8; nd++) {
            int colw = h*32 + nd*4 + c;
            uint32_t hw, lw;
            split2h(oacc[mf][nd][0] * inv[mf][0], oacc[mf][nd][1] * inv[mf][0], hw, lw);
            g_x_h[(size_t)(b*T_SEQ + row0)*256 + colw] = hw;
            g_x_l[(size_t)(b*T_SEQ + row0)*256 + colw] = lw;
            split2h(oacc[mf][nd][2] * inv[mf][1], oacc[mf][nd][3] * inv[mf][1], hw, lw);
            g_x_h[(size_t)(b*T_SEQ + row1)*256 + colw] = hw;
            g_x_l[(size_t)(b*T_SEQ + row1)*256 + colw] = lw;
        }
    }
}

// ---------------------------------------------------------------------------
extern "C" void kernel_launch(void* const* d_in, const int* in_sizes, int n_in,
                              void* d_out, int out_size)
{
    const float* query = (const float*)d_in[0];
    const float* key_  = (const float*)d_in[1];
    const float* value = (const float*)d_in[2];
    const int*   mask  = (const int*)d_in[3];
    const float* Wq = (const float*)d_in[4];
    const float* bq = (const float*)d_in[5];
    const float* Wk = (const float*)d_in[6];
    const float* bk = (const float*)d_in[7];
    const float* Wv = (const float*)d_in[8];
    const float* bv = (const float*)d_in[9];
    const float* Wo = (const float*)d_in[10];
    const float* bo = (const float*)d_in[11];
    float* out = (float*)d_out;

    uint32_t *inh, *inl, *wt, *xh, *xl;
    cudaGetSymbolAddress((void**)&inh, g_in_h);
    cudaGetSymbolAddress((void**)&inl, g_in_l);
    cudaGetSymbolAddress((void**)&wt,  g_wt);
    cudaGetSymbolAddress((void**)&xh,  g_x_h);
    cudaGetSymbolAddress((void**)&xl,  g_x_l);

    conv_all<<<2048, 256>>>(query, key_, value, Wq, Wk, Wv, Wo);

    cudaFuncSetAttribute(gemm_tc, cudaFuncAttributeMaxDynamicSharedMemorySize,
                         GEMM_SMEM);
    cudaFuncSetAttribute(attn_tc, cudaFuncAttributeMaxDynamicSharedMemorySize,
                         ATTN_SMEM);

    gemm_tc<<<dim3(4, 64, 3), 128, GEMM_SMEM>>>(
        inh, inl, wt, bq, bk, bv, nullptr, -1);

    attn_tc<<<dim3(T_SEQ / 128, BHTOT), 128, ATTN_SMEM>>>(mask);

    gemm_tc<<<dim3(4, 64, 1), 128, GEMM_SMEM>>>(
        xh, xl, wt + 3*NPW, bo, nullptr, nullptr, out, 0);
}

// round 13
// speedup vs baseline: 2.1295x; 1.0129x over previous
#include <cuda_runtime.h>
#include <cuda_fp16.h>
#include <cstdint>

#define T_SEQ 2048
#define NFEAT 512
#define HEADS 8
#define DK 64
#define BHTOT 32
#define MTOT 8192

// A-side operands split into fp16 hi/lo; B-side single fp16.
// Q pre-scaled by log2(e)/8 (exp2 in attn). V stored transposed [bh][d][t].
__device__ __half g_q_h[(size_t)BHTOT*T_SEQ*DK];
__device__ __half g_q_l[(size_t)BHTOT*T_SEQ*DK];
__device__ __half g_k[(size_t)BHTOT*T_SEQ*DK];
__device__ __half g_vt[(size_t)BHTOT*DK*T_SEQ];
__device__ uint32_t g_in_h[(size_t)3*MTOT*256];
__device__ uint32_t g_in_l[(size_t)3*MTOT*256];
__device__ uint32_t g_wt[(size_t)4*512*256];
__device__ uint32_t g_x_h[(size_t)MTOT*256];
__device__ uint32_t g_x_l[(size_t)MTOT*256];

#define NPI (MTOT*256)
#define NPW (512*256)

static __device__ __forceinline__ void split2h(float x, float y,
                                               uint32_t& hw, uint32_t& lw) {
    __half2 h = __floats2half2_rn(x, y);
    float hx = __low2float(h), hy = __high2float(h);
    __half2 l = __floats2half2_rn(x - hx, y - hy);
    hw = *reinterpret_cast<uint32_t*>(&h);
    lw = *reinterpret_cast<uint32_t*>(&l);
}
static __device__ __forceinline__ uint32_t pack2h(float x, float y) {
    __half2 h = __floats2half2_rn(x, y);
    return *reinterpret_cast<uint32_t*>(&h);
}

static __device__ __forceinline__ void mma16816(float* d, const uint32_t* a,
                                                const uint32_t* b) {
    asm volatile(
        "mma.sync.aligned.m16n8k16.row.col.f32.f16.f16.f32 "
        "{%0,%1,%2,%3}, {%4,%5,%6,%7}, {%8,%9}, {%0,%1,%2,%3};"
        : "+f"(d[0]), "+f"(d[1]), "+f"(d[2]), "+f"(d[3])
        : "r"(a[0]), "r"(a[1]), "r"(a[2]), "r"(a[3]), "r"(b[0]), "r"(b[1]));
}

static __device__ __forceinline__ void ldsm4(uint32_t* r, uint32_t addr) {
    asm volatile(
        "ldmatrix.sync.aligned.m8n8.x4.shared.b16 {%0,%1,%2,%3}, [%4];"
        : "=r"(r[0]), "=r"(r[1]), "=r"(r[2]), "=r"(r[3]) : "r"(addr));
}

static __device__ __forceinline__ uint32_t smem_u32(const void* p) {
    uint32_t a;
    asm("{ .reg .u64 t; cvta.to.shared.u64 t, %1; cvt.u32.u64 %0, t; }"
        : "=r"(a) : "l"(p));
    return a;
}

#define CP16(saddr, gptr) \
    asm volatile("cp.async.ca.shared.global [%0], [%1], 16;" \
                 :: "r"(saddr), "l"(gptr))
#define CP_COMMIT() asm volatile("cp.async.commit_group;" ::: "memory")
#define CP_WAIT0()  asm volatile("cp.async.wait_group 0;" ::: "memory")
#define CP_WAIT1()  asm volatile("cp.async.wait_group 1;" ::: "memory")

// ldmatrix lane offsets, 144-byte rows (attn)
static __device__ __forceinline__ uint32_t a_lane_off(int lane) {
    return (uint32_t)((lane & 15) * 144 + ((lane & 16) ? 16 : 0));
}
static __device__ __forceinline__ uint32_t b_lane_off(int lane) {
    return (uint32_t)(((lane & 7) + ((lane >> 4) & 1) * 8) * 144 +
                      ((lane & 8) ? 16 : 0));
}
// ldmatrix lane offsets, 80-byte rows (gemm)
static __device__ __forceinline__ uint32_t a80_off(int lane) {
    return (uint32_t)((lane & 15) * 80 + ((lane & 16) ? 16 : 0));
}
static __device__ __forceinline__ uint32_t b80_off(int lane) {
    return (uint32_t)(((lane & 7) + ((lane >> 4) & 1) * 8) * 80 +
                      ((lane & 8) ? 16 : 0));
}

// ---------------------------------------------------------------------------
// Merged converter: inputs -> fp16 hi/lo pairs; weights -> single fp16.
// ---------------------------------------------------------------------------
__global__ void conv_all(const float* __restrict__ q, const float* __restrict__ k,
                         const float* __restrict__ v, const float* __restrict__ wq,
                         const float* __restrict__ wk, const float* __restrict__ wv,
                         const float* __restrict__ wo)
{
    const int total = 3*NPI + 4*NPW;
    for (int i = blockIdx.x * blockDim.x + threadIdx.x; i < total;
         i += gridDim.x * blockDim.x) {
        if (i < 3*NPI) {
            const float* src; int off; uint32_t *dh, *dl;
            if (i < NPI)        { src = q; off = i;         dh = g_in_h;         dl = g_in_l; }
            else if (i < 2*NPI) { src = k; off = i - NPI;   dh = g_in_h + NPI;   dl = g_in_l + NPI; }
            else                { src = v; off = i - 2*NPI; dh = g_in_h + 2*NPI; dl = g_in_l + 2*NPI; }
            float2 p = ((const float2*)src)[off];
            uint32_t hw, lw; split2h(p.x, p.y, hw, lw);
            dh[off] = hw; dl[off] = lw;
        } else {
            int j = i - 3*NPI;
            const float* src; int off; uint32_t* d;
            if (j < NPW)        { src = wq; off = j;         d = g_wt; }
            else if (j < 2*NPW) { src = wk; off = j - NPW;   d = g_wt + NPW; }
            else if (j < 3*NPW) { src = wv; off = j - 2*NPW; d = g_wt + 2*NPW; }
            else                { src = wo; off = j - 3*NPW; d = g_wt + 3*NPW; }
            float2 p = ((const float2*)src)[off];
            d[off] = pack2h(p.x, p.y);
        }
    }
}

// ---------------------------------------------------------------------------
// fp16-2x GEMM, double-buffered cp.async (round-11 proven structure).
// 128 thr, 4 warps (2mx2n), warp 64x64, k-chunk 32.
// Buffer 30720 B (Ah+0, Al+10240, B+20480, 80 B rows), x2 = 61440.
// ---------------------------------------------------------------------------
#define GEMM_SMEM 61440
extern __shared__ uint32_t smw[];

__global__ __launch_bounds__(128) void gemm_tc(
    const uint32_t* __restrict__ Xh, const uint32_t* __restrict__ Xl,
    const uint32_t* __restrict__ W,
    const float* __restrict__ b0, const float* __restrict__ b1,
    const float* __restrict__ b2, float* __restrict__ Out, int out_sel)
{
    const int tid = threadIdx.x, lane = tid & 31, wid = tid >> 5;
    const int g = lane >> 2, c = lane & 3;
    const int mw = wid >> 1, nw = wid & 1;
    const int m0 = blockIdx.y * 128, n0 = blockIdx.x * 128;

    int sel = out_sel;
    const float* Bv = b0;
    if (out_sel < 0) {
        int z = blockIdx.z;
        sel = 1 + z;
        Xh += (size_t)z * NPI; Xl += (size_t)z * NPI;
        W  += (size_t)z * NPW;
        Bv = (z == 0) ? b0 : (z == 1) ? b1 : b2;
    }

    const uint32_t sbg = smem_u32(smw);
    const uint32_t abase = sbg + (uint32_t)(mw*64)*80 + a80_off(lane);
    const uint32_t bbase = sbg + 20480u + (uint32_t)(nw*64)*80 + b80_off(lane);

    const int seg = tid & 3;
    const int row0 = tid >> 2;

    float acc[4][8][4] = {};

    // prologue
    #pragma unroll
    for (int l = 0; l < 4; l++) {
        int row = row0 + l*32;
        uint32_t sa = sbg + row*80 + seg*16;
        uint32_t ga = (uint32_t)(m0+row)*256 + seg*4;
        uint32_t gb = (uint32_t)(n0+row)*256 + seg*4;
        CP16(sa,         Xh + ga);
        CP16(sa + 10240, Xl + ga);
        CP16(sa + 20480, W  + gb);
    }
    CP_COMMIT();
    CP_WAIT0();
    __syncthreads();

    for (int kc = 0; kc < 16; kc++) {
        const uint32_t bo_ = (uint32_t)(kc & 1) * 30720u;
        const bool more = (kc + 1 < 16);
        if (more) {
            uint32_t sb = sbg + (uint32_t)((kc+1) & 1) * 30720u;
            #pragma unroll
            for (int l = 0; l < 4; l++) {
                int row = row0 + l*32;
                uint32_t sa = sb + row*80 + seg*16;
                uint32_t ga = (uint32_t)(m0+row)*256 + (kc+1)*16 + seg*4;
                uint32_t gb = (uint32_t)(n0+row)*256 + (kc+1)*16 + seg*4;
                CP16(sa,         Xh + ga);
                CP16(sa + 10240, Xl + ga);
                CP16(sa + 20480, W  + gb);
            }
            CP_COMMIT();
        }

        #pragma unroll
        for (int ks = 0; ks < 2; ks++) {
            uint32_t ah[4][4], al[4][4], b4[4][4];
            #pragma unroll
            for (int mf = 0; mf < 4; mf++) {
                ldsm4(ah[mf], abase + bo_ + mf*1280 + ks*32);
                ldsm4(al[mf], abase + bo_ + mf*1280 + ks*32 + 10240);
            }
            #pragma unroll
            for (int np = 0; np < 4; np++)
                ldsm4(b4[np], bbase + bo_ + np*1280 + ks*32);
            #pragma unroll
            for (int mf = 0; mf < 4; mf++)
                #pragma unroll
                for (int np = 0; np < 4; np++) {
                    mma16816(acc[mf][2*np  ], ah[mf], &b4[np][0]);
                    mma16816(acc[mf][2*np  ], al[mf], &b4[np][0]);
                    mma16816(acc[mf][2*np+1], ah[mf], &b4[np][2]);
                    mma16816(acc[mf][2*np+1], al[mf], &b4[np][2]);
                }
        }

        if (more) CP_WAIT0();
        __syncthreads();
    }

    // ---- epilogues ----
    if (sel == 0) {
        #pragma unroll
        for (int mf = 0; mf < 4; mf++) {
            int r0 = mw*64 + mf*16 + g;
            #pragma unroll
            for (int nf = 0; nf < 8; nf++) {
                int col = n0 + nw*64 + nf*8 + 2*c;
                float2 bb = *(const float2*)&Bv[col];
                float2 o0 = {acc[mf][nf][0] + bb.x, acc[mf][nf][1] + bb.y};
                float2 o1 = {acc[mf][nf][2] + bb.x, acc[mf][nf][3] + bb.y};
                *(float2*)&Out[(size_t)(m0+r0  )*NFEAT + col] = o0;
                *(float2*)&Out[(size_t)(m0+r0+8)*NFEAT + col] = o1;
            }
        }
    } else if (sel == 1) {
        const float scl = 0.1803368801111204f;   // log2(e)/8
        #pragma unroll
        for (int mf = 0; mf < 4; mf++)
            #pragma unroll
            for (int half = 0; half < 2; half++) {
                int m  = m0 + mw*64 + mf*16 + g + half*8;
                int bb_ = m >> 11, tt = m & (T_SEQ - 1);
                #pragma unroll
                for (int nf = 0; nf < 8; nf++) {
                    int col = nw*64 + nf*8 + 2*c;
                    int hh = (n0 + col) >> 6, d = (n0 + col) & 63;
                    float2 bb = *(const float2*)&Bv[n0 + col];
                    float v0 = (acc[mf][nf][half*2+0] + bb.x) * scl;
                    float v1 = (acc[mf][nf][half*2+1] + bb.y) * scl;
                    uint32_t hw, lw; split2h(v0, v1, hw, lw);
                    size_t widx = (((size_t)(bb_*HEADS+hh)*T_SEQ + tt)*DK + d) >> 1;
                    ((uint32_t*)g_q_h)[widx] = hw;
                    ((uint32_t*)g_q_l)[widx] = lw;
                }
            }
    } else if (sel == 2) {
        #pragma unroll
        for (int mf = 0; mf < 4; mf++)
            #pragma unroll
            for (int half = 0; half < 2; half++) {
                int m  = m0 + mw*64 + mf*16 + g + half*8;
                int bb_ = m >> 11, tt = m & (T_SEQ - 1);
                #pragma unroll
                for (int nf = 0; nf < 8; nf++) {
                    int col = nw*64 + nf*8 + 2*c;
                    int hh = (n0 + col) >> 6, d = (n0 + col) & 63;
                    float2 bb = *(const float2*)&Bv[n0 + col];
                    size_t widx = (((size_t)(bb_*HEADS+hh)*T_SEQ + tt)*DK + d) >> 1;
                    ((uint32_t*)g_k)[widx] =
                        pack2h(acc[mf][nf][half*2+0] + bb.x,
                               acc[mf][nf][half*2+1] + bb.y);
                }
            }
    } else {
        // V: single fp16, transpose to [bh][d][t] through smem
        __syncthreads();
        __half* Ts = (__half*)smw;                      // [128n][136]
        #pragma unroll
        for (int mf = 0; mf < 4; mf++)
            #pragma unroll
            for (int half = 0; half < 2; half++) {
                int t_loc = mw*64 + mf*16 + g + half*8;
                #pragma unroll
                for (int nf = 0; nf < 8; nf++) {
                    int col = nw*64 + nf*8 + 2*c;
                    float2 bb = *(const float2*)&Bv[n0 + col];
                    Ts[(size_t)(col  )*136 + t_loc] =
                        __float2half_rn(acc[mf][nf][half*2+0] + bb.x);
                    Ts[(size_t)(col+1)*136 + t_loc] =
                        __float2half_rn(acc[mf][nf][half*2+1] + bb.y);
                }
            }
        __syncthreads();
        int bb_ = m0 >> 11, tt0 = m0 & (T_SEQ - 1);
        #pragma unroll
        for (int l = 0; l < 16; l++) {
            int idx = tid + l * 128, n = idx >> 4, j = idx & 15;
            int hh = (n0 >> 6) + (n >> 6), d = n & 63;
            size_t go = ((size_t)(bb_*HEADS + hh)*DK + d)*T_SEQ + tt0 + j*8;
            *(uint4*)&g_vt[go] = *(uint4*)((char*)Ts + (size_t)n*272 + j*16);
        }
    }
}

// ---------------------------------------------------------------------------
// fp16 attention: Q split (2-term S), P single via h2exp2 (half-rate MUFU),
// K/V single. Triple-buffered cp.async. 128 threads, 4 warps x 32 q-rows.
// SMEM: QH 0, QL 18432, 3 K/V buffers at 36864 (18432 each), mask 92160.
// ---------------------------------------------------------------------------
#define AQH 0
#define AQL 18432
#define ABUF 36864
#define AMB 92160
#define ATTN_SMEM 92928

static __device__ __forceinline__ void attn_issue_tile(
    uint32_t kbase, int bh, int kt, int tid)
{
    #pragma unroll
    for (int l = 0; l < 4; l++) {
        int idx = tid + l * 128, row = idx >> 3, j = idx & 7;
        uint32_t soff = row * 144 + j * 16;
        size_t kg = ((size_t)bh * T_SEQ + kt + row) * DK + j * 8;
        size_t vg = ((size_t)bh * DK + row) * T_SEQ + kt + j * 8;
        CP16(kbase +        soff, (const char*)&g_k[kg]);
        CP16(kbase + 9216 + soff, (const char*)&g_vt[vg]);
    }
    CP_COMMIT();
}

__global__ __launch_bounds__(128) void attn_tc(const int* __restrict__ mask)
{
    extern __shared__ char sm[];
    const uint32_t sb = smem_u32(sm);
    float* mbufF = (float*)(sm + AMB);

    const int tid = threadIdx.x, lane = tid & 31, wid = tid >> 5;
    const int c = lane & 3;
    const int bh = blockIdx.y, b = bh >> 3, h = bh & 7;
    const int q0 = blockIdx.x * 128;
    const int rb = wid * 32;

    const uint32_t q_amem = sb + AQH + (uint32_t)rb*144 + a_lane_off(lane);
    const uint32_t b_off  = b_lane_off(lane);

    #pragma unroll
    for (int l = 0; l < 8; l++) {
        int idx = tid + l * 128, row = idx >> 3, j = idx & 7;
        size_t gsrc = ((size_t)bh*T_SEQ + q0 + row)*DK + j*8;
        *(uint4*)(sm + AQH + row*144 + j*16) = *(const uint4*)&g_q_h[gsrc];
        *(uint4*)(sm + AQL + row*144 + j*16) = *(const uint4*)&g_q_l[gsrc];
    }
    attn_issue_tile(sb + ABUF,          bh, 0,  tid);
    attn_issue_tile(sb + ABUF + 18432u, bh, 64, tid);
    if (tid < 64) {
        mbufF[tid]      = (float)mask[b*T_SEQ + tid];
        mbufF[64 + tid] = (float)mask[b*T_SEQ + 64 + tid];
    }

    float oacc[2][8][4] = {};
    float lacc[2][2] = {};

    for (int it = 0; it < 32; it++) {
        const int cur3 = it % 3;
        const uint32_t kb = sb + ABUF + (uint32_t)cur3 * 18432u + b_off;
        const uint32_t vb = kb + 9216;

        if (it + 1 < 32) CP_WAIT1(); else CP_WAIT0();
        __syncthreads();
        if (it + 2 < 32) {
            attn_issue_tile(sb + ABUF + (uint32_t)((it+2) % 3) * 18432u,
                            bh, (it+2)*64, tid);
            if (tid < 64)
                mbufF[((it+2) % 3)*64 + tid] =
                    (float)mask[b*T_SEQ + (it+2)*64 + tid];
        }

        // ---- S = Q K^T : Q split, K single ----
        float sacc[2][8][4] = {};
        #pragma unroll
        for (int ks = 0; ks < 4; ks++) {
            uint32_t ah[2][4], al[2][4];
            #pragma unroll
            for (int mf = 0; mf < 2; mf++) {
                ldsm4(ah[mf], q_amem + mf*2304 + ks*32);
                ldsm4(al[mf], q_amem + mf*2304 + ks*32 + 18432);
            }
            #pragma unroll
            for (int np = 0; np < 4; np++) {
                uint32_t k4[4];
                ldsm4(k4, kb + np*2304 + ks*32);
                #pragma unroll
                for (int mf = 0; mf < 2; mf++) {
                    mma16816(sacc[mf][2*np  ], ah[mf], &k4[0]);
                    mma16816(sacc[mf][2*np  ], al[mf], &k4[0]);
                    mma16816(sacc[mf][2*np+1], ah[mf], &k4[2]);
                    mma16816(sacc[mf][2*np+1], al[mf], &k4[2]);
                }
            }
        }

        // ---- exp2 in half2 (h2exp2: 1 MUFU per 2 values) + mask + row-sum --
        uint32_t ph[2][8][2];
        #pragma unroll
        for (int nf = 0; nf < 8; nf++) {
            int cb = nf*8 + 2*c;
            __half2 msk = __floats2half2_rn(mbufF[cur3*64 + cb],
                                            mbufF[cur3*64 + cb + 1]);
            #pragma unroll
            for (int mf = 0; mf < 2; mf++) {
                __half2 s01 = __floats2half2_rn(sacc[mf][nf][0], sacc[mf][nf][1]);
                __half2 s23 = __floats2half2_rn(sacc[mf][nf][2], sacc[mf][nf][3]);
                __half2 e01 = __hmul2(h2exp2(s01), msk);
                __half2 e23 = __hmul2(h2exp2(s23), msk);
                float2 f01 = __half22float2(e01);
                float2 f23 = __half22float2(e23);
                lacc[mf][0] += f01.x + f01.y;
                lacc[mf][1] += f23.x + f23.y;
                ph[mf][nf][0] = *reinterpret_cast<uint32_t*>(&e01);
                ph[mf][nf][1] = *reinterpret_cast<uint32_t*>(&e23);
            }
        }

        // ---- O += P V : P single, V single ----
        #pragma unroll
        for (int kg = 0; kg < 4; kg++) {
            uint32_t pah[2][4];
            #pragma unroll
            for (int mf = 0; mf < 2; mf++) {
                pah[mf][0] = ph[mf][2*kg][0];   pah[mf][1] = ph[mf][2*kg][1];
                pah[mf][2] = ph[mf][2*kg+1][0]; pah[mf][3] = ph[mf][2*kg+1][1];
            }
            #pragma unroll
            for (int np = 0; np < 4; np++) {
                uint32_t v4[4];
                ldsm4(v4, vb + np*2304 + kg*32);
                #pragma unroll
                for (int mf = 0; mf < 2; mf++) {
                    mma16816(oacc[mf][2*np  ], pah[mf], &v4[0]);
                    mma16816(oacc[mf][2*np+1], pah[mf], &v4[2]);
                }
            }
        }
    }

    // ---- reduce l, normalize, store fp16 hi/lo ----
    float inv[2][2];
    #pragma unroll
    for (int mf = 0; mf < 2; mf++)
        #pragma unroll
        for (int hf = 0; hf < 2; hf++) {
            float lv = lacc[mf][hf];
            lv += __shfl_xor_sync(0xffffffffu, lv, 1);
            lv += __shfl_xor_sync(0xffffffffu, lv, 2);
            inv[mf][hf] = (lv > 0.f) ? 1.f / (lv * (1.f + 1e-8f)) : 0.f;
        }

    const int g = lane >> 2;
    #pragma unroll
    for (int mf = 0; mf < 2; mf++) {
        const int row0 = q0 + rb + mf*16 + g, row1 = row0 + 8;
        #pragma unroll
        for (int nd = 0; nd < 8; nd++) {
            int colw = h*32 + nd*4 + c;
            uint32_t hw, lw;
            split2h(oacc[mf][nd][0] * inv[mf][0], oacc[mf][nd][1] * inv[mf][0], hw, lw);
            g_x_h[(size_t)(b*T_SEQ + row0)*256 + colw] = hw;
            g_x_l[(size_t)(b*T_SEQ + row0)*256 + colw] = lw;
            split2h(oacc[mf][nd][2] * inv[mf][1], oacc[mf][nd][3] * inv[mf][1], hw, lw);
            g_x_h[(size_t)(b*T_SEQ + row1)*256 + colw] = hw;
            g_x_l[(size_t)(b*T_SEQ + row1)*256 + colw] = lw;
        }
    }
}

// ---------------------------------------------------------------------------
extern "C" void kernel_launch(void* const* d_in, const int* in_sizes, int n_in,
                              void* d_out, int out_size)
{
    const float* query = (const float*)d_in[0];
    const float* key_  = (const float*)d_in[1];
    const float* value = (const float*)d_in[2];
    const int*   mask  = (const int*)d_in[3];
    const float* Wq = (const float*)d_in[4];
    const float* bq = (const float*)d_in[5];
    const float* Wk = (const float*)d_in[6];
    const float* bk = (const float*)d_in[7];
    const float* Wv = (const float*)d_in[8];
    const float* bv = (const float*)d_in[9];
    const float* Wo = (const float*)d_in[10];
    const float* bo = (const float*)d_in[11];
    float* out = (float*)d_out;

    uint32_t *inh, *inl, *wt, *xh, *xl;
    cudaGetSymbolAddress((void**)&inh, g_in_h);
    cudaGetSymbolAddress((void**)&inl, g_in_l);
    cudaGetSymbolAddress((void**)&wt,  g_wt);
    cudaGetSymbolAddress((void**)&xh,  g_x_h);
    cudaGetSymbolAddress((void**)&xl,  g_x_l);

    conv_all<<<2048, 256>>>(query, key_, value, Wq, Wk, Wv, Wo);

    cudaFuncSetAttribute(gemm_tc, cudaFuncAttributeMaxDynamicSharedMemorySize,
                         GEMM_SMEM);
    cudaFuncSetAttribute(attn_tc, cudaFuncAttributeMaxDynamicSharedMemorySize,
                         ATTN_SMEM);

    gemm_tc<<<dim3(4, 64, 3), 128, GEMM_SMEM>>>(
        inh, inl, wt, bq, bk, bv, nullptr, -1);

    attn_tc<<<dim3(T_SEQ / 128, BHTOT), 128, ATTN_SMEM>>>(mask);

    gemm_tc<<<dim3(4, 64, 1), 128, GEMM_SMEM>>>(
        xh, xl, wt + 3*NPW, bo, nullptr, nullptr, out, 0);
}

// round 14
// speedup vs baseline: 2.1535x; 1.0113x over previous
#include <cuda_runtime.h>
#include <cuda_fp16.h>
#include <cstdint>

#define T_SEQ 2048
#define NFEAT 512
#define HEADS 8
#define DK 64
#define BHTOT 32
#define MTOT 8192

// A-side operands split into fp16 hi/lo; B-side single fp16.
// Q pre-scaled by log2(e)/8 (exp2 in attn). V stored transposed [bh][d][t].
__device__ __half g_q_h[(size_t)BHTOT*T_SEQ*DK];
__device__ __half g_q_l[(size_t)BHTOT*T_SEQ*DK];
__device__ __half g_k[(size_t)BHTOT*T_SEQ*DK];
__device__ __half g_vt[(size_t)BHTOT*DK*T_SEQ];
__device__ uint32_t g_in_h[(size_t)3*MTOT*256];
__device__ uint32_t g_in_l[(size_t)3*MTOT*256];
__device__ uint32_t g_wt[(size_t)4*512*256];
__device__ uint32_t g_x_h[(size_t)MTOT*256];
__device__ uint32_t g_x_l[(size_t)MTOT*256];

#define NPI (MTOT*256)
#define NPW (512*256)

static __device__ __forceinline__ void split2h(float x, float y,
                                               uint32_t& hw, uint32_t& lw) {
    __half2 h = __floats2half2_rn(x, y);
    float hx = __low2float(h), hy = __high2float(h);
    __half2 l = __floats2half2_rn(x - hx, y - hy);
    hw = *reinterpret_cast<uint32_t*>(&h);
    lw = *reinterpret_cast<uint32_t*>(&l);
}
static __device__ __forceinline__ uint32_t pack2h(float x, float y) {
    __half2 h = __floats2half2_rn(x, y);
    return *reinterpret_cast<uint32_t*>(&h);
}

static __device__ __forceinline__ void mma16816(float* d, const uint32_t* a,
                                                const uint32_t* b) {
    asm volatile(
        "mma.sync.aligned.m16n8k16.row.col.f32.f16.f16.f32 "
        "{%0,%1,%2,%3}, {%4,%5,%6,%7}, {%8,%9}, {%0,%1,%2,%3};"
        : "+f"(d[0]), "+f"(d[1]), "+f"(d[2]), "+f"(d[3])
        : "r"(a[0]), "r"(a[1]), "r"(a[2]), "r"(a[3]), "r"(b[0]), "r"(b[1]));
}

static __device__ __forceinline__ void ldsm4(uint32_t* r, uint32_t addr) {
    asm volatile(
        "ldmatrix.sync.aligned.m8n8.x4.shared.b16 {%0,%1,%2,%3}, [%4];"
        : "=r"(r[0]), "=r"(r[1]), "=r"(r[2]), "=r"(r[3]) : "r"(addr));
}

static __device__ __forceinline__ uint32_t smem_u32(const void* p) {
    uint32_t a;
    asm("{ .reg .u64 t; cvta.to.shared.u64 t, %1; cvt.u32.u64 %0, t; }"
        : "=r"(a) : "l"(p));
    return a;
}

#define CP16(saddr, gptr) \
    asm volatile("cp.async.ca.shared.global [%0], [%1], 16;" \
                 :: "r"(saddr), "l"(gptr))
#define CP_COMMIT() asm volatile("cp.async.commit_group;" ::: "memory")
#define CP_WAIT0()  asm volatile("cp.async.wait_group 0;" ::: "memory")
#define CP_WAIT1()  asm volatile("cp.async.wait_group 1;" ::: "memory")

// ldmatrix lane offsets, 144-byte rows (attn)
static __device__ __forceinline__ uint32_t a_lane_off(int lane) {
    return (uint32_t)((lane & 15) * 144 + ((lane & 16) ? 16 : 0));
}
static __device__ __forceinline__ uint32_t b_lane_off(int lane) {
    return (uint32_t)(((lane & 7) + ((lane >> 4) & 1) * 8) * 144 +
                      ((lane & 8) ? 16 : 0));
}
// ldmatrix lane offsets, 80-byte rows (gemm)
static __device__ __forceinline__ uint32_t a80_off(int lane) {
    return (uint32_t)((lane & 15) * 80 + ((lane & 16) ? 16 : 0));
}
static __device__ __forceinline__ uint32_t b80_off(int lane) {
    return (uint32_t)(((lane & 7) + ((lane >> 4) & 1) * 8) * 80 +
                      ((lane & 8) ? 16 : 0));
}

// ---------------------------------------------------------------------------
// Merged converter: inputs -> fp16 hi/lo pairs; weights -> single fp16.
// ---------------------------------------------------------------------------
__global__ void conv_all(const float* __restrict__ q, const float* __restrict__ k,
                         const float* __restrict__ v, const float* __restrict__ wq,
                         const float* __restrict__ wk, const float* __restrict__ wv,
                         const float* __restrict__ wo)
{
    const int total = 3*NPI + 4*NPW;
    for (int i = blockIdx.x * blockDim.x + threadIdx.x; i < total;
         i += gridDim.x * blockDim.x) {
        if (i < 3*NPI) {
            const float* src; int off; uint32_t *dh, *dl;
            if (i < NPI)        { src = q; off = i;         dh = g_in_h;         dl = g_in_l; }
            else if (i < 2*NPI) { src = k; off = i - NPI;   dh = g_in_h + NPI;   dl = g_in_l + NPI; }
            else                { src = v; off = i - 2*NPI; dh = g_in_h + 2*NPI; dl = g_in_l + 2*NPI; }
            float2 p = ((const float2*)src)[off];
            uint32_t hw, lw; split2h(p.x, p.y, hw, lw);
            dh[off] = hw; dl[off] = lw;
        } else {
            int j = i - 3*NPI;
            const float* src; int off; uint32_t* d;
            if (j < NPW)        { src = wq; off = j;         d = g_wt; }
            else if (j < 2*NPW) { src = wk; off = j - NPW;   d = g_wt + NPW; }
            else if (j < 3*NPW) { src = wv; off = j - 2*NPW; d = g_wt + 2*NPW; }
            else                { src = wo; off = j - 3*NPW; d = g_wt + 3*NPW; }
            float2 p = ((const float2*)src)[off];
            d[off] = pack2h(p.x, p.y);
        }
    }
}

// ---------------------------------------------------------------------------
// fp16-2x GEMM, double-buffered cp.async (proven structure, ~89% of floor).
// 128 thr, 4 warps (2mx2n), warp 64x64, k-chunk 32.
// Buffer 30720 B (Ah+0, Al+10240, B+20480, 80 B rows), x2 = 61440.
// ---------------------------------------------------------------------------
#define GEMM_SMEM 61440
extern __shared__ uint32_t smw[];

__global__ __launch_bounds__(128) void gemm_tc(
    const uint32_t* __restrict__ Xh, const uint32_t* __restrict__ Xl,
    const uint32_t* __restrict__ W,
    const float* __restrict__ b0, const float* __restrict__ b1,
    const float* __restrict__ b2, float* __restrict__ Out, int out_sel)
{
    const int tid = threadIdx.x, lane = tid & 31, wid = tid >> 5;
    const int g = lane >> 2, c = lane & 3;
    const int mw = wid >> 1, nw = wid & 1;
    const int m0 = blockIdx.y * 128, n0 = blockIdx.x * 128;

    int sel = out_sel;
    const float* Bv = b0;
    if (out_sel < 0) {
        int z = blockIdx.z;
        sel = 1 + z;
        Xh += (size_t)z * NPI; Xl += (size_t)z * NPI;
        W  += (size_t)z * NPW;
        Bv = (z == 0) ? b0 : (z == 1) ? b1 : b2;
    }

    const uint32_t sbg = smem_u32(smw);
    const uint32_t abase = sbg + (uint32_t)(mw*64)*80 + a80_off(lane);
    const uint32_t bbase = sbg + 20480u + (uint32_t)(nw*64)*80 + b80_off(lane);

    const int seg = tid & 3;
    const int row0 = tid >> 2;

    float acc[4][8][4] = {};

    // prologue
    #pragma unroll
    for (int l = 0; l < 4; l++) {
        int row = row0 + l*32;
        uint32_t sa = sbg + row*80 + seg*16;
        uint32_t ga = (uint32_t)(m0+row)*256 + seg*4;
        uint32_t gb = (uint32_t)(n0+row)*256 + seg*4;
        CP16(sa,         Xh + ga);
        CP16(sa + 10240, Xl + ga);
        CP16(sa + 20480, W  + gb);
    }
    CP_COMMIT();
    CP_WAIT0();
    __syncthreads();

    for (int kc = 0; kc < 16; kc++) {
        const uint32_t bo_ = (uint32_t)(kc & 1) * 30720u;
        const bool more = (kc + 1 < 16);
        if (more) {
            uint32_t sb = sbg + (uint32_t)((kc+1) & 1) * 30720u;
            #pragma unroll
            for (int l = 0; l < 4; l++) {
                int row = row0 + l*32;
                uint32_t sa = sb + row*80 + seg*16;
                uint32_t ga = (uint32_t)(m0+row)*256 + (kc+1)*16 + seg*4;
                uint32_t gb = (uint32_t)(n0+row)*256 + (kc+1)*16 + seg*4;
                CP16(sa,         Xh + ga);
                CP16(sa + 10240, Xl + ga);
                CP16(sa + 20480, W  + gb);
            }
            CP_COMMIT();
        }

        #pragma unroll
        for (int ks = 0; ks < 2; ks++) {
            uint32_t ah[4][4], al[4][4], b4[4][4];
            #pragma unroll
            for (int mf = 0; mf < 4; mf++) {
                ldsm4(ah[mf], abase + bo_ + mf*1280 + ks*32);
                ldsm4(al[mf], abase + bo_ + mf*1280 + ks*32 + 10240);
            }
            #pragma unroll
            for (int np = 0; np < 4; np++)
                ldsm4(b4[np], bbase + bo_ + np*1280 + ks*32);
            #pragma unroll
            for (int mf = 0; mf < 4; mf++)
                #pragma unroll
                for (int np = 0; np < 4; np++) {
                    mma16816(acc[mf][2*np  ], ah[mf], &b4[np][0]);
                    mma16816(acc[mf][2*np  ], al[mf], &b4[np][0]);
                    mma16816(acc[mf][2*np+1], ah[mf], &b4[np][2]);
                    mma16816(acc[mf][2*np+1], al[mf], &b4[np][2]);
                }
        }

        if (more) CP_WAIT0();
        __syncthreads();
    }

    // ---- epilogues ----
    if (sel == 0) {
        #pragma unroll
        for (int mf = 0; mf < 4; mf++) {
            int r0 = mw*64 + mf*16 + g;
            #pragma unroll
            for (int nf = 0; nf < 8; nf++) {
                int col = n0 + nw*64 + nf*8 + 2*c;
                float2 bb = *(const float2*)&Bv[col];
                float2 o0 = {acc[mf][nf][0] + bb.x, acc[mf][nf][1] + bb.y};
                float2 o1 = {acc[mf][nf][2] + bb.x, acc[mf][nf][3] + bb.y};
                *(float2*)&Out[(size_t)(m0+r0  )*NFEAT + col] = o0;
                *(float2*)&Out[(size_t)(m0+r0+8)*NFEAT + col] = o1;
            }
        }
    } else if (sel == 1) {
        const float scl = 0.1803368801111204f;   // log2(e)/8
        #pragma unroll
        for (int mf = 0; mf < 4; mf++)
            #pragma unroll
            for (int half = 0; half < 2; half++) {
                int m  = m0 + mw*64 + mf*16 + g + half*8;
                int bb_ = m >> 11, tt = m & (T_SEQ - 1);
                #pragma unroll
                for (int nf = 0; nf < 8; nf++) {
                    int col = nw*64 + nf*8 + 2*c;
                    int hh = (n0 + col) >> 6, d = (n0 + col) & 63;
                    float2 bb = *(const float2*)&Bv[n0 + col];
                    float v0 = (acc[mf][nf][half*2+0] + bb.x) * scl;
                    float v1 = (acc[mf][nf][half*2+1] + bb.y) * scl;
                    uint32_t hw, lw; split2h(v0, v1, hw, lw);
                    size_t widx = (((size_t)(bb_*HEADS+hh)*T_SEQ + tt)*DK + d) >> 1;
                    ((uint32_t*)g_q_h)[widx] = hw;
                    ((uint32_t*)g_q_l)[widx] = lw;
                }
            }
    } else if (sel == 2) {
        #pragma unroll
        for (int mf = 0; mf < 4; mf++)
            #pragma unroll
            for (int half = 0; half < 2; half++) {
                int m  = m0 + mw*64 + mf*16 + g + half*8;
                int bb_ = m >> 11, tt = m & (T_SEQ - 1);
                #pragma unroll
                for (int nf = 0; nf < 8; nf++) {
                    int col = nw*64 + nf*8 + 2*c;
                    int hh = (n0 + col) >> 6, d = (n0 + col) & 63;
                    float2 bb = *(const float2*)&Bv[n0 + col];
                    size_t widx = (((size_t)(bb_*HEADS+hh)*T_SEQ + tt)*DK + d) >> 1;
                    ((uint32_t*)g_k)[widx] =
                        pack2h(acc[mf][nf][half*2+0] + bb.x,
                               acc[mf][nf][half*2+1] + bb.y);
                }
            }
    } else {
        // V: single fp16, transpose to [bh][d][t] through smem
        __syncthreads();
        __half* Ts = (__half*)smw;                      // [128n][136]
        #pragma unroll
        for (int mf = 0; mf < 4; mf++)
            #pragma unroll
            for (int half = 0; half < 2; half++) {
                int t_loc = mw*64 + mf*16 + g + half*8;
                #pragma unroll
                for (int nf = 0; nf < 8; nf++) {
                    int col = nw*64 + nf*8 + 2*c;
                    float2 bb = *(const float2*)&Bv[n0 + col];
                    Ts[(size_t)(col  )*136 + t_loc] =
                        __float2half_rn(acc[mf][nf][half*2+0] + bb.x);
                    Ts[(size_t)(col+1)*136 + t_loc] =
                        __float2half_rn(acc[mf][nf][half*2+1] + bb.y);
                }
            }
        __syncthreads();
        int bb_ = m0 >> 11, tt0 = m0 & (T_SEQ - 1);
        #pragma unroll
        for (int l = 0; l < 16; l++) {
            int idx = tid + l * 128, n = idx >> 4, j = idx & 15;
            int hh = (n0 >> 6) + (n >> 6), d = n & 63;
            size_t go = ((size_t)(bb_*HEADS + hh)*DK + d)*T_SEQ + tt0 + j*8;
            *(uint4*)&g_vt[go] = *(uint4*)((char*)Ts + (size_t)n*272 + j*16);
        }
    }
}

// ---------------------------------------------------------------------------
// fp16 attention: Q fragments resident in registers (loaded once), P single
// via h2exp2, K/V single, triple-buffered cp.async. 128 thr, 4 warps x 32
// q-rows, 2 CTAs/SM target. Per-tile ldsm: 16 K + 16 V (Q free).
// ---------------------------------------------------------------------------
#define AQH 0
#define AQL 18432
#define ABUF 36864
#define AMB 92160
#define ATTN_SMEM 92928

static __device__ __forceinline__ void attn_issue_tile(
    uint32_t kbase, int bh, int kt, int tid)
{
    #pragma unroll
    for (int l = 0; l < 4; l++) {
        int idx = tid + l * 128, row = idx >> 3, j = idx & 7;
        uint32_t soff = row * 144 + j * 16;
        size_t kg = ((size_t)bh * T_SEQ + kt + row) * DK + j * 8;
        size_t vg = ((size_t)bh * DK + row) * T_SEQ + kt + j * 8;
        CP16(kbase +        soff, (const char*)&g_k[kg]);
        CP16(kbase + 9216 + soff, (const char*)&g_vt[vg]);
    }
    CP_COMMIT();
}

__global__ __launch_bounds__(128, 2) void attn_tc(const int* __restrict__ mask)
{
    extern __shared__ char sm[];
    const uint32_t sb = smem_u32(sm);
    float* mbufF = (float*)(sm + AMB);

    const int tid = threadIdx.x, lane = tid & 31, wid = tid >> 5;
    const int c = lane & 3;
    const int bh = blockIdx.y, b = bh >> 3, h = bh & 7;
    const int q0 = blockIdx.x * 128;
    const int rb = wid * 32;

    const uint32_t q_amem = sb + AQH + (uint32_t)rb*144 + a_lane_off(lane);
    const uint32_t b_off  = b_lane_off(lane);

    #pragma unroll
    for (int l = 0; l < 8; l++) {
        int idx = tid + l * 128, row = idx >> 3, j = idx & 7;
        size_t gsrc = ((size_t)bh*T_SEQ + q0 + row)*DK + j*8;
        *(uint4*)(sm + AQH + row*144 + j*16) = *(const uint4*)&g_q_h[gsrc];
        *(uint4*)(sm + AQL + row*144 + j*16) = *(const uint4*)&g_q_l[gsrc];
    }
    attn_issue_tile(sb + ABUF,          bh, 0,  tid);
    attn_issue_tile(sb + ABUF + 18432u, bh, 64, tid);
    if (tid < 64) {
        mbufF[tid]      = (float)mask[b*T_SEQ + tid];
        mbufF[64 + tid] = (float)mask[b*T_SEQ + 64 + tid];
    }
    __syncthreads();   // Q smem visible to all warps

    // ---- hoist Q fragments into registers (loop-invariant) ----
    uint32_t qfh[2][4][4], qfl[2][4][4];
    #pragma unroll
    for (int mf = 0; mf < 2; mf++)
        #pragma unroll
        for (int ks = 0; ks < 4; ks++) {
            ldsm4(qfh[mf][ks], q_amem + mf*2304 + ks*32);
            ldsm4(qfl[mf][ks], q_amem + mf*2304 + ks*32 + 18432);
        }

    float oacc[2][8][4] = {};
    float lacc[2][2] = {};

    for (int it = 0; it < 32; it++) {
        const int cur3 = it % 3;
        const uint32_t kb = sb + ABUF + (uint32_t)cur3 * 18432u + b_off;
        const uint32_t vb = kb + 9216;

        if (it + 1 < 32) CP_WAIT1(); else CP_WAIT0();
        __syncthreads();
        if (it + 2 < 32) {
            attn_issue_tile(sb + ABUF + (uint32_t)((it+2) % 3) * 18432u,
                            bh, (it+2)*64, tid);
            if (tid < 64)
                mbufF[((it+2) % 3)*64 + tid] =
                    (float)mask[b*T_SEQ + (it+2)*64 + tid];
        }

        // ---- S = Q K^T : Q in registers, K single from smem ----
        float sacc[2][8][4] = {};
        #pragma unroll
        for (int ks = 0; ks < 4; ks++) {
            #pragma unroll
            for (int np = 0; np < 4; np++) {
                uint32_t k4[4];
                ldsm4(k4, kb + np*2304 + ks*32);
                #pragma unroll
                for (int mf = 0; mf < 2; mf++) {
                    mma16816(sacc[mf][2*np  ], qfh[mf][ks], &k4[0]);
                    mma16816(sacc[mf][2*np  ], qfl[mf][ks], &k4[0]);
                    mma16816(sacc[mf][2*np+1], qfh[mf][ks], &k4[2]);
                    mma16816(sacc[mf][2*np+1], qfl[mf][ks], &k4[2]);
                }
            }
        }

        // ---- exp2 in half2 + mask + row-sum ----
        uint32_t ph[2][8][2];
        #pragma unroll
        for (int nf = 0; nf < 8; nf++) {
            int cb = nf*8 + 2*c;
            __half2 msk = __floats2half2_rn(mbufF[cur3*64 + cb],
                                            mbufF[cur3*64 + cb + 1]);
            #pragma unroll
            for (int mf = 0; mf < 2; mf++) {
                __half2 s01 = __floats2half2_rn(sacc[mf][nf][0], sacc[mf][nf][1]);
                __half2 s23 = __floats2half2_rn(sacc[mf][nf][2], sacc[mf][nf][3]);
                __half2 e01 = __hmul2(h2exp2(s01), msk);
                __half2 e23 = __hmul2(h2exp2(s23), msk);
                float2 f01 = __half22float2(e01);
                float2 f23 = __half22float2(e23);
                lacc[mf][0] += f01.x + f01.y;
                lacc[mf][1] += f23.x + f23.y;
                ph[mf][nf][0] = *reinterpret_cast<uint32_t*>(&e01);
                ph[mf][nf][1] = *reinterpret_cast<uint32_t*>(&e23);
            }
        }

        // ---- O += P V : P single, V single ----
        #pragma unroll
        for (int kg = 0; kg < 4; kg++) {
            uint32_t pah[2][4];
            #pragma unroll
            for (int mf = 0; mf < 2; mf++) {
                pah[mf][0] = ph[mf][2*kg][0];   pah[mf][1] = ph[mf][2*kg][1];
                pah[mf][2] = ph[mf][2*kg+1][0]; pah[mf][3] = ph[mf][2*kg+1][1];
            }
            #pragma unroll
            for (int np = 0; np < 4; np++) {
                uint32_t v4[4];
                ldsm4(v4, vb + np*2304 + kg*32);
                #pragma unroll
                for (int mf = 0; mf < 2; mf++) {
                    mma16816(oacc[mf][2*np  ], pah[mf], &v4[0]);
                    mma16816(oacc[mf][2*np+1], pah[mf], &v4[2]);
                }
            }
        }
    }

    // ---- reduce l, normalize, store fp16 hi/lo ----
    float inv[2][2];
    #pragma unroll
    for (int mf = 0; mf < 2; mf++)
        #pragma unroll
        for (int hf = 0; hf < 2; hf++) {
            float lv = lacc[mf][hf];
            lv += __shfl_xor_sync(0xffffffffu, lv, 1);
            lv += __shfl_xor_sync(0xffffffffu, lv, 2);
            inv[mf][hf] = (lv > 0.f) ? 1.f / (lv * (1.f + 1e-8f)) : 0.f;
        }

    const int g = lane >> 2;
    #pragma unroll
    for (int mf = 0; mf < 2; mf++) {
        const int row0 = q0 + rb + mf*16 + g, row1 = row0 + 8;
        #pragma unroll
        for (int nd = 0; nd < 8; nd++) {
            int colw = h*32 + nd*4 + c;
            uint32_t hw, lw;
            split2h(oacc[mf][nd][0] * inv[mf][0], oacc[mf][nd][1] * inv[mf][0], hw, lw);
            g_x_h[(size_t)(b*T_SEQ + row0)*256 + colw] = hw;
            g_x_l[(size_t)(b*T_SEQ + row0)*256 + colw] = lw;
            split2h(oacc[mf][nd][2] * inv[mf][1], oacc[mf][nd][3] * inv[mf][1], hw, lw);
            g_x_h[(size_t)(b*T_SEQ + row1)*256 + colw] = hw;
            g_x_l[(size_t)(b*T_SEQ + row1)*256 + colw] = lw;
        }
    }
}

// ---------------------------------------------------------------------------
extern "C" void kernel_launch(void* const* d_in, const int* in_sizes, int n_in,
                              void* d_out, int out_size)
{
    const float* query = (const float*)d_in[0];
    const float* key_  = (const float*)d_in[1];
    const float* value = (const float*)d_in[2];
    const int*   mask  = (const int*)d_in[3];
    const float* Wq = (const float*)d_in[4];
    const float* bq = (const float*)d_in[5];
    const float* Wk = (const float*)d_in[6];
    const float* bk = (const float*)d_in[7];
    const float* Wv = (const float*)d_in[8];
    const float* bv = (const float*)d_in[9];
    const float* Wo = (const float*)d_in[10];
    const float* bo = (const float*)d_in[11];
    float* out = (float*)d_out;

    uint32_t *inh, *inl, *wt, *xh, *xl;
    cudaGetSymbolAddress((void**)&inh, g_in_h);
    cudaGetSymbolAddress((void**)&inl, g_in_l);
    cudaGetSymbolAddress((void**)&wt,  g_wt);
    cudaGetSymbolAddress((void**)&xh,  g_x_h);
    cudaGetSymbolAddress((void**)&xl,  g_x_l);

    conv_all<<<2048, 256>>>(query, key_, value, Wq, Wk, Wv, Wo);

    cudaFuncSetAttribute(gemm_tc, cudaFuncAttributeMaxDynamicSharedMemorySize,
                         GEMM_SMEM);
    cudaFuncSetAttribute(attn_tc, cudaFuncAttributeMaxDynamicSharedMemorySize,
                         ATTN_SMEM);

    gemm_tc<<<dim3(4, 64, 3), 128, GEMM_SMEM>>>(
        inh, inl, wt, bq, bk, bv, nullptr, -1);

    attn_tc<<<dim3(T_SEQ / 128, BHTOT), 128, ATTN_SMEM>>>(mask);

    gemm_tc<<<dim3(4, 64, 1), 128, GEMM_SMEM>>>(
        xh, xl, wt + 3*NPW, bo, nullptr, nullptr, out, 0);
}

// round 16
// speedup vs baseline: 2.4399x; 1.1330x over previous
#include <cuda_runtime.h>
#include <cuda_fp16.h>
#include <cstdint>

#define T_SEQ 2048
#define NFEAT 512
#define HEADS 8
#define DK 64
#define BHTOT 32
#define MTOT 8192

// Projections: X 2-term (hi/lo), W single. Attention: Q/K/V/P all single fp16
// (S score error ~2^-11-grade, calibrated safe); attn-out x kept 2-term.
// Q pre-scaled by log2(e)/8 (exp2 in attn). V stored transposed [bh][d][t].
__device__ __half g_q[(size_t)BHTOT*T_SEQ*DK];
__device__ __half g_k[(size_t)BHTOT*T_SEQ*DK];
__device__ __half g_vt[(size_t)BHTOT*DK*T_SEQ];
__device__ uint32_t g_in_h[(size_t)3*MTOT*256];
__device__ uint32_t g_in_l[(size_t)3*MTOT*256];
__device__ uint32_t g_wt[(size_t)4*512*256];
__device__ uint32_t g_x_h[(size_t)MTOT*256];
__device__ uint32_t g_x_l[(size_t)MTOT*256];

#define NPI (MTOT*256)
#define NPW (512*256)

static __device__ __forceinline__ void split2h(float x, float y,
                                               uint32_t& hw, uint32_t& lw) {
    __half2 h = __floats2half2_rn(x, y);
    float hx = __low2float(h), hy = __high2float(h);
    __half2 l = __floats2half2_rn(x - hx, y - hy);
    hw = *reinterpret_cast<uint32_t*>(&h);
    lw = *reinterpret_cast<uint32_t*>(&l);
}
static __device__ __forceinline__ uint32_t pack2h(float x, float y) {
    __half2 h = __floats2half2_rn(x, y);
    return *reinterpret_cast<uint32_t*>(&h);
}

static __device__ __forceinline__ void mma16816(float* d, const uint32_t* a,
                                                const uint32_t* b) {
    asm volatile(
        "mma.sync.aligned.m16n8k16.row.col.f32.f16.f16.f32 "
        "{%0,%1,%2,%3}, {%4,%5,%6,%7}, {%8,%9}, {%0,%1,%2,%3};"
        : "+f"(d[0]), "+f"(d[1]), "+f"(d[2]), "+f"(d[3])
        : "r"(a[0]), "r"(a[1]), "r"(a[2]), "r"(a[3]), "r"(b[0]), "r"(b[1]));
}

static __device__ __forceinline__ void ldsm4(uint32_t* r, uint32_t addr) {
    asm volatile(
        "ldmatrix.sync.aligned.m8n8.x4.shared.b16 {%0,%1,%2,%3}, [%4];"
        : "=r"(r[0]), "=r"(r[1]), "=r"(r[2]), "=r"(r[3]) : "r"(addr));
}

static __device__ __forceinline__ uint32_t smem_u32(const void* p) {
    uint32_t a;
    asm("{ .reg .u64 t; cvta.to.shared.u64 t, %1; cvt.u32.u64 %0, t; }"
        : "=r"(a) : "l"(p));
    return a;
}

#define CP16(saddr, gptr) \
    asm volatile("cp.async.ca.shared.global [%0], [%1], 16;" \
                 :: "r"(saddr), "l"(gptr))
#define CP_COMMIT() asm volatile("cp.async.commit_group;" ::: "memory")
#define CP_WAIT0()  asm volatile("cp.async.wait_group 0;" ::: "memory")
#define CP_WAIT1()  asm volatile("cp.async.wait_group 1;" ::: "memory")

// ldmatrix lane offsets, 144-byte rows (attn)
static __device__ __forceinline__ uint32_t a_lane_off(int lane) {
    return (uint32_t)((lane & 15) * 144 + ((lane & 16) ? 16 : 0));
}
static __device__ __forceinline__ uint32_t b_lane_off(int lane) {
    return (uint32_t)(((lane & 7) + ((lane >> 4) & 1) * 8) * 144 +
                      ((lane & 8) ? 16 : 0));
}
// ldmatrix lane offsets, 80-byte rows (gemm)
static __device__ __forceinline__ uint32_t a80_off(int lane) {
    return (uint32_t)((lane & 15) * 80 + ((lane & 16) ? 16 : 0));
}
static __device__ __forceinline__ uint32_t b80_off(int lane) {
    return (uint32_t)(((lane & 7) + ((lane >> 4) & 1) * 8) * 80 +
                      ((lane & 8) ? 16 : 0));
}

// ---------------------------------------------------------------------------
// Merged converter: inputs -> fp16 hi/lo pairs; weights -> single fp16.
// ---------------------------------------------------------------------------
__global__ void conv_all(const float* __restrict__ q, const float* __restrict__ k,
                         const float* __restrict__ v, const float* __restrict__ wq,
                         const float* __restrict__ wk, const float* __restrict__ wv,
                         const float* __restrict__ wo)
{
    const int total = 3*NPI + 4*NPW;
    for (int i = blockIdx.x * blockDim.x + threadIdx.x; i < total;
         i += gridDim.x * blockDim.x) {
        if (i < 3*NPI) {
            const float* src; int off; uint32_t *dh, *dl;
            if (i < NPI)        { src = q; off = i;         dh = g_in_h;         dl = g_in_l; }
            else if (i < 2*NPI) { src = k; off = i - NPI;   dh = g_in_h + NPI;   dl = g_in_l + NPI; }
            else                { src = v; off = i - 2*NPI; dh = g_in_h + 2*NPI; dl = g_in_l + 2*NPI; }
            float2 p = ((const float2*)src)[off];
            uint32_t hw, lw; split2h(p.x, p.y, hw, lw);
            dh[off] = hw; dl[off] = lw;
        } else {
            int j = i - 3*NPI;
            const float* src; int off; uint32_t* d;
            if (j < NPW)        { src = wq; off = j;         d = g_wt; }
            else if (j < 2*NPW) { src = wk; off = j - NPW;   d = g_wt + NPW; }
            else if (j < 3*NPW) { src = wv; off = j - 2*NPW; d = g_wt + 2*NPW; }
            else                { src = wo; off = j - 3*NPW; d = g_wt + 3*NPW; }
            float2 p = ((const float2*)src)[off];
            d[off] = pack2h(p.x, p.y);
        }
    }
}

// ---------------------------------------------------------------------------
// fp16-2x GEMM, double-buffered cp.async (proven structure).
// 128 thr, 4 warps (2mx2n), warp 64x64, k-chunk 32.
// Buffer 30720 B (Ah+0, Al+10240, B+20480, 80 B rows), x2 = 61440.
// ---------------------------------------------------------------------------
#define GEMM_SMEM 61440
extern __shared__ uint32_t smw[];

__global__ __launch_bounds__(128) void gemm_tc(
    const uint32_t* __restrict__ Xh, const uint32_t* __restrict__ Xl,
    const uint32_t* __restrict__ W,
    const float* __restrict__ b0, const float* __restrict__ b1,
    const float* __restrict__ b2, float* __restrict__ Out, int out_sel)
{
    const int tid = threadIdx.x, lane = tid & 31, wid = tid >> 5;
    const int g = lane >> 2, c = lane & 3;
    const int mw = wid >> 1, nw = wid & 1;
    const int m0 = blockIdx.y * 128, n0 = blockIdx.x * 128;

    int sel = out_sel;
    const float* Bv = b0;
    if (out_sel < 0) {
        int z = blockIdx.z;
        sel = 1 + z;
        Xh += (size_t)z * NPI; Xl += (size_t)z * NPI;
        W  += (size_t)z * NPW;
        Bv = (z == 0) ? b0 : (z == 1) ? b1 : b2;
    }

    const uint32_t sbg = smem_u32(smw);
    const uint32_t abase = sbg + (uint32_t)(mw*64)*80 + a80_off(lane);
    const uint32_t bbase = sbg + 20480u + (uint32_t)(nw*64)*80 + b80_off(lane);

    const int seg = tid & 3;
    const int row0 = tid >> 2;

    float acc[4][8][4] = {};

    // prologue
    #pragma unroll
    for (int l = 0; l < 4; l++) {
        int row = row0 + l*32;
        uint32_t sa = sbg + row*80 + seg*16;
        uint32_t ga = (uint32_t)(m0+row)*256 + seg*4;
        uint32_t gb = (uint32_t)(n0+row)*256 + seg*4;
        CP16(sa,         Xh + ga);
        CP16(sa + 10240, Xl + ga);
        CP16(sa + 20480, W  + gb);
    }
    CP_COMMIT();
    CP_WAIT0();
    __syncthreads();

    for (int kc = 0; kc < 16; kc++) {
        const uint32_t bo_ = (uint32_t)(kc & 1) * 30720u;
        const bool more = (kc + 1 < 16);
        if (more) {
            uint32_t sb = sbg + (uint32_t)((kc+1) & 1) * 30720u;
            #pragma unroll
            for (int l = 0; l < 4; l++) {
                int row = row0 + l*32;
                uint32_t sa = sb + row*80 + seg*16;
                uint32_t ga = (uint32_t)(m0+row)*256 + (kc+1)*16 + seg*4;
                uint32_t gb = (uint32_t)(n0+row)*256 + (kc+1)*16 + seg*4;
                CP16(sa,         Xh + ga);
                CP16(sa + 10240, Xl + ga);
                CP16(sa + 20480, W  + gb);
            }
            CP_COMMIT();
        }

        #pragma unroll
        for (int ks = 0; ks < 2; ks++) {
            uint32_t ah[4][4], al[4][4], b4[4][4];
            #pragma unroll
            for (int mf = 0; mf < 4; mf++) {
                ldsm4(ah[mf], abase + bo_ + mf*1280 + ks*32);
                ldsm4(al[mf], abase + bo_ + mf*1280 + ks*32 + 10240);
            }
            #pragma unroll
            for (int np = 0; np < 4; np++)
                ldsm4(b4[np], bbase + bo_ + np*1280 + ks*32);
            #pragma unroll
            for (int mf = 0; mf < 4; mf++)
                #pragma unroll
                for (int np = 0; np < 4; np++) {
                    mma16816(acc[mf][2*np  ], ah[mf], &b4[np][0]);
                    mma16816(acc[mf][2*np  ], al[mf], &b4[np][0]);
                    mma16816(acc[mf][2*np+1], ah[mf], &b4[np][2]);
                    mma16816(acc[mf][2*np+1], al[mf], &b4[np][2]);
                }
        }

        if (more) CP_WAIT0();
        __syncthreads();
    }

    // ---- epilogues ----
    if (sel == 0) {
        #pragma unroll
        for (int mf = 0; mf < 4; mf++) {
            int r0 = mw*64 + mf*16 + g;
            #pragma unroll
            for (int nf = 0; nf < 8; nf++) {
                int col = n0 + nw*64 + nf*8 + 2*c;
                float2 bb = *(const float2*)&Bv[col];
                float2 o0 = {acc[mf][nf][0] + bb.x, acc[mf][nf][1] + bb.y};
                float2 o1 = {acc[mf][nf][2] + bb.x, acc[mf][nf][3] + bb.y};
                *(float2*)&Out[(size_t)(m0+r0  )*NFEAT + col] = o0;
                *(float2*)&Out[(size_t)(m0+r0+8)*NFEAT + col] = o1;
            }
        }
    } else if (sel == 1 || sel == 2) {
        __half* O = (sel == 1) ? g_q : g_k;
        const float scl = (sel == 1) ? 0.1803368801111204f : 1.0f;  // log2e/8
        #pragma unroll
        for (int mf = 0; mf < 4; mf++)
            #pragma unroll
            for (int half = 0; half < 2; half++) {
                int m  = m0 + mw*64 + mf*16 + g + half*8;
                int bb_ = m >> 11, tt = m & (T_SEQ - 1);
                #pragma unroll
                for (int nf = 0; nf < 8; nf++) {
                    int col = nw*64 + nf*8 + 2*c;
                    int hh = (n0 + col) >> 6, d = (n0 + col) & 63;
                    float2 bb = *(const float2*)&Bv[n0 + col];
                    size_t widx = (((size_t)(bb_*HEADS+hh)*T_SEQ + tt)*DK + d) >> 1;
                    ((uint32_t*)O)[widx] =
                        pack2h((acc[mf][nf][half*2+0] + bb.x) * scl,
                               (acc[mf][nf][half*2+1] + bb.y) * scl);
                }
            }
    } else {
        // V: single fp16, transpose to [bh][d][t] through smem
        __syncthreads();
        __half* Ts = (__half*)smw;                      // [128n][136]
        #pragma unroll
        for (int mf = 0; mf < 4; mf++)
            #pragma unroll
            for (int half = 0; half < 2; half++) {
                int t_loc = mw*64 + mf*16 + g + half*8;
                #pragma unroll
                for (int nf = 0; nf < 8; nf++) {
                    int col = nw*64 + nf*8 + 2*c;
                    float2 bb = *(const float2*)&Bv[n0 + col];
                    Ts[(size_t)(col  )*136 + t_loc] =
                        __float2half_rn(acc[mf][nf][half*2+0] + bb.x);
                    Ts[(size_t)(col+1)*136 + t_loc] =
                        __float2half_rn(acc[mf][nf][half*2+1] + bb.y);
                }
            }
        __syncthreads();
        int bb_ = m0 >> 11, tt0 = m0 & (T_SEQ - 1);
        #pragma unroll
        for (int l = 0; l < 16; l++) {
            int idx = tid + l * 128, n = idx >> 4, j = idx & 15;
            int hh = (n0 >> 6) + (n >> 6), d = n & 63;
            size_t go = ((size_t)(bb_*HEADS + hh)*DK + d)*T_SEQ + tt0 + j*8;
            *(uint4*)&g_vt[go] = *(uint4*)((char*)Ts + (size_t)n*272 + j*16);
        }
    }
}

// ---------------------------------------------------------------------------
// fp16 attention, all-single operands: Q resident in registers (1-term S),
// P single via h2exp2, K/V single. Triple-buffered cp.async.
// 128 thr, 4 warps x 32 q-rows, 2 CTAs/SM.
// SMEM: Q 0 (18432), 3 K/V buffers at 18432 (18432 each), mask at 73728.
// ---------------------------------------------------------------------------
#define AQ   0
#define ABUF 18432
#define AMB  73728
#define ATTN_SMEM 74496

static __device__ __forceinline__ void attn_issue_tile(
    uint32_t kbase, int bh, int kt, int tid)
{
    #pragma unroll
    for (int l = 0; l < 4; l++) {
        int idx = tid + l * 128, row = idx >> 3, j = idx & 7;
        uint32_t soff = row * 144 + j * 16;
        size_t kg = ((size_t)bh * T_SEQ + kt + row) * DK + j * 8;
        size_t vg = ((size_t)bh * DK + row) * T_SEQ + kt + j * 8;
        CP16(kbase +        soff, (const char*)&g_k[kg]);
        CP16(kbase + 9216 + soff, (const char*)&g_vt[vg]);
    }
    CP_COMMIT();
}

__global__ __launch_bounds__(128, 2) void attn_tc(const int* __restrict__ mask)
{
    extern __shared__ char sm[];
    const uint32_t sb = smem_u32(sm);
    float* mbufF = (float*)(sm + AMB);

    const int tid = threadIdx.x, lane = tid & 31, wid = tid >> 5;
    const int c = lane & 3;
    const int bh = blockIdx.y, b = bh >> 3, h = bh & 7;
    const int q0 = blockIdx.x * 128;
    const int rb = wid * 32;

    const uint32_t q_amem = sb + AQ + (uint32_t)rb*144 + a_lane_off(lane);
    const uint32_t b_off  = b_lane_off(lane);

    // full 128-row Q tile: 1024 uint4 -> 8 iterations x 128 threads
    #pragma unroll
    for (int l = 0; l < 8; l++) {
        int idx = tid + l * 128, row = idx >> 3, j = idx & 7;
        size_t gsrc = ((size_t)bh*T_SEQ + q0 + row)*DK + j*8;
        *(uint4*)(sm + AQ + row*144 + j*16) = *(const uint4*)&g_q[gsrc];
    }
    attn_issue_tile(sb + ABUF,          bh, 0,  tid);
    attn_issue_tile(sb + ABUF + 18432u, bh, 64, tid);
    if (tid < 64) {
        mbufF[tid]      = (float)mask[b*T_SEQ + tid];
        mbufF[64 + tid] = (float)mask[b*T_SEQ + 64 + tid];
    }
    __syncthreads();   // Q smem visible

    // ---- Q fragments resident in registers (loop-invariant, single) ----
    uint32_t qf[2][4][4];
    #pragma unroll
    for (int mf = 0; mf < 2; mf++)
        #pragma unroll
        for (int ks = 0; ks < 4; ks++)
            ldsm4(qf[mf][ks], q_amem + mf*2304 + ks*32);

    float oacc[2][8][4] = {};
    float lacc[2][2] = {};

    for (int it = 0; it < 32; it++) {
        const int cur3 = it % 3;
        const uint32_t kb = sb + ABUF + (uint32_t)cur3 * 18432u + b_off;
        const uint32_t vb = kb + 9216;

        if (it + 1 < 32) CP_WAIT1(); else CP_WAIT0();
        __syncthreads();
        if (it + 2 < 32) {
            attn_issue_tile(sb + ABUF + (uint32_t)((it+2) % 3) * 18432u,
                            bh, (it+2)*64, tid);
            if (tid < 64)
                mbufF[((it+2) % 3)*64 + tid] =
                    (float)mask[b*T_SEQ + (it+2)*64 + tid];
        }

        // ---- S = Q K^T : single-term ----
        float sacc[2][8][4] = {};
        #pragma unroll
        for (int ks = 0; ks < 4; ks++) {
            #pragma unroll
            for (int np = 0; np < 4; np++) {
                uint32_t k4[4];
                ldsm4(k4, kb + np*2304 + ks*32);
                #pragma unroll
                for (int mf = 0; mf < 2; mf++) {
                    mma16816(sacc[mf][2*np  ], qf[mf][ks], &k4[0]);
                    mma16816(sacc[mf][2*np+1], qf[mf][ks], &k4[2]);
                }
            }
        }

        // ---- exp2 in half2 + mask + row-sum ----
        uint32_t ph[2][8][2];
        #pragma unroll
        for (int nf = 0; nf < 8; nf++) {
            int cb = nf*8 + 2*c;
            __half2 msk = __floats2half2_rn(mbufF[cur3*64 + cb],
                                            mbufF[cur3*64 + cb + 1]);
            #pragma unroll
            for (int mf = 0; mf < 2; mf++) {
                __half2 s01 = __floats2half2_rn(sacc[mf][nf][0], sacc[mf][nf][1]);
                __half2 s23 = __floats2half2_rn(sacc[mf][nf][2], sacc[mf][nf][3]);
                __half2 e01 = __hmul2(h2exp2(s01), msk);
                __half2 e23 = __hmul2(h2exp2(s23), msk);
                float2 f01 = __half22float2(e01);
                float2 f23 = __half22float2(e23);
                lacc[mf][0] += f01.x + f01.y;
                lacc[mf][1] += f23.x + f23.y;
                ph[mf][nf][0] = *reinterpret_cast<uint32_t*>(&e01);
                ph[mf][nf][1] = *reinterpret_cast<uint32_t*>(&e23);
            }
        }

        // ---- O += P V ----
        #pragma unroll
        for (int kg = 0; kg < 4; kg++) {
            uint32_t pah[2][4];
            #pragma unroll
            for (int mf = 0; mf < 2; mf++) {
                pah[mf][0] = ph[mf][2*kg][0];   pah[mf][1] = ph[mf][2*kg][1];
                pah[mf][2] = ph[mf][2*kg+1][0]; pah[mf][3] = ph[mf][2*kg+1][1];
            }
            #pragma unroll
            for (int np = 0; np < 4; np++) {
                uint32_t v4[4];
                ldsm4(v4, vb + np*2304 + kg*32);
                #pragma unroll
                for (int mf = 0; mf < 2; mf++) {
                    mma16816(oacc[mf][2*np  ], pah[mf], &v4[0]);
                    mma16816(oacc[mf][2*np+1], pah[mf], &v4[2]);
                }
            }
        }
    }

    // ---- reduce l, normalize, store fp16 hi/lo ----
    float inv[2][2];
    #pragma unroll
    for (int mf = 0; mf < 2; mf++)
        #pragma unroll
        for (int hf = 0; hf < 2; hf++) {
            float lv = lacc[mf][hf];
            lv += __shfl_xor_sync(0xffffffffu, lv, 1);
            lv += __shfl_xor_sync(0xffffffffu, lv, 2);
            inv[mf][hf] = (lv > 0.f) ? 1.f / (lv * (1.f + 1e-8f)) : 0.f;
        }

    const int g = lane >> 2;
    #pragma unroll
    for (int mf = 0; mf < 2; mf++) {
        const int row0 = q0 + rb + mf*16 + g, row1 = row0 + 8;
        #pragma unroll
        for (int nd = 0; nd < 8; nd++) {
            int colw = h*32 + nd*4 + c;
            uint32_t hw, lw;
            split2h(oacc[mf][nd][0] * inv[mf][0], oacc[mf][nd][1] * inv[mf][0], hw, lw);
            g_x_h[(size_t)(b*T_SEQ + row0)*256 + colw] = hw;
            g_x_l[(size_t)(b*T_SEQ + row0)*256 + colw] = lw;
            split2h(oacc[mf][nd][2] * inv[mf][1], oacc[mf][nd][3] * inv[mf][1], hw, lw);
            g_x_h[(size_t)(b*T_SEQ + row1)*256 + colw] = hw;
            g_x_l[(size_t)(b*T_SEQ + row1)*256 + colw] = lw;
        }
    }
}

// ---------------------------------------------------------------------------
extern "C" void kernel_launch(void* const* d_in, const int* in_sizes, int n_in,
                              void* d_out, int out_size)
{
    const float* query = (const float*)d_in[0];
    const float* key_  = (const float*)d_in[1];
    const float* value = (const float*)d_in[2];
    const int*   mask  = (const int*)d_in[3];
    const float* Wq = (const float*)d_in[4];
    const float* bq = (const float*)d_in[5];
    const float* Wk = (const float*)d_in[6];
    const float* bk = (const float*)d_in[7];
    const float* Wv = (const float*)d_in[8];
    const float* bv = (const float*)d_in[9];
    const float* Wo = (const float*)d_in[10];
    const float* bo = (const float*)d_in[11];
    float* out = (float*)d_out;

    uint32_t *inh, *inl, *wt, *xh, *xl;
    cudaGetSymbolAddress((void**)&inh, g_in_h);
    cudaGetSymbolAddress((void**)&inl, g_in_l);
    cudaGetSymbolAddress((void**)&wt,  g_wt);
    cudaGetSymbolAddress((void**)&xh,  g_x_h);
    cudaGetSymbolAddress((void**)&xl,  g_x_l);

    conv_all<<<2048, 256>>>(query, key_, value, Wq, Wk, Wv, Wo);

    cudaFuncSetAttribute(gemm_tc, cudaFuncAttributeMaxDynamicSharedMemorySize,
                         GEMM_SMEM);
    cudaFuncSetAttribute(attn_tc, cudaFuncAttributeMaxDynamicSharedMemorySize,
                         ATTN_SMEM);

    gemm_tc<<<dim3(4, 64, 3), 128, GEMM_SMEM>>>(
        inh, inl, wt, bq, bk, bv, nullptr, -1);

    attn_tc<<<dim3(T_SEQ / 128, BHTOT), 128, ATTN_SMEM>>>(mask);

    gemm_tc<<<dim3(4, 64, 1), 128, GEMM_SMEM>>>(
        xh, xl, wt + 3*NPW, bo, nullptr, nullptr, out, 0);
}

// round 17
// speedup vs baseline: 2.9074x; 1.1916x over previous
#include <cuda_runtime.h>
#include <cuda_fp16.h>
#include <cstdint>

#define T_SEQ 2048
#define NFEAT 512
#define HEADS 8
#define DK 64
#define BHTOT 32
#define MTOT 8192

// All operands single fp16 (error model calibrated over rounds 11-16:
// each single-ization adds ~1.3e-4 in quadrature; budget 1e-3).
// Q pre-scaled by log2(e)/8 (exp2 in attn). V stored transposed [bh][d][t].
__device__ __half g_q[(size_t)BHTOT*T_SEQ*DK];
__device__ __half g_k[(size_t)BHTOT*T_SEQ*DK];
__device__ __half g_vt[(size_t)BHTOT*DK*T_SEQ];
__device__ uint32_t g_in[(size_t)3*MTOT*256];   // inputs, half2 words
__device__ uint32_t g_wt[(size_t)4*512*256];    // weights, half2 words
__device__ uint32_t g_x[(size_t)MTOT*256];      // attn out, half2 words

#define NPI (MTOT*256)
#define NPW (512*256)

static __device__ __forceinline__ uint32_t pack2h(float x, float y) {
    __half2 h = __floats2half2_rn(x, y);
    return *reinterpret_cast<uint32_t*>(&h);
}

static __device__ __forceinline__ void mma16816(float* d, const uint32_t* a,
                                                const uint32_t* b) {
    asm volatile(
        "mma.sync.aligned.m16n8k16.row.col.f32.f16.f16.f32 "
        "{%0,%1,%2,%3}, {%4,%5,%6,%7}, {%8,%9}, {%0,%1,%2,%3};"
        : "+f"(d[0]), "+f"(d[1]), "+f"(d[2]), "+f"(d[3])
        : "r"(a[0]), "r"(a[1]), "r"(a[2]), "r"(a[3]), "r"(b[0]), "r"(b[1]));
}

static __device__ __forceinline__ void ldsm4(uint32_t* r, uint32_t addr) {
    asm volatile(
        "ldmatrix.sync.aligned.m8n8.x4.shared.b16 {%0,%1,%2,%3}, [%4];"
        : "=r"(r[0]), "=r"(r[1]), "=r"(r[2]), "=r"(r[3]) : "r"(addr));
}

static __device__ __forceinline__ uint32_t smem_u32(const void* p) {
    uint32_t a;
    asm("{ .reg .u64 t; cvta.to.shared.u64 t, %1; cvt.u32.u64 %0, t; }"
        : "=r"(a) : "l"(p));
    return a;
}

#define CP16(saddr, gptr) \
    asm volatile("cp.async.ca.shared.global [%0], [%1], 16;" \
                 :: "r"(saddr), "l"(gptr))
#define CP_COMMIT() asm volatile("cp.async.commit_group;" ::: "memory")
#define CP_WAIT0()  asm volatile("cp.async.wait_group 0;" ::: "memory")
#define CP_WAIT1()  asm volatile("cp.async.wait_group 1;" ::: "memory")

// ldmatrix lane offsets, 144-byte rows (attn)
static __device__ __forceinline__ uint32_t a_lane_off(int lane) {
    return (uint32_t)((lane & 15) * 144 + ((lane & 16) ? 16 : 0));
}
static __device__ __forceinline__ uint32_t b_lane_off(int lane) {
    return (uint32_t)(((lane & 7) + ((lane >> 4) & 1) * 8) * 144 +
                      ((lane & 8) ? 16 : 0));
}
// ldmatrix lane offsets, 80-byte rows (gemm)
static __device__ __forceinline__ uint32_t a80_off(int lane) {
    return (uint32_t)((lane & 15) * 80 + ((lane & 16) ? 16 : 0));
}
static __device__ __forceinline__ uint32_t b80_off(int lane) {
    return (uint32_t)(((lane & 7) + ((lane >> 4) & 1) * 8) * 80 +
                      ((lane & 8) ? 16 : 0));
}

// ---------------------------------------------------------------------------
// Merged converter: everything -> single fp16 (half2 words).
// ---------------------------------------------------------------------------
__global__ void conv_all(const float* __restrict__ q, const float* __restrict__ k,
                         const float* __restrict__ v, const float* __restrict__ wq,
                         const float* __restrict__ wk, const float* __restrict__ wv,
                         const float* __restrict__ wo)
{
    const int total = 3*NPI + 4*NPW;
    for (int i = blockIdx.x * blockDim.x + threadIdx.x; i < total;
         i += gridDim.x * blockDim.x) {
        const float* src; int off; uint32_t* d;
        if (i < NPI)             { src = q;  off = i;             d = g_in; }
        else if (i < 2*NPI)      { src = k;  off = i - NPI;       d = g_in + NPI; }
        else if (i < 3*NPI)      { src = v;  off = i - 2*NPI;     d = g_in + 2*NPI; }
        else if (i < 3*NPI+NPW)  { src = wq; off = i - 3*NPI;     d = g_wt; }
        else if (i < 3*NPI+2*NPW){ src = wk; off = i-3*NPI-NPW;   d = g_wt + NPW; }
        else if (i < 3*NPI+3*NPW){ src = wv; off = i-3*NPI-2*NPW; d = g_wt + 2*NPW; }
        else                     { src = wo; off = i-3*NPI-3*NPW; d = g_wt + 3*NPW; }
        float2 p = ((const float2*)src)[off];
        d[off] = pack2h(p.x, p.y);
    }
}

// ---------------------------------------------------------------------------
// Pure fp16 GEMM, double-buffered cp.async. 128 thr, 4 warps (2mx2n),
// warp 64x64, k-chunk 32. Buffer 20480 B (A+0, B+10240, 80 B rows), x2.
// ---------------------------------------------------------------------------
#define GEMM_SMEM 40960
extern __shared__ uint32_t smw[];

__global__ __launch_bounds__(128) void gemm_tc(
    const uint32_t* __restrict__ X, const uint32_t* __restrict__ W,
    const float* __restrict__ b0, const float* __restrict__ b1,
    const float* __restrict__ b2, float* __restrict__ Out, int out_sel)
{
    const int tid = threadIdx.x, lane = tid & 31, wid = tid >> 5;
    const int g = lane >> 2, c = lane & 3;
    const int mw = wid >> 1, nw = wid & 1;
    const int m0 = blockIdx.y * 128, n0 = blockIdx.x * 128;

    int sel = out_sel;
    const float* Bv = b0;
    if (out_sel < 0) {
        int z = blockIdx.z;
        sel = 1 + z;
        X += (size_t)z * NPI;
        W += (size_t)z * NPW;
        Bv = (z == 0) ? b0 : (z == 1) ? b1 : b2;
    }

    const uint32_t sbg = smem_u32(smw);
    const uint32_t abase = sbg + (uint32_t)(mw*64)*80 + a80_off(lane);
    const uint32_t bbase = sbg + 10240u + (uint32_t)(nw*64)*80 + b80_off(lane);

    const int seg = tid & 3;
    const int row0 = tid >> 2;

    float acc[4][8][4] = {};

    // prologue
    #pragma unroll
    for (int l = 0; l < 4; l++) {
        int row = row0 + l*32;
        uint32_t sa = sbg + row*80 + seg*16;
        uint32_t ga = (uint32_t)(m0+row)*256 + seg*4;
        uint32_t gb = (uint32_t)(n0+row)*256 + seg*4;
        CP16(sa,         X + ga);
        CP16(sa + 10240, W + gb);
    }
    CP_COMMIT();
    CP_WAIT0();
    __syncthreads();

    for (int kc = 0; kc < 16; kc++) {
        const uint32_t bo_ = (uint32_t)(kc & 1) * 20480u;
        const bool more = (kc + 1 < 16);
        if (more) {
            uint32_t sb = sbg + (uint32_t)((kc+1) & 1) * 20480u;
            #pragma unroll
            for (int l = 0; l < 4; l++) {
                int row = row0 + l*32;
                uint32_t sa = sb + row*80 + seg*16;
                uint32_t ga = (uint32_t)(m0+row)*256 + (kc+1)*16 + seg*4;
                uint32_t gb = (uint32_t)(n0+row)*256 + (kc+1)*16 + seg*4;
                CP16(sa,         X + ga);
                CP16(sa + 10240, W + gb);
            }
            CP_COMMIT();
        }

        #pragma unroll
        for (int ks = 0; ks < 2; ks++) {
            uint32_t ah[4][4], b4[4][4];
            #pragma unroll
            for (int mf = 0; mf < 4; mf++)
                ldsm4(ah[mf], abase + bo_ + mf*1280 + ks*32);
            #pragma unroll
            for (int np = 0; np < 4; np++)
                ldsm4(b4[np], bbase + bo_ + np*1280 + ks*32);
            #pragma unroll
            for (int mf = 0; mf < 4; mf++)
                #pragma unroll
                for (int np = 0; np < 4; np++) {
                    mma16816(acc[mf][2*np  ], ah[mf], &b4[np][0]);
                    mma16816(acc[mf][2*np+1], ah[mf], &b4[np][2]);
                }
        }

        if (more) CP_WAIT0();
        __syncthreads();
    }

    // ---- epilogues ----
    if (sel == 0) {
        #pragma unroll
        for (int mf = 0; mf < 4; mf++) {
            int r0 = mw*64 + mf*16 + g;
            #pragma unroll
            for (int nf = 0; nf < 8; nf++) {
                int col = n0 + nw*64 + nf*8 + 2*c;
                float2 bb = *(const float2*)&Bv[col];
                float2 o0 = {acc[mf][nf][0] + bb.x, acc[mf][nf][1] + bb.y};
                float2 o1 = {acc[mf][nf][2] + bb.x, acc[mf][nf][3] + bb.y};
                *(float2*)&Out[(size_t)(m0+r0  )*NFEAT + col] = o0;
                *(float2*)&Out[(size_t)(m0+r0+8)*NFEAT + col] = o1;
            }
        }
    } else if (sel == 1 || sel == 2) {
        __half* O = (sel == 1) ? g_q : g_k;
        const float scl = (sel == 1) ? 0.1803368801111204f : 1.0f;  // log2e/8
        #pragma unroll
        for (int mf = 0; mf < 4; mf++)
            #pragma unroll
            for (int half = 0; half < 2; half++) {
                int m  = m0 + mw*64 + mf*16 + g + half*8;
                int bb_ = m >> 11, tt = m & (T_SEQ - 1);
                #pragma unroll
                for (int nf = 0; nf < 8; nf++) {
                    int col = nw*64 + nf*8 + 2*c;
                    int hh = (n0 + col) >> 6, d = (n0 + col) & 63;
                    float2 bb = *(const float2*)&Bv[n0 + col];
                    size_t widx = (((size_t)(bb_*HEADS+hh)*T_SEQ + tt)*DK + d) >> 1;
                    ((uint32_t*)O)[widx] =
                        pack2h((acc[mf][nf][half*2+0] + bb.x) * scl,
                               (acc[mf][nf][half*2+1] + bb.y) * scl);
                }
            }
    } else {
        // V: single fp16, transpose to [bh][d][t] through smem
        __syncthreads();
        __half* Ts = (__half*)smw;                      // [128n][136]
        #pragma unroll
        for (int mf = 0; mf < 4; mf++)
            #pragma unroll
            for (int half = 0; half < 2; half++) {
                int t_loc = mw*64 + mf*16 + g + half*8;
                #pragma unroll
                for (int nf = 0; nf < 8; nf++) {
                    int col = nw*64 + nf*8 + 2*c;
                    float2 bb = *(const float2*)&Bv[n0 + col];
                    Ts[(size_t)(col  )*136 + t_loc] =
                        __float2half_rn(acc[mf][nf][half*2+0] + bb.x);
                    Ts[(size_t)(col+1)*136 + t_loc] =
                        __float2half_rn(acc[mf][nf][half*2+1] + bb.y);
                }
            }
        __syncthreads();
        int bb_ = m0 >> 11, tt0 = m0 & (T_SEQ - 1);
        #pragma unroll
        for (int l = 0; l < 16; l++) {
            int idx = tid + l * 128, n = idx >> 4, j = idx & 15;
            int hh = (n0 >> 6) + (n >> 6), d = n & 63;
            size_t go = ((size_t)(bb_*HEADS + hh)*DK + d)*T_SEQ + tt0 + j*8;
            *(uint4*)&g_vt[go] = *(uint4*)((char*)Ts + (size_t)n*272 + j*16);
        }
    }
}

// ---------------------------------------------------------------------------
// fp16 attention (round-16, passing): Q in registers, P via h2exp2,
// triple-buffered cp.async, 128 thr, 4 warps x 32 q-rows. Output now single.
// SMEM: Q 0 (18432), 3 K/V buffers at 18432 (18432 each), mask at 73728.
// ---------------------------------------------------------------------------
#define AQ   0
#define ABUF 18432
#define AMB  73728
#define ATTN_SMEM 74496

static __device__ __forceinline__ void attn_issue_tile(
    uint32_t kbase, int bh, int kt, int tid)
{
    #pragma unroll
    for (int l = 0; l < 4; l++) {
        int idx = tid + l * 128, row = idx >> 3, j = idx & 7;
        uint32_t soff = row * 144 + j * 16;
        size_t kg = ((size_t)bh * T_SEQ + kt + row) * DK + j * 8;
        size_t vg = ((size_t)bh * DK + row) * T_SEQ + kt + j * 8;
        CP16(kbase +        soff, (const char*)&g_k[kg]);
        CP16(kbase + 9216 + soff, (const char*)&g_vt[vg]);
    }
    CP_COMMIT();
}

__global__ __launch_bounds__(128, 2) void attn_tc(const int* __restrict__ mask)
{
    extern __shared__ char sm[];
    const uint32_t sb = smem_u32(sm);
    float* mbufF = (float*)(sm + AMB);

    const int tid = threadIdx.x, lane = tid & 31, wid = tid >> 5;
    const int c = lane & 3;
    const int bh = blockIdx.y, b = bh >> 3, h = bh & 7;
    const int q0 = blockIdx.x * 128;
    const int rb = wid * 32;

    const uint32_t q_amem = sb + AQ + (uint32_t)rb*144 + a_lane_off(lane);
    const uint32_t b_off  = b_lane_off(lane);

    // full 128-row Q tile: 1024 uint4
    #pragma unroll
    for (int l = 0; l < 8; l++) {
        int idx = tid + l * 128, row = idx >> 3, j = idx & 7;
        size_t gsrc = ((size_t)bh*T_SEQ + q0 + row)*DK + j*8;
        *(uint4*)(sm + AQ + row*144 + j*16) = *(const uint4*)&g_q[gsrc];
    }
    attn_issue_tile(sb + ABUF,          bh, 0,  tid);
    attn_issue_tile(sb + ABUF + 18432u, bh, 64, tid);
    if (tid < 64) {
        mbufF[tid]      = (float)mask[b*T_SEQ + tid];
        mbufF[64 + tid] = (float)mask[b*T_SEQ + 64 + tid];
    }
    __syncthreads();

    // ---- Q fragments resident in registers ----
    uint32_t qf[2][4][4];
    #pragma unroll
    for (int mf = 0; mf < 2; mf++)
        #pragma unroll
        for (int ks = 0; ks < 4; ks++)
            ldsm4(qf[mf][ks], q_amem + mf*2304 + ks*32);

    float oacc[2][8][4] = {};
    float lacc[2][2] = {};

    for (int it = 0; it < 32; it++) {
        const int cur3 = it % 3;
        const uint32_t kb = sb + ABUF + (uint32_t)cur3 * 18432u + b_off;
        const uint32_t vb = kb + 9216;

        if (it + 1 < 32) CP_WAIT1(); else CP_WAIT0();
        __syncthreads();
        if (it + 2 < 32) {
            attn_issue_tile(sb + ABUF + (uint32_t)((it+2) % 3) * 18432u,
                            bh, (it+2)*64, tid);
            if (tid < 64)
                mbufF[((it+2) % 3)*64 + tid] =
                    (float)mask[b*T_SEQ + (it+2)*64 + tid];
        }

        // ---- S = Q K^T ----
        float sacc[2][8][4] = {};
        #pragma unroll
        for (int ks = 0; ks < 4; ks++) {
            #pragma unroll
            for (int np = 0; np < 4; np++) {
                uint32_t k4[4];
                ldsm4(k4, kb + np*2304 + ks*32);
                #pragma unroll
                for (int mf = 0; mf < 2; mf++) {
                    mma16816(sacc[mf][2*np  ], qf[mf][ks], &k4[0]);
                    mma16816(sacc[mf][2*np+1], qf[mf][ks], &k4[2]);
                }
            }
        }

        // ---- exp2 in half2 + mask + row-sum ----
        uint32_t ph[2][8][2];
        #pragma unroll
        for (int nf = 0; nf < 8; nf++) {
            int cb = nf*8 + 2*c;
            __half2 msk = __floats2half2_rn(mbufF[cur3*64 + cb],
                                            mbufF[cur3*64 + cb + 1]);
            #pragma unroll
            for (int mf = 0; mf < 2; mf++) {
                __half2 s01 = __floats2half2_rn(sacc[mf][nf][0], sacc[mf][nf][1]);
                __half2 s23 = __floats2half2_rn(sacc[mf][nf][2], sacc[mf][nf][3]);
                __half2 e01 = __hmul2(h2exp2(s01), msk);
                __half2 e23 = __hmul2(h2exp2(s23), msk);
                float2 f01 = __half22float2(e01);
                float2 f23 = __half22float2(e23);
                lacc[mf][0] += f01.x + f01.y;
                lacc[mf][1] += f23.x + f23.y;
                ph[mf][nf][0] = *reinterpret_cast<uint32_t*>(&e01);
                ph[mf][nf][1] = *reinterpret_cast<uint32_t*>(&e23);
            }
        }

        // ---- O += P V ----
        #pragma unroll
        for (int kg = 0; kg < 4; kg++) {
            uint32_t pah[2][4];
            #pragma unroll
            for (int mf = 0; mf < 2; mf++) {
                pah[mf][0] = ph[mf][2*kg][0];   pah[mf][1] = ph[mf][2*kg][1];
                pah[mf][2] = ph[mf][2*kg+1][0]; pah[mf][3] = ph[mf][2*kg+1][1];
            }
            #pragma unroll
            for (int np = 0; np < 4; np++) {
                uint32_t v4[4];
                ldsm4(v4, vb + np*2304 + kg*32);
                #pragma unroll
                for (int mf = 0; mf < 2; mf++) {
                    mma16816(oacc[mf][2*np  ], pah[mf], &v4[0]);
                    mma16816(oacc[mf][2*np+1], pah[mf], &v4[2]);
                }
            }
        }
    }

    // ---- reduce l, normalize, store single fp16 ----
    float inv[2][2];
    #pragma unroll
    for (int mf = 0; mf < 2; mf++)
        #pragma unroll
        for (int hf = 0; hf < 2; hf++) {
            float lv = lacc[mf][hf];
            lv += __shfl_xor_sync(0xffffffffu, lv, 1);
            lv += __shfl_xor_sync(0xffffffffu, lv, 2);
            inv[mf][hf] = (lv > 0.f) ? 1.f / (lv * (1.f + 1e-8f)) : 0.f;
        }

    const int g = lane >> 2;
    #pragma unroll
    for (int mf = 0; mf < 2; mf++) {
        const int row0 = q0 + rb + mf*16 + g, row1 = row0 + 8;
        #pragma unroll
        for (int nd = 0; nd < 8; nd++) {
            int colw = h*32 + nd*4 + c;
            g_x[(size_t)(b*T_SEQ + row0)*256 + colw] =
                pack2h(oacc[mf][nd][0] * inv[mf][0], oacc[mf][nd][1] * inv[mf][0]);
            g_x[(size_t)(b*T_SEQ + row1)*256 + colw] =
                pack2h(oacc[mf][nd][2] * inv[mf][1], oacc[mf][nd][3] * inv[mf][1]);
        }
    }
}

// ---------------------------------------------------------------------------
extern "C" void kernel_launch(void* const* d_in, const int* in_sizes, int n_in,
                              void* d_out, int out_size)
{
    const float* query = (const float*)d_in[0];
    const float* key_  = (const float*)d_in[1];
    const float* value = (const float*)d_in[2];
    const int*   mask  = (const int*)d_in[3];
    const float* Wq = (const float*)d_in[4];
    const float* bq = (const float*)d_in[5];
    const float* Wk = (const float*)d_in[6];
    const float* bk = (const float*)d_in[7];
    const float* Wv = (const float*)d_in[8];
    const float* bv = (const float*)d_in[9];
    const float* Wo = (const float*)d_in[10];
    const float* bo = (const float*)d_in[11];
    float* out = (float*)d_out;

    uint32_t *in_, *wt, *x_;
    cudaGetSymbolAddress((void**)&in_, g_in);
    cudaGetSymbolAddress((void**)&wt,  g_wt);
    cudaGetSymbolAddress((void**)&x_,  g_x);

    conv_all<<<2048, 256>>>(query, key_, value, Wq, Wk, Wv, Wo);

    cudaFuncSetAttribute(gemm_tc, cudaFuncAttributeMaxDynamicSharedMemorySize,
                         GEMM_SMEM);
    cudaFuncSetAttribute(attn_tc, cudaFuncAttributeMaxDynamicSharedMemorySize,
                         ATTN_SMEM);

    gemm_tc<<<dim3(4, 64, 3), 128, GEMM_SMEM>>>(
        in_, wt, bq, bk, bv, nullptr, -1);

    attn_tc<<<dim3(T_SEQ / 128, BHTOT), 128, ATTN_SMEM>>>(mask);

    gemm_tc<<<dim3(4, 64, 1), 128, GEMM_SMEM>>>(
        x_, wt + 3*NPW, bo, nullptr, nullptr, out, 0);
}